// round 5
// baseline (speedup 1.0000x reference)
#include <cuda_runtime.h>
#include <cuda_bf16.h>
#include <cstdint>

#define HW 1024

// ---------------- scratch (__device__ globals: alloc-guard-safe) ----------------
__device__ float g_cat [8u * 1024u * HW];   // 32 MB fp32 concat (residual + im2col source)
__device__ float g_scale[2048];
__device__ float g_bias [2048];
__device__ __nv_bfloat16 g_Whi[589824];
__device__ __nv_bfloat16 g_Wlo[589824];
// one big bf16 arena, element offsets:
#define IM_OFF    0u          // im2col B           18,874,368
#define XB_OFF    18874368u   // x as B (K=512)      4,194,304
#define CATB_OFF  23068672u   // concat B (K=1024)   8,388,608
#define ZB_OFF    31457280u   // z as B (K=256)      2,097,152
#define QT_OFF    33554432u   // Q^T [bh][i][64]     2,097,152
#define KT_OFF    35651584u   // K^T [bh][i][64]     2,097,152
#define V_OFF     37748736u   // V   [bh][d][1024]   2,097,152
#define ATB_OFF   39845888u   // attn out as B       2,097,152
__device__ __nv_bfloat16 g_Bhi[41943040];
__device__ __nv_bfloat16 g_Blo[41943040];

__device__ __forceinline__ float silu_f(float v) { return v / (1.f + __expf(-v)); }

__device__ __forceinline__ uint32_t smem_u32(const void* p) {
    uint32_t a;
    asm("{ .reg .u64 t; cvta.to.shared.u64 t, %1; cvt.u32.u64 %0, t; }" : "=r"(a) : "l"(p));
    return a;
}
#define SWZ128(o) ((o) ^ (((o) >> 3) & 0x70))
#define SWZ64(o)  ((o) ^ (((o) >> 3) & 0x30))

__device__ __forceinline__ void ldsm_x4(uint32_t* r, uint32_t a) {
    asm volatile("ldmatrix.sync.aligned.m8n8.x4.shared.b16 {%0,%1,%2,%3}, [%4];"
        : "=r"(r[0]), "=r"(r[1]), "=r"(r[2]), "=r"(r[3]) : "r"(a));
}
__device__ __forceinline__ void ldsm_x2(uint32_t* r, uint32_t a) {
    asm volatile("ldmatrix.sync.aligned.m8n8.x2.shared.b16 {%0,%1}, [%2];"
        : "=r"(r[0]), "=r"(r[1]) : "r"(a));
}
__device__ __forceinline__ void mma16816(float* d, const uint32_t* a, const uint32_t* b) {
    asm volatile("mma.sync.aligned.m16n8k16.row.col.f32.bf16.bf16.f32 "
        "{%0,%1,%2,%3}, {%4,%5,%6,%7}, {%8,%9}, {%0,%1,%2,%3};"
        : "+f"(d[0]), "+f"(d[1]), "+f"(d[2]), "+f"(d[3])
        : "r"(a[0]), "r"(a[1]), "r"(a[2]), "r"(a[3]), "r"(b[0]), "r"(b[1]));
}
__device__ __forceinline__ void cpa16(uint32_t d, const void* s) {
    asm volatile("cp.async.cg.shared.global [%0], [%1], 16;" :: "r"(d), "l"(s));
}
#define CPA_COMMIT() asm volatile("cp.async.commit_group;" ::: "memory")
#define CPA_WAIT0()  asm volatile("cp.async.wait_group 0;" ::: "memory")

// packs: element k = lo, element k+1 = hi
__device__ __forceinline__ uint32_t packbf(float lo, float hi) {
    uint32_t r;
    asm("cvt.rn.bf16x2.f32 %0, %1, %2;" : "=r"(r) : "f"(hi), "f"(lo));
    return r;
}
__device__ __forceinline__ float bflo(float v) {
    return v - __bfloat162float(__float2bfloat16(v));
}

// ---------------- BN fold ----------------
__global__ void fold_bn_kernel(const float* __restrict__ cv1, const float* __restrict__ cv2,
                               const float* __restrict__ mcv1, const float* __restrict__ mcv2)
{
    int c = blockIdx.x * 256 + threadIdx.x;
    if (c >= 2048) return;
    const float* p; int C, lc;
    if (c < 512)        { p = cv1;  C = 512; lc = c; }
    else if (c < 1024)  { p = cv2;  C = 512; lc = c - 512; }
    else if (c < 1536)  { int i = (c - 1024) >> 8; p = mcv1 + i * 1024; C = 256; lc = (c - 1024) & 255; }
    else                { int i = (c - 1536) >> 8; p = mcv2 + i * 1024; C = 256; lc = (c - 1536) & 255; }
    float g = p[lc], b = p[C + lc], m = p[2 * C + lc], v = p[3 * C + lc];
    float s = g / sqrtf(v + 1e-3f);
    g_scale[c] = s;
    g_bias[c]  = b - m * s;
}

// ---------------- weight converter ----------------
__global__ void convW_kernel(const float* __restrict__ W, int M, int K, int isConv,
                             __nv_bfloat16* __restrict__ Whi, __nv_bfloat16* __restrict__ Wlo)
{
    long e = (long)blockIdx.x * 256 + threadIdx.x;
    if (e >= (long)M * K) return;
    long m = e / K, k = e % K;
    float v;
    if (isConv) { int off = (int)(k >> 8), ci = (int)(k & 255); v = W[m * 2304 + ci * 9 + off]; }
    else v = W[e];
    __nv_bfloat16 h = __float2bfloat16(v);
    Whi[e] = h;
    Wlo[e] = __float2bfloat16(v - __bfloat162float(h));
}

// ---------------- activation converter (only for x): [b][K][HW] -> [b][n][K] hi/lo ----------------
__global__ void convB_kernel(const float* __restrict__ In, long inStride, int K,
                             __nv_bfloat16* __restrict__ Bhi, __nv_bfloat16* __restrict__ Blo)
{
    __shared__ float t[32][33];
    int n0 = blockIdx.x * 32, k0 = blockIdx.y * 32, b = blockIdx.z;
    int tx = threadIdx.x, ty = threadIdx.y;
    const float* in = In + (long)b * inStride;
#pragma unroll
    for (int yy = 0; yy < 32; yy += 8)
        t[yy + ty][tx] = in[(long)(k0 + yy + ty) * HW + n0 + tx];
    __syncthreads();
#pragma unroll
    for (int yy = 0; yy < 32; yy += 8) {
        int n = n0 + yy + ty, k = k0 + tx;
        float v = t[tx][yy + ty];
        long o = ((long)b * 1024 + n) * K + k;
        __nv_bfloat16 h = __float2bfloat16(v);
        Bhi[o] = h;
        Blo[o] = __float2bfloat16(v - __bfloat162float(h));
    }
}

// ---------------- im2col converter: k = (ky*3+kx)*256 + ci ----------------
__global__ void im2colB_kernel(const float* __restrict__ In, long inStride,
                               __nv_bfloat16* __restrict__ Bhi, __nv_bfloat16* __restrict__ Blo)
{
    __shared__ float t[32][33];
    int y = blockIdx.x, ci0 = blockIdx.y * 32;
    int off = blockIdx.z % 9, b = blockIdx.z / 9;
    int ky = off / 3, kx = off % 3;
    int tx = threadIdx.x, ty = threadIdx.y;
    const float* in = In + (long)b * inStride;
    int yy = y + ky - 1;
    int xx = tx + kx - 1;
    bool vy = (yy >= 0 && yy < 32), vx = (xx >= 0 && xx < 32);
#pragma unroll
    for (int d = 0; d < 32; d += 8) {
        float v = 0.f;
        if (vy && vx) v = in[(long)(ci0 + d + ty) * HW + yy * 32 + xx];
        t[d + ty][tx] = v;
    }
    __syncthreads();
#pragma unroll
    for (int d = 0; d < 32; d += 8) {
        int n = y * 32 + d + ty;
        int k = off * 256 + ci0 + tx;
        float v = t[tx][d + ty];
        long o = ((long)b * 1024 + n) * 2304 + k;
        __nv_bfloat16 h = __float2bfloat16(v);
        Bhi[o] = h;
        Blo[o] = __float2bfloat16(v - __bfloat162float(h));
    }
}

// ---------------- warp-MMA GEMM v3 ----------------
// Modes: 0 = fp32 only; 1 = also bf16 hi/lo transposed [n][kOut] at kBase=mOfs+m0;
//        2 = qkv attention operands (Q^T scaled / K^T + relpos / V direct).
#define MG_STAGE 32768
#define MG_SMEM  66560   // max(2 stages = 65536, epilogue stage 128*129*4 = 66048)

__device__ __forceinline__ void mg_load(uint32_t smb, int tid,
    const uint4* __restrict__ wHi, const uint4* __restrict__ wLo,
    const uint4* __restrict__ bHi, const uint4* __restrict__ bLo,
    int m0, int n0, int K16, int c, uint32_t stOff)
{
    uint32_t sb = smb + stOff;
    int r = tid >> 1;
    int j = (tid & 1) * 2;
    uint32_t o0 = SWZ64((uint32_t)(r * 64 + j * 16));
    uint32_t o1 = SWZ64((uint32_t)(r * 64 + (j + 1) * 16));
    const uint4* a;
    a = wHi + (long)(m0 + r) * K16 + c * 4 + j;
    cpa16(sb + o0, a); cpa16(sb + o1, a + 1);
    a = wLo + (long)(m0 + r) * K16 + c * 4 + j;
    cpa16(sb + 8192 + o0, a); cpa16(sb + 8192 + o1, a + 1);
    a = bHi + (long)(n0 + r) * K16 + c * 4 + j;
    cpa16(sb + 16384 + o0, a); cpa16(sb + 16384 + o1, a + 1);
    a = bLo + (long)(n0 + r) * K16 + c * 4 + j;
    cpa16(sb + 24576 + o0, a); cpa16(sb + 24576 + o1, a + 1);
}

extern __shared__ char mg_smem[];

__global__ void __launch_bounds__(256, 2) mgemm_kernel(
    const __nv_bfloat16* __restrict__ Bhi, const __nv_bfloat16* __restrict__ Blo,
    const __nv_bfloat16* __restrict__ Whi, const __nv_bfloat16* __restrict__ Wlo,
    int K,
    float* __restrict__ Out, long outStride,
    const float* __restrict__ scale, const float* __restrict__ bias,
    const float* __restrict__ Res, long resStride,
    int doSilu,
    int mode, __nv_bfloat16* __restrict__ bOutHi, __nv_bfloat16* __restrict__ bOutLo,
    int kOut, int mOfs,
    const float* __restrict__ RW, const float* __restrict__ RH)
{
    int b = blockIdx.z, m0 = blockIdx.y * 128, n0 = blockIdx.x * 128;
    int tid = threadIdx.x, wid = tid >> 5, lane = tid & 31;
    int warp_m = wid & 1, warp_n = wid >> 1;
    uint32_t smb = smem_u32(mg_smem);

    int K16 = K >> 3;
    const uint4* wHi = (const uint4*)Whi;
    const uint4* wLo = (const uint4*)Wlo;
    const uint4* bHi = (const uint4*)(Bhi + (long)b * 1024 * K);
    const uint4* bLo = (const uint4*)(Blo + (long)b * 1024 * K);

    float acc[4][4][4];
#pragma unroll
    for (int i = 0; i < 4; i++)
#pragma unroll
        for (int j = 0; j < 4; j++)
#pragma unroll
            for (int r = 0; r < 4; r++) acc[i][j][r] = 0.f;

    int nChunks = K >> 5;
    mg_load(smb, tid, wHi, wLo, bHi, bLo, m0, n0, K16, 0, 0);
    CPA_COMMIT();

    int aRowL = warp_m * 64 + (lane & 7) + (lane & 8);
    int aColL = ((lane >> 4) & 1) * 16;
    int bRowX4 = warp_n * 32 + (lane >> 4) * 8 + (lane & 7);  // + p*16
    uint32_t bColX4 = (uint32_t)(((lane >> 3) & 1) * 16);

    for (int c = 0; c < nChunks; c++) {
        int s = c & 1;
        CPA_WAIT0();
        __syncthreads();
        if (c + 1 < nChunks) {
            mg_load(smb, tid, wHi, wLo, bHi, bLo, m0, n0, K16, c + 1, (uint32_t)((s ^ 1) * MG_STAGE));
            CPA_COMMIT();
        }

        uint32_t base = smb + s * MG_STAGE;
#pragma unroll
        for (int ks = 0; ks < 2; ks++) {
            uint32_t ah[4][4], bh4[2][4];
#pragma unroll
            for (int mt = 0; mt < 4; mt++)
                ldsm_x4(ah[mt], base + SWZ64((uint32_t)((aRowL + mt * 16) * 64 + aColL + ks * 32)));
#pragma unroll
            for (int p = 0; p < 2; p++)
                ldsm_x4(bh4[p], base + 16384 + SWZ64((uint32_t)((bRowX4 + p * 16) * 64 + bColX4 + ks * 32)));
#pragma unroll
            for (int mt = 0; mt < 4; mt++)
#pragma unroll
                for (int p = 0; p < 2; p++) {
                    mma16816(acc[mt][2 * p],     ah[mt], &bh4[p][0]);
                    mma16816(acc[mt][2 * p + 1], ah[mt], &bh4[p][2]);
                }

            uint32_t al[4][4];
#pragma unroll
            for (int mt = 0; mt < 4; mt++)
                ldsm_x4(al[mt], base + 8192 + SWZ64((uint32_t)((aRowL + mt * 16) * 64 + aColL + ks * 32)));
#pragma unroll
            for (int mt = 0; mt < 4; mt++)
#pragma unroll
                for (int p = 0; p < 2; p++) {
                    mma16816(acc[mt][2 * p],     al[mt], &bh4[p][0]);
                    mma16816(acc[mt][2 * p + 1], al[mt], &bh4[p][2]);
                }

            uint32_t bl4[2][4];
#pragma unroll
            for (int p = 0; p < 2; p++)
                ldsm_x4(bl4[p], base + 24576 + SWZ64((uint32_t)((bRowX4 + p * 16) * 64 + bColX4 + ks * 32)));
#pragma unroll
            for (int mt = 0; mt < 4; mt++)
#pragma unroll
                for (int p = 0; p < 2; p++) {
                    mma16816(acc[mt][2 * p],     ah[mt], &bl4[p][0]);
                    mma16816(acc[mt][2 * p + 1], ah[mt], &bl4[p][2]);
                }
        }
    }

    // ---- epilogue ----
    int doStage = (mode == 1) || (mode == 2 && m0 < 512);
    float* stage = (float*)mg_smem;
    if (doStage) __syncthreads();

#pragma unroll
    for (int mt = 0; mt < 4; mt++) {
        int mlB = warp_m * 64 + mt * 16 + (lane >> 2);
#pragma unroll
        for (int h2 = 0; h2 < 2; h2++) {
            int ml = mlB + h2 * 8;
            int m = m0 + ml;
            float s = 1.f, bb = 0.f;
            if (scale) { s = scale[m]; bb = bias[m]; }
            long rowOff = Out ? ((long)b * outStride + (long)m * HW) : 0;
            long resOff = Res ? ((long)b * resStride + (long)m * HW) : 0;
#pragma unroll
            for (int nt = 0; nt < 4; nt++) {
                int nl = warp_n * 32 + nt * 8 + (lane & 3) * 2;
                int n = n0 + nl;
                float v0 = acc[mt][nt][h2 * 2 + 0] * s + bb;
                float v1 = acc[mt][nt][h2 * 2 + 1] * s + bb;
                if (doSilu) { v0 = silu_f(v0); v1 = silu_f(v1); }
                if (Res) {
                    float2 r2 = *(const float2*)&Res[resOff + n];
                    v0 += r2.x; v1 += r2.y;
                }
                if (Out) *(float2*)&Out[rowOff + n] = make_float2(v0, v1);
                if (doStage) {
                    stage[nl * 129 + ml] = v0;
                    stage[(nl + 1) * 129 + ml] = v1;
                } else if (mode == 2 && m0 >= 512) {
                    int ch = m - 512;
                    int bh = b * 4 + (ch >> 6), d = ch & 63;
                    long o = (long)V_OFF + (long)bh * 65536 + d * 1024 + n;
                    *(uint32_t*)(bOutHi + o) = packbf(v0, v1);
                    *(uint32_t*)(bOutLo + o) = packbf(bflo(v0), bflo(v1));
                }
            }
        }
    }

    if (!doStage) return;
    __syncthreads();

    if (mode == 1) {
        long rowBase = (long)b * 1024 + n0;
        int kBase = mOfs + m0;
        for (int r = wid; r < 128; r += 8) {
            const float* sp = stage + r * 129 + lane * 4;
            float a0 = sp[0], a1 = sp[1], a2 = sp[2], a3 = sp[3];
            uint2 hv = make_uint2(packbf(a0, a1), packbf(a2, a3));
            uint2 lv = make_uint2(packbf(bflo(a0), bflo(a1)), packbf(bflo(a2), bflo(a3)));
            long o = (rowBase + r) * kOut + kBase + lane * 4;
            *(uint2*)(bOutHi + o) = hv;
            *(uint2*)(bOutLo + o) = lv;
        }
    } else {  // mode 2, Q or K transposed
        int isK = (m0 >= 256);
        long regionOff = isK ? (long)KT_OFF : (long)QT_OFF;
        int chBase = m0 - (isK ? 256 : 0);   // 0 or 128
        for (int idx = wid; idx < 256; idx += 8) {
            int il = idx >> 1, half = idx & 1;
            int h = (chBase >> 6) + half;
            int bh = b * 4 + h;
            int gi = n0 + il;
            int d0 = lane * 2;
            float v0 = stage[il * 129 + half * 64 + d0];
            float v1 = stage[il * 129 + half * 64 + d0 + 1];
            if (!isK) { v0 *= 0.125f; v1 *= 0.125f; }
            else {
                int x = gi & 31, y = gi >> 5;
                int c0 = (h * 64 + d0) * 32;
                v0 += RW[c0 + x] + RH[c0 + y];
                v1 += RW[c0 + 32 + x] + RH[c0 + 32 + y];
            }
            long o = regionOff + ((long)bh * 1024 + gi) * 64 + d0;
            *(uint32_t*)(bOutHi + o) = packbf(v0, v1);
            *(uint32_t*)(bOutLo + o) = packbf(bflo(v0), bflo(v1));
        }
    }
}

// ---------------- MMA flash attention (bf16 hi/lo in, bf16 hi/lo B-layout out) ----------------
#define AT_SMEM 163840

__device__ __forceinline__ void kv_load(uint32_t smb, int tid,
    const __nv_bfloat16* __restrict__ kTh, const __nv_bfloat16* __restrict__ kTl,
    const __nv_bfloat16* __restrict__ vH, const __nv_bfloat16* __restrict__ vL,
    int bh, int t, uint32_t stOff)
{
    uint32_t kb = smb + stOff;
    const uint4* kh4 = (const uint4*)(kTh + ((long)bh * 1024 + t * 128) * 64);
    const uint4* kl4 = (const uint4*)(kTl + ((long)bh * 1024 + t * 128) * 64);
    int r = tid >> 1, j0 = (tid & 1) * 4;
#pragma unroll
    for (int j = 0; j < 4; j++) {
        uint32_t off = SWZ128((uint32_t)(r * 128 + (j0 + j) * 16));
        cpa16(kb + off, kh4 + (long)r * 8 + j0 + j);
        cpa16(kb + 16384 + off, kl4 + (long)r * 8 + j0 + j);
    }
    const uint4* vh4 = (const uint4*)(vH + (long)bh * 65536 + t * 128);
    const uint4* vl4 = (const uint4*)(vL + (long)bh * 65536 + t * 128);
    int d = tid >> 2, jc0 = (tid & 3) * 4;
#pragma unroll
    for (int j = 0; j < 4; j++) {
        int jc = jc0 + j;
        uint32_t off = (uint32_t)((jc >> 3) * 8192) + SWZ128((uint32_t)(d * 128 + (jc & 7) * 16));
        cpa16(kb + 32768 + off, vh4 + (long)d * 128 + jc);
        cpa16(kb + 49152 + off, vl4 + (long)d * 128 + jc);
    }
}

extern __shared__ char at_smem[];

__global__ void __launch_bounds__(256) attn_mma_kernel(
    const __nv_bfloat16* __restrict__ Hi, const __nv_bfloat16* __restrict__ Lo,
    __nv_bfloat16* __restrict__ OutHi, __nv_bfloat16* __restrict__ OutLo)
{
    int qt = blockIdx.x, h = blockIdx.y, b = blockIdx.z;
    int bh = b * 4 + h;
    int tid = threadIdx.x, wid = tid >> 5, lane = tid & 31, li = lane & 15;
    uint32_t smb = smem_u32(at_smem);

    const __nv_bfloat16* qTh = Hi + QT_OFF;
    const __nv_bfloat16* qTl = Lo + QT_OFF;
    const __nv_bfloat16* kTh = Hi + KT_OFF;
    const __nv_bfloat16* kTl = Lo + KT_OFF;
    const __nv_bfloat16* vH  = Hi + V_OFF;
    const __nv_bfloat16* vL  = Lo + V_OFF;

    // Q tile load
    {
        const uint4* qh4 = (const uint4*)(qTh + ((long)bh * 1024 + qt * 128) * 64);
        const uint4* ql4 = (const uint4*)(qTl + ((long)bh * 1024 + qt * 128) * 64);
        int r = tid >> 1, j0 = (tid & 1) * 4;
        uint32_t qb = smb + 131072;
#pragma unroll
        for (int j = 0; j < 4; j++) {
            uint32_t off = SWZ128((uint32_t)(r * 128 + (j0 + j) * 16));
            cpa16(qb + off, qh4 + (long)r * 8 + j0 + j);
            cpa16(qb + 16384 + off, ql4 + (long)r * 8 + j0 + j);
        }
    }
    CPA_COMMIT();
    kv_load(smb, tid, kTh, kTl, vH, vL, bh, 0, 0);
    CPA_COMMIT();
    CPA_WAIT0();
    __syncthreads();

    uint32_t qfh[4][4], qfl[4][4];
    {
        int aRow = wid * 16 + (lane & 7) + (lane & 8);
        int aCol = ((lane >> 4) & 1) * 16;
#pragma unroll
        for (int ks = 0; ks < 4; ks++) {
            uint32_t off = SWZ128((uint32_t)(aRow * 128 + aCol + ks * 32));
            ldsm_x4(qfh[ks], smb + 131072 + off);
            ldsm_x4(qfl[ks], smb + 131072 + 16384 + off);
        }
    }

    float oacc[8][4];
#pragma unroll
    for (int i = 0; i < 8; i++)
#pragma unroll
        for (int j = 0; j < 4; j++) oacc[i][j] = 0.f;
    float m0 = -1e30f, m1 = -1e30f, l0 = 0.f, l1 = 0.f;

    int sRowX4 = (lane >> 4) * 8 + (lane & 7);       // + p*16
    uint32_t sColX4 = (uint32_t)(((lane >> 3) & 1) * 16);

    for (int t = 0; t < 8; t++) {
        int s = t & 1;
        if (t < 7) {
            kv_load(smb, tid, kTh, kTl, vH, vL, bh, t + 1, (uint32_t)((s ^ 1) * 65536));
            CPA_COMMIT();
        }

        uint32_t kb = smb + s * 65536;
        float sacc[16][4];
#pragma unroll
        for (int i = 0; i < 16; i++)
#pragma unroll
            for (int j = 0; j < 4; j++) sacc[i][j] = 0.f;

#pragma unroll
        for (int p = 0; p < 8; p++) {
            int rowB = p * 16 + sRowX4;
#pragma unroll
            for (int ks = 0; ks < 4; ks++) {
                uint32_t off = SWZ128((uint32_t)(rowB * 128 + sColX4 + ks * 32));
                uint32_t kh4[4], kl4[4];
                ldsm_x4(kh4, kb + off);
                ldsm_x4(kl4, kb + 16384 + off);
                mma16816(sacc[2 * p],     qfh[ks], &kh4[0]);
                mma16816(sacc[2 * p + 1], qfh[ks], &kh4[2]);
                mma16816(sacc[2 * p],     qfl[ks], &kh4[0]);
                mma16816(sacc[2 * p + 1], qfl[ks], &kh4[2]);
                mma16816(sacc[2 * p],     qfh[ks], &kl4[0]);
                mma16816(sacc[2 * p + 1], qfh[ks], &kl4[2]);
            }
        }

        float mx0 = m0, mx1 = m1;
#pragma unroll
        for (int nt = 0; nt < 16; nt++) {
            mx0 = fmaxf(mx0, fmaxf(sacc[nt][0], sacc[nt][1]));
            mx1 = fmaxf(mx1, fmaxf(sacc[nt][2], sacc[nt][3]));
        }
        mx0 = fmaxf(mx0, __shfl_xor_sync(0xffffffffu, mx0, 1));
        mx0 = fmaxf(mx0, __shfl_xor_sync(0xffffffffu, mx0, 2));
        mx1 = fmaxf(mx1, __shfl_xor_sync(0xffffffffu, mx1, 1));
        mx1 = fmaxf(mx1, __shfl_xor_sync(0xffffffffu, mx1, 2));
        float a0 = __expf(m0 - mx0), a1 = __expf(m1 - mx1);
        m0 = mx0; m1 = mx1;

        float ls0 = 0.f, ls1 = 0.f;
        uint32_t pah[8][4], pal[8][4];
#pragma unroll
        for (int kj = 0; kj < 8; kj++) {
            float p00 = __expf(sacc[2 * kj][0] - m0);
            float p01 = __expf(sacc[2 * kj][1] - m0);
            float p02 = __expf(sacc[2 * kj][2] - m1);
            float p03 = __expf(sacc[2 * kj][3] - m1);
            float p10 = __expf(sacc[2 * kj + 1][0] - m0);
            float p11 = __expf(sacc[2 * kj + 1][1] - m0);
            float p12 = __expf(sacc[2 * kj + 1][2] - m1);
            float p13 = __expf(sacc[2 * kj + 1][3] - m1);
            ls0 += p00 + p01 + p10 + p11;
            ls1 += p02 + p03 + p12 + p13;
            pah[kj][0] = packbf(p00, p01);
            pah[kj][1] = packbf(p02, p03);
            pah[kj][2] = packbf(p10, p11);
            pah[kj][3] = packbf(p12, p13);
            pal[kj][0] = packbf(bflo(p00), bflo(p01));
            pal[kj][1] = packbf(bflo(p02), bflo(p03));
            pal[kj][2] = packbf(bflo(p10), bflo(p11));
            pal[kj][3] = packbf(bflo(p12), bflo(p13));
        }
        ls0 += __shfl_xor_sync(0xffffffffu, ls0, 1);
        ls0 += __shfl_xor_sync(0xffffffffu, ls0, 2);
        ls1 += __shfl_xor_sync(0xffffffffu, ls1, 1);
        ls1 += __shfl_xor_sync(0xffffffffu, ls1, 2);
        l0 = l0 * a0 + ls0;
        l1 = l1 * a1 + ls1;
#pragma unroll
        for (int dt = 0; dt < 8; dt++) {
            oacc[dt][0] *= a0; oacc[dt][1] *= a0;
            oacc[dt][2] *= a1; oacc[dt][3] *= a1;
        }

#pragma unroll
        for (int dt = 0; dt < 8; dt++) {
            int rowV = dt * 8 + (li & 7);
#pragma unroll
            for (int kj = 0; kj < 8; kj++) {
                uint32_t off = (uint32_t)((kj >> 2) * 8192) +
                               SWZ128((uint32_t)(rowV * 128 + (li >> 3) * 16 + (kj & 3) * 32));
                uint32_t vh2[2], vl2[2];
                ldsm_x2(vh2, kb + 32768 + off);
                ldsm_x2(vl2, kb + 49152 + off);
                mma16816(oacc[dt], pah[kj], vh2);
                mma16816(oacc[dt], pal[kj], vh2);
                mma16816(oacc[dt], pah[kj], vl2);
            }
        }
        if (t < 7) {
            CPA_WAIT0();
            __syncthreads();
        }
    }

    // epilogue: stage [i][d] then emit bf16 hi/lo B-layout [n=i][k=256]
    float i0 = 1.f / l0, i1 = 1.f / l1;
    float* stg = (float*)at_smem;   // [128][66]
    int r0 = wid * 16 + (lane >> 2);
#pragma unroll
    for (int dt = 0; dt < 8; dt++) {
        int d = dt * 8 + (lane & 3) * 2;
        stg[r0 * 66 + d]           = oacc[dt][0] * i0;
        stg[r0 * 66 + d + 1]       = oacc[dt][1] * i0;
        stg[(r0 + 8) * 66 + d]     = oacc[dt][2] * i1;
        stg[(r0 + 8) * 66 + d + 1] = oacc[dt][3] * i1;
    }
    __syncthreads();
    for (int e = tid; e < 4096; e += 256) {
        int i = e >> 5, dp = (e & 31) * 2;
        float v0 = stg[i * 66 + dp], v1 = stg[i * 66 + dp + 1];
        long o = (long)ATB_OFF + ((long)b * 1024 + qt * 128 + i) * 256 + h * 64 + dp;
        *(uint32_t*)(OutHi + o) = packbf(v0, v1);
        *(uint32_t*)(OutLo + o) = packbf(bflo(v0), bflo(v1));
    }
}

// ---------------- launch ----------------
extern "C" void kernel_launch(void* const* d_in, const int* in_sizes, int n_in,
                              void* d_out, int out_size)
{
    const float* x      = (const float*)d_in[0];
    const float* cv1_w  = (const float*)d_in[1];
    const float* cv1_bn = (const float*)d_in[2];
    const float* cv2_w  = (const float*)d_in[3];
    const float* cv2_bn = (const float*)d_in[4];
    const float* mcv1w  = (const float*)d_in[5];
    const float* mcv1bn = (const float*)d_in[6];
    const float* mqkvw  = (const float*)d_in[7];
    const float* mrw    = (const float*)d_in[8];
    const float* mrh    = (const float*)d_in[9];
    const float* mcv2w  = (const float*)d_in[10];
    const float* mcv2bn = (const float*)d_in[11];
    float* out = (float*)d_out;

    float *cat, *scl, *bia;
    __nv_bfloat16 *whi, *wlo, *bhi, *blo;
    cudaGetSymbolAddress((void**)&cat,  g_cat);
    cudaGetSymbolAddress((void**)&scl,  g_scale);
    cudaGetSymbolAddress((void**)&bia,  g_bias);
    cudaGetSymbolAddress((void**)&whi,  g_Whi);
    cudaGetSymbolAddress((void**)&wlo,  g_Wlo);
    cudaGetSymbolAddress((void**)&bhi,  g_Bhi);
    cudaGetSymbolAddress((void**)&blo,  g_Blo);

    cudaFuncSetAttribute(mgemm_kernel, cudaFuncAttributeMaxDynamicSharedMemorySize, MG_SMEM);
    cudaFuncSetAttribute(attn_mma_kernel, cudaFuncAttributeMaxDynamicSharedMemorySize, AT_SMEM);

    fold_bn_kernel<<<8, 256>>>(cv1_bn, cv2_bn, mcv1bn, mcv2bn);

    // ---- cv1: 512 -> 512, BN+SiLU -> fp32 cat[0:512) + bf16 catB k[0:512) ----
    convW_kernel<<<(512 * 512 + 255) / 256, 256>>>(cv1_w, 512, 512, 0, whi, wlo);
    convB_kernel<<<dim3(32, 16, 8), dim3(32, 8)>>>(x, (long)512 * HW, 512, bhi + XB_OFF, blo + XB_OFF);
    mgemm_kernel<<<dim3(8, 4, 8), 256, MG_SMEM>>>(
        bhi + XB_OFF, blo + XB_OFF, whi, wlo, 512, cat, (long)1024 * HW,
        scl + 0, bia + 0, nullptr, 0, 1,
        1, bhi + CATB_OFF, blo + CATB_OFF, 1024, 0, nullptr, nullptr);

    for (int i = 0; i < 2; i++) {
        long yin  = (long)(i == 0 ? 256 : 512) * HW;

        // z = cbs(yi, 3x3) as implicit GEMM, K=2304 -> bf16 ZB only
        convW_kernel<<<(256 * 2304 + 255) / 256, 256>>>(
            mcv1w + (long)i * 256 * 2304, 256, 2304, 1, whi, wlo);
        im2colB_kernel<<<dim3(32, 8, 72), dim3(32, 8)>>>(cat + yin, (long)1024 * HW,
                                                         bhi + IM_OFF, blo + IM_OFF);
        mgemm_kernel<<<dim3(8, 2, 8), 256, MG_SMEM>>>(
            bhi + IM_OFF, blo + IM_OFF, whi, wlo, 2304, nullptr, 0,
            scl + 1024 + i * 256, bia + 1024 + i * 256, nullptr, 0, 1,
            1, bhi + ZB_OFF, blo + ZB_OFF, 256, 0, nullptr, nullptr);

        // qkv = conv1x1(z), 256 -> 768, emits Q^T/K^T(+relpos)/V bf16 operands directly
        convW_kernel<<<(768 * 256 + 255) / 256, 256>>>(
            mqkvw + (long)i * 768 * 256, 768, 256, 0, whi, wlo);
        mgemm_kernel<<<dim3(8, 6, 8), 256, MG_SMEM>>>(
            bhi + ZB_OFF, blo + ZB_OFF, whi, wlo, 256, nullptr, 0,
            nullptr, nullptr, nullptr, 0, 0,
            2, bhi, blo, 0, 0, mrw + (long)i * 8192, mrh + (long)i * 8192);

        // flash attention -> bf16 B-layout ATB
        attn_mma_kernel<<<dim3(8, 4, 8), 256, AT_SMEM>>>(bhi, blo, bhi, blo);

        // y_{i+2} = yi + silu(bn(conv1x1(attn))) -> fp32 cat slice + bf16 catB slice
        convW_kernel<<<(256 * 256 + 255) / 256, 256>>>(
            mcv2w + (long)i * 256 * 256, 256, 256, 0, whi, wlo);
        mgemm_kernel<<<dim3(8, 2, 8), 256, MG_SMEM>>>(
            bhi + ATB_OFF, blo + ATB_OFF, whi, wlo, 256,
            cat + (long)(512 + i * 256) * HW, (long)1024 * HW,
            scl + 1536 + i * 256, bia + 1536 + i * 256, cat + yin, (long)1024 * HW, 1,
            1, bhi + CATB_OFF, blo + CATB_OFF, 1024, 512 + i * 256, nullptr, nullptr);
    }

    // ---- final: 1024 -> 512, BN+SiLU, reads catB directly ----
    convW_kernel<<<(512 * 1024 + 255) / 256, 256>>>(cv2_w, 512, 1024, 0, whi, wlo);
    mgemm_kernel<<<dim3(8, 4, 8), 256, MG_SMEM>>>(
        bhi + CATB_OFF, blo + CATB_OFF, whi, wlo, 1024, out, (long)512 * HW,
        scl + 512, bia + 512, nullptr, 0, 1,
        0, nullptr, nullptr, 0, 0, nullptr, nullptr);
}

// round 6
// speedup vs baseline: 1.0986x; 1.0986x over previous
#include <cuda_runtime.h>
#include <cuda_bf16.h>
#include <cstdint>

#define HW 1024

// ---------------- scratch (__device__ globals: alloc-guard-safe) ----------------
__device__ float g_cat [8u * 1024u * HW];   // 32 MB
__device__ float g_z   [8u * 256u  * HW];   //  8 MB
__device__ float g_qkv [8u * 768u  * HW];   // 24 MB
__device__ float g_atto[8u * 256u  * HW];   //  8 MB
__device__ float g_scale[2048];
__device__ float g_bias [2048];
__device__ __nv_bfloat16 g_Whi[589824];
__device__ __nv_bfloat16 g_Wlo[589824];
__device__ __nv_bfloat16 g_Bhi[18874368];
__device__ __nv_bfloat16 g_Blo[18874368];

// offsets (elements) inside g_Bhi/g_Blo for attention operands
#define QT_OFF 0
#define KT_OFF 2097152
#define V_OFF  4194304

__device__ __forceinline__ float silu_f(float v) { return v / (1.f + __expf(-v)); }

__device__ __forceinline__ uint32_t smem_u32(const void* p) {
    uint32_t a;
    asm("{ .reg .u64 t; cvta.to.shared.u64 t, %1; cvt.u32.u64 %0, t; }" : "=r"(a) : "l"(p));
    return a;
}
#define SWZ128(o) ((o) ^ (((o) >> 3) & 0x70))
#define SWZ64(o)  ((o) ^ (((o) >> 3) & 0x30))

__device__ __forceinline__ void ldsm_x4(uint32_t* r, uint32_t a) {
    asm volatile("ldmatrix.sync.aligned.m8n8.x4.shared.b16 {%0,%1,%2,%3}, [%4];"
        : "=r"(r[0]), "=r"(r[1]), "=r"(r[2]), "=r"(r[3]) : "r"(a));
}
__device__ __forceinline__ void ldsm_x2(uint32_t* r, uint32_t a) {
    asm volatile("ldmatrix.sync.aligned.m8n8.x2.shared.b16 {%0,%1}, [%2];"
        : "=r"(r[0]), "=r"(r[1]) : "r"(a));
}
__device__ __forceinline__ void mma16816(float* d, const uint32_t* a, const uint32_t* b) {
    asm volatile("mma.sync.aligned.m16n8k16.row.col.f32.bf16.bf16.f32 "
        "{%0,%1,%2,%3}, {%4,%5,%6,%7}, {%8,%9}, {%0,%1,%2,%3};"
        : "+f"(d[0]), "+f"(d[1]), "+f"(d[2]), "+f"(d[3])
        : "r"(a[0]), "r"(a[1]), "r"(a[2]), "r"(a[3]), "r"(b[0]), "r"(b[1]));
}
__device__ __forceinline__ void cpa16(uint32_t d, const void* s) {
    asm volatile("cp.async.cg.shared.global [%0], [%1], 16;" :: "r"(d), "l"(s));
}
#define CPA_COMMIT() asm volatile("cp.async.commit_group;" ::: "memory")
#define CPA_WAIT1()  asm volatile("cp.async.wait_group 1;" ::: "memory")
#define CPA_WAIT0()  asm volatile("cp.async.wait_group 0;" ::: "memory")

__device__ __forceinline__ uint32_t packbf(float lo, float hi) {
    uint32_t r;
    asm("cvt.rn.bf16x2.f32 %0, %1, %2;" : "=r"(r) : "f"(hi), "f"(lo));
    return r;
}

// ---------------- BN fold ----------------
__global__ void fold_bn_kernel(const float* __restrict__ cv1, const float* __restrict__ cv2,
                               const float* __restrict__ mcv1, const float* __restrict__ mcv2)
{
    int c = blockIdx.x * 256 + threadIdx.x;
    if (c >= 2048) return;
    const float* p; int C, lc;
    if (c < 512)        { p = cv1;  C = 512; lc = c; }
    else if (c < 1024)  { p = cv2;  C = 512; lc = c - 512; }
    else if (c < 1536)  { int i = (c - 1024) >> 8; p = mcv1 + i * 1024; C = 256; lc = (c - 1024) & 255; }
    else                { int i = (c - 1536) >> 8; p = mcv2 + i * 1024; C = 256; lc = (c - 1536) & 255; }
    float g = p[lc], b = p[C + lc], m = p[2 * C + lc], v = p[3 * C + lc];
    float s = g / sqrtf(v + 1e-3f);
    g_scale[c] = s;
    g_bias[c]  = b - m * s;
}

// ---------------- weight converter ----------------
__global__ void convW_kernel(const float* __restrict__ W, int M, int K, int isConv,
                             __nv_bfloat16* __restrict__ Whi, __nv_bfloat16* __restrict__ Wlo)
{
    long e = (long)blockIdx.x * 256 + threadIdx.x;
    if (e >= (long)M * K) return;
    long m = e / K, k = e % K;
    float v;
    if (isConv) { int off = (int)(k >> 8), ci = (int)(k & 255); v = W[m * 2304 + ci * 9 + off]; }
    else v = W[e];
    __nv_bfloat16 h = __float2bfloat16(v);
    Whi[e] = h;
    Wlo[e] = __float2bfloat16(v - __bfloat162float(h));
}

// ---------------- activation converter: [b][K][HW] -> [b][n][K] hi/lo ----------------
__global__ void convB_kernel(const float* __restrict__ In, long inStride, int K,
                             __nv_bfloat16* __restrict__ Bhi, __nv_bfloat16* __restrict__ Blo)
{
    __shared__ float t[32][33];
    int n0 = blockIdx.x * 32, k0 = blockIdx.y * 32, b = blockIdx.z;
    int tx = threadIdx.x, ty = threadIdx.y;
    const float* in = In + (long)b * inStride;
#pragma unroll
    for (int yy = 0; yy < 32; yy += 8)
        t[yy + ty][tx] = in[(long)(k0 + yy + ty) * HW + n0 + tx];
    __syncthreads();
#pragma unroll
    for (int yy = 0; yy < 32; yy += 8) {
        int n = n0 + yy + ty, k = k0 + tx;
        float v = t[tx][yy + ty];
        long o = ((long)b * 1024 + n) * K + k;
        __nv_bfloat16 h = __float2bfloat16(v);
        Bhi[o] = h;
        Blo[o] = __float2bfloat16(v - __bfloat162float(h));
    }
}

// ---------------- im2col converter: k = (ky*3+kx)*256 + ci ----------------
__global__ void im2colB_kernel(const float* __restrict__ In, long inStride,
                               __nv_bfloat16* __restrict__ Bhi, __nv_bfloat16* __restrict__ Blo)
{
    __shared__ float t[32][33];
    int y = blockIdx.x, ci0 = blockIdx.y * 32;
    int off = blockIdx.z % 9, b = blockIdx.z / 9;
    int ky = off / 3, kx = off % 3;
    int tx = threadIdx.x, ty = threadIdx.y;
    const float* in = In + (long)b * inStride;
    int yy = y + ky - 1;
    int xx = tx + kx - 1;
    bool vy = (yy >= 0 && yy < 32), vx = (xx >= 0 && xx < 32);
#pragma unroll
    for (int d = 0; d < 32; d += 8) {
        float v = 0.f;
        if (vy && vx) v = in[(long)(ci0 + d + ty) * HW + yy * 32 + xx];
        t[d + ty][tx] = v;
    }
    __syncthreads();
#pragma unroll
    for (int d = 0; d < 32; d += 8) {
        int n = y * 32 + d + ty;
        int k = off * 256 + ci0 + tx;
        float v = t[tx][d + ty];
        long o = ((long)b * 1024 + n) * 2304 + k;
        __nv_bfloat16 h = __float2bfloat16(v);
        Bhi[o] = h;
        Blo[o] = __float2bfloat16(v - __bfloat162float(h));
    }
}

// ---------------- warp-MMA GEMM v4: cp.async 3-stage pipeline, K-chunk 32, SW64 ----------------
#define MG_STAGE 32768
#define MG_SMEM  98304   // 3 stages

__device__ __forceinline__ void mg_load(uint32_t smb, int tid,
    const uint4* __restrict__ wHi, const uint4* __restrict__ wLo,
    const uint4* __restrict__ bHi, const uint4* __restrict__ bLo,
    int m0, int n0, int K16, int c, uint32_t stOff)
{
    uint32_t sb = smb + stOff;
    int r = tid >> 1;
    int j = (tid & 1) * 2;
    uint32_t o0 = SWZ64((uint32_t)(r * 64 + j * 16));
    uint32_t o1 = SWZ64((uint32_t)(r * 64 + (j + 1) * 16));
    const uint4* a;
    a = wHi + (long)(m0 + r) * K16 + c * 4 + j;
    cpa16(sb + o0, a); cpa16(sb + o1, a + 1);
    a = wLo + (long)(m0 + r) * K16 + c * 4 + j;
    cpa16(sb + 8192 + o0, a); cpa16(sb + 8192 + o1, a + 1);
    a = bHi + (long)(n0 + r) * K16 + c * 4 + j;
    cpa16(sb + 16384 + o0, a); cpa16(sb + 16384 + o1, a + 1);
    a = bLo + (long)(n0 + r) * K16 + c * 4 + j;
    cpa16(sb + 24576 + o0, a); cpa16(sb + 24576 + o1, a + 1);
}

extern __shared__ char mg_smem[];

__global__ void __launch_bounds__(256, 2) mgemm_kernel(
    const __nv_bfloat16* __restrict__ Bhi, const __nv_bfloat16* __restrict__ Blo,
    const __nv_bfloat16* __restrict__ Whi, const __nv_bfloat16* __restrict__ Wlo,
    int K,
    float* __restrict__ Out, long outStride,
    const float* __restrict__ scale, const float* __restrict__ bias,
    const float* __restrict__ Res, long resStride,
    int doSilu)
{
    int b = blockIdx.z, m0 = blockIdx.y * 128, n0 = blockIdx.x * 128;
    int tid = threadIdx.x, wid = tid >> 5, lane = tid & 31;
    int warp_m = wid & 1, warp_n = wid >> 1;
    uint32_t smb = smem_u32(mg_smem);

    int K16 = K >> 3;
    const uint4* wHi = (const uint4*)Whi;
    const uint4* wLo = (const uint4*)Wlo;
    const uint4* bHi = (const uint4*)(Bhi + (long)b * 1024 * K);
    const uint4* bLo = (const uint4*)(Blo + (long)b * 1024 * K);

    float acc[4][4][4];
#pragma unroll
    for (int i = 0; i < 4; i++)
#pragma unroll
        for (int j = 0; j < 4; j++)
#pragma unroll
            for (int r = 0; r < 4; r++) acc[i][j][r] = 0.f;

    int nChunks = K >> 5;
    // prologue: prefetch chunks 0 and 1
    mg_load(smb, tid, wHi, wLo, bHi, bLo, m0, n0, K16, 0, 0);
    CPA_COMMIT();
    if (nChunks > 1) {
        mg_load(smb, tid, wHi, wLo, bHi, bLo, m0, n0, K16, 1, MG_STAGE);
        CPA_COMMIT();
    }

    int aRowL = warp_m * 64 + (lane & 7) + (lane & 8);
    int aColL = ((lane >> 4) & 1) * 16;
    int bRowX4 = warp_n * 32 + (lane >> 4) * 8 + (lane & 7);  // + p*16
    uint32_t bColX4 = (uint32_t)(((lane >> 3) & 1) * 16);

    int stageIdx = 0;
    for (int c = 0; c < nChunks; c++) {
        if (c + 1 < nChunks) { CPA_WAIT1(); } else { CPA_WAIT0(); }
        __syncthreads();
        if (c + 2 < nChunks) {
            int st2 = stageIdx + 2; if (st2 >= 3) st2 -= 3;
            mg_load(smb, tid, wHi, wLo, bHi, bLo, m0, n0, K16, c + 2, (uint32_t)(st2 * MG_STAGE));
            CPA_COMMIT();
        }

        uint32_t base = smb + (uint32_t)(stageIdx * MG_STAGE);
#pragma unroll
        for (int ks = 0; ks < 2; ks++) {
            uint32_t ah[4][4], bh4[2][4];
#pragma unroll
            for (int mt = 0; mt < 4; mt++)
                ldsm_x4(ah[mt], base + SWZ64((uint32_t)((aRowL + mt * 16) * 64 + aColL + ks * 32)));
#pragma unroll
            for (int p = 0; p < 2; p++)
                ldsm_x4(bh4[p], base + 16384 + SWZ64((uint32_t)((bRowX4 + p * 16) * 64 + bColX4 + ks * 32)));
#pragma unroll
            for (int mt = 0; mt < 4; mt++)
#pragma unroll
                for (int p = 0; p < 2; p++) {
                    mma16816(acc[mt][2 * p],     ah[mt], &bh4[p][0]);
                    mma16816(acc[mt][2 * p + 1], ah[mt], &bh4[p][2]);
                }

            uint32_t al[4][4];
#pragma unroll
            for (int mt = 0; mt < 4; mt++)
                ldsm_x4(al[mt], base + 8192 + SWZ64((uint32_t)((aRowL + mt * 16) * 64 + aColL + ks * 32)));
#pragma unroll
            for (int mt = 0; mt < 4; mt++)
#pragma unroll
                for (int p = 0; p < 2; p++) {
                    mma16816(acc[mt][2 * p],     al[mt], &bh4[p][0]);
                    mma16816(acc[mt][2 * p + 1], al[mt], &bh4[p][2]);
                }

            uint32_t bl4[2][4];
#pragma unroll
            for (int p = 0; p < 2; p++)
                ldsm_x4(bl4[p], base + 24576 + SWZ64((uint32_t)((bRowX4 + p * 16) * 64 + bColX4 + ks * 32)));
#pragma unroll
            for (int mt = 0; mt < 4; mt++)
#pragma unroll
                for (int p = 0; p < 2; p++) {
                    mma16816(acc[mt][2 * p],     ah[mt], &bl4[p][0]);
                    mma16816(acc[mt][2 * p + 1], ah[mt], &bl4[p][2]);
                }
        }
        stageIdx++; if (stageIdx >= 3) stageIdx = 0;
    }

#pragma unroll
    for (int mt = 0; mt < 4; mt++) {
        int mb = m0 + warp_m * 64 + mt * 16 + (lane >> 2);
#pragma unroll
        for (int h2 = 0; h2 < 2; h2++) {
            int m = mb + h2 * 8;
            float s = 1.f, bb = 0.f;
            if (scale) { s = scale[m]; bb = bias[m]; }
            long rowOff = (long)b * outStride + (long)m * HW;
            long resOff = Res ? ((long)b * resStride + (long)m * HW) : 0;
#pragma unroll
            for (int nt = 0; nt < 4; nt++) {
                int n = n0 + warp_n * 32 + nt * 8 + (lane & 3) * 2;
                float v0 = acc[mt][nt][h2 * 2 + 0] * s + bb;
                float v1 = acc[mt][nt][h2 * 2 + 1] * s + bb;
                if (doSilu) { v0 = silu_f(v0); v1 = silu_f(v1); }
                if (Res) {
                    float2 r2 = *(const float2*)&Res[resOff + n];
                    v0 += r2.x; v1 += r2.y;
                }
                *(float2*)&Out[rowOff + n] = make_float2(v0, v1);
            }
        }
    }
}

// ---------------- attention converter: qkv fp32 -> qT/kT(+relpos)/v bf16 hi/lo ----------------
__global__ void convAttn_kernel(const float* __restrict__ QKV,
                                const float* __restrict__ RW, const float* __restrict__ RH,
                                __nv_bfloat16* __restrict__ Hi, __nv_bfloat16* __restrict__ Lo)
{
    __shared__ float tq[32][33], tk[32][33];
    int it = blockIdx.x, dt = blockIdx.y, bh = blockIdx.z;
    int b = bh >> 2, hh = bh & 3;
    int tx = threadIdx.x, ty = threadIdx.y;
    const float* base = QKV + (long)b * 768 * HW;
#pragma unroll
    for (int l = 0; l < 4; l++) {
        int d = dt * 32 + ty + l * 8;
        int ch = hh * 64 + d;
        float qv = base[(long)ch * HW + it * 32 + tx] * 0.125f;
        float kv = base[(long)(256 + ch) * HW + it * 32 + tx] + RW[ch * 32 + tx] + RH[ch * 32 + it];
        float vv = base[(long)(512 + ch) * HW + it * 32 + tx];
        tq[ty + l * 8][tx] = qv;
        tk[ty + l * 8][tx] = kv;
        long vo = V_OFF + ((long)bh * 64 + d) * 1024 + it * 32 + tx;
        __nv_bfloat16 vh = __float2bfloat16(vv);
        Hi[vo] = vh;
        Lo[vo] = __float2bfloat16(vv - __bfloat162float(vh));
    }
    __syncthreads();
#pragma unroll
    for (int l = 0; l < 4; l++) {
        int i = it * 32 + ty + l * 8;
        int d = dt * 32 + tx;
        float qv = tq[tx][ty + l * 8];
        float kv = tk[tx][ty + l * 8];
        long qo = ((long)bh * 1024 + i) * 64 + d;
        __nv_bfloat16 qh = __float2bfloat16(qv);
        Hi[QT_OFF + qo] = qh;
        Lo[QT_OFF + qo] = __float2bfloat16(qv - __bfloat162float(qh));
        __nv_bfloat16 kh = __float2bfloat16(kv);
        Hi[KT_OFF + qo] = kh;
        Lo[KT_OFF + qo] = __float2bfloat16(kv - __bfloat162float(kh));
    }
}

// ---------------- MMA flash attention ----------------
#define AT_SMEM 163840

__device__ __forceinline__ void kv_load(uint32_t smb, int tid,
    const __nv_bfloat16* __restrict__ kTh, const __nv_bfloat16* __restrict__ kTl,
    const __nv_bfloat16* __restrict__ vH, const __nv_bfloat16* __restrict__ vL,
    int bh, int t, uint32_t stOff)
{
    uint32_t kb = smb + stOff;
    const uint4* kh4 = (const uint4*)(kTh + ((long)bh * 1024 + t * 128) * 64);
    const uint4* kl4 = (const uint4*)(kTl + ((long)bh * 1024 + t * 128) * 64);
    int r = tid >> 1, j0 = (tid & 1) * 4;
#pragma unroll
    for (int j = 0; j < 4; j++) {
        uint32_t off = SWZ128((uint32_t)(r * 128 + (j0 + j) * 16));
        cpa16(kb + off, kh4 + (long)r * 8 + j0 + j);
        cpa16(kb + 16384 + off, kl4 + (long)r * 8 + j0 + j);
    }
    const uint4* vh4 = (const uint4*)(vH + (long)bh * 65536 + t * 128);
    const uint4* vl4 = (const uint4*)(vL + (long)bh * 65536 + t * 128);
    int d = tid >> 2, jc0 = (tid & 3) * 4;
#pragma unroll
    for (int j = 0; j < 4; j++) {
        int jc = jc0 + j;
        uint32_t off = (uint32_t)((jc >> 3) * 8192) + SWZ128((uint32_t)(d * 128 + (jc & 7) * 16));
        cpa16(kb + 32768 + off, vh4 + (long)d * 128 + jc);
        cpa16(kb + 49152 + off, vl4 + (long)d * 128 + jc);
    }
}

extern __shared__ char at_smem[];

__global__ void __launch_bounds__(256) attn_mma_kernel(
    const __nv_bfloat16* __restrict__ Hi, const __nv_bfloat16* __restrict__ Lo,
    float* __restrict__ Outp)
{
    int qt = blockIdx.x, h = blockIdx.y, b = blockIdx.z;
    int bh = b * 4 + h;
    int tid = threadIdx.x, wid = tid >> 5, lane = tid & 31, li = lane & 15;
    uint32_t smb = smem_u32(at_smem);

    const __nv_bfloat16* qTh = Hi + QT_OFF;
    const __nv_bfloat16* qTl = Lo + QT_OFF;
    const __nv_bfloat16* kTh = Hi + KT_OFF;
    const __nv_bfloat16* kTl = Lo + KT_OFF;
    const __nv_bfloat16* vH  = Hi + V_OFF;
    const __nv_bfloat16* vL  = Lo + V_OFF;

    {
        const uint4* qh4 = (const uint4*)(qTh + ((long)bh * 1024 + qt * 128) * 64);
        const uint4* ql4 = (const uint4*)(qTl + ((long)bh * 1024 + qt * 128) * 64);
        int r = tid >> 1, j0 = (tid & 1) * 4;
        uint32_t qb = smb + 131072;
#pragma unroll
        for (int j = 0; j < 4; j++) {
            uint32_t off = SWZ128((uint32_t)(r * 128 + (j0 + j) * 16));
            cpa16(qb + off, qh4 + (long)r * 8 + j0 + j);
            cpa16(qb + 16384 + off, ql4 + (long)r * 8 + j0 + j);
        }
    }
    CPA_COMMIT();
    kv_load(smb, tid, kTh, kTl, vH, vL, bh, 0, 0);
    CPA_COMMIT();
    CPA_WAIT1();
    __syncthreads();

    uint32_t qfh[4][4], qfl[4][4];
    {
        int aRow = wid * 16 + (lane & 7) + (lane & 8);
        int aCol = ((lane >> 4) & 1) * 16;
#pragma unroll
        for (int ks = 0; ks < 4; ks++) {
            uint32_t off = SWZ128((uint32_t)(aRow * 128 + aCol + ks * 32));
            ldsm_x4(qfh[ks], smb + 131072 + off);
            ldsm_x4(qfl[ks], smb + 131072 + 16384 + off);
        }
    }

    float oacc[8][4];
#pragma unroll
    for (int i = 0; i < 8; i++)
#pragma unroll
        for (int j = 0; j < 4; j++) oacc[i][j] = 0.f;
    float m0 = -1e30f, m1 = -1e30f, l0 = 0.f, l1 = 0.f;

    int sRowX4 = (lane >> 4) * 8 + (lane & 7);
    uint32_t sColX4 = (uint32_t)(((lane >> 3) & 1) * 16);

    for (int t = 0; t < 8; t++) {
        int s = t & 1;
        if (t < 7) {
            kv_load(smb, tid, kTh, kTl, vH, vL, bh, t + 1, (uint32_t)((s ^ 1) * 65536));
            CPA_COMMIT();
            CPA_WAIT1();
        } else {
            CPA_WAIT0();
        }
        __syncthreads();

        uint32_t kb = smb + s * 65536;
        float sacc[16][4];
#pragma unroll
        for (int i = 0; i < 16; i++)
#pragma unroll
            for (int j = 0; j < 4; j++) sacc[i][j] = 0.f;

#pragma unroll
        for (int p = 0; p < 8; p++) {
            int rowB = p * 16 + sRowX4;
#pragma unroll
            for (int ks = 0; ks < 4; ks++) {
                uint32_t off = SWZ128((uint32_t)(rowB * 128 + sColX4 + ks * 32));
                uint32_t kh4[4], kl4[4];
                ldsm_x4(kh4, kb + off);
                ldsm_x4(kl4, kb + 16384 + off);
                mma16816(sacc[2 * p],     qfh[ks], &kh4[0]);
                mma16816(sacc[2 * p + 1], qfh[ks], &kh4[2]);
                mma16816(sacc[2 * p],     qfl[ks], &kh4[0]);
                mma16816(sacc[2 * p + 1], qfl[ks], &kh4[2]);
                mma16816(sacc[2 * p],     qfh[ks], &kl4[0]);
                mma16816(sacc[2 * p + 1], qfh[ks], &kl4[2]);
            }
        }

        float mx0 = m0, mx1 = m1;
#pragma unroll
        for (int nt = 0; nt < 16; nt++) {
            mx0 = fmaxf(mx0, fmaxf(sacc[nt][0], sacc[nt][1]));
            mx1 = fmaxf(mx1, fmaxf(sacc[nt][2], sacc[nt][3]));
        }
        mx0 = fmaxf(mx0, __shfl_xor_sync(0xffffffffu, mx0, 1));
        mx0 = fmaxf(mx0, __shfl_xor_sync(0xffffffffu, mx0, 2));
        mx1 = fmaxf(mx1, __shfl_xor_sync(0xffffffffu, mx1, 1));
        mx1 = fmaxf(mx1, __shfl_xor_sync(0xffffffffu, mx1, 2));
        float a0 = __expf(m0 - mx0), a1 = __expf(m1 - mx1);
        m0 = mx0; m1 = mx1;

        float ls0 = 0.f, ls1 = 0.f;
        uint32_t pah[8][4], pal[8][4];
#pragma unroll
        for (int kj = 0; kj < 8; kj++) {
            float p00 = __expf(sacc[2 * kj][0] - m0);
            float p01 = __expf(sacc[2 * kj][1] - m0);
            float p02 = __expf(sacc[2 * kj][2] - m1);
            float p03 = __expf(sacc[2 * kj][3] - m1);
            float p10 = __expf(sacc[2 * kj + 1][0] - m0);
            float p11 = __expf(sacc[2 * kj + 1][1] - m0);
            float p12 = __expf(sacc[2 * kj + 1][2] - m1);
            float p13 = __expf(sacc[2 * kj + 1][3] - m1);
            ls0 += p00 + p01 + p10 + p11;
            ls1 += p02 + p03 + p12 + p13;
            pah[kj][0] = packbf(p00, p01);
            pah[kj][1] = packbf(p02, p03);
            pah[kj][2] = packbf(p10, p11);
            pah[kj][3] = packbf(p12, p13);
            float q00 = p00 - __bfloat162float(__float2bfloat16(p00));
            float q01 = p01 - __bfloat162float(__float2bfloat16(p01));
            float q02 = p02 - __bfloat162float(__float2bfloat16(p02));
            float q03 = p03 - __bfloat162float(__float2bfloat16(p03));
            float q10 = p10 - __bfloat162float(__float2bfloat16(p10));
            float q11 = p11 - __bfloat162float(__float2bfloat16(p11));
            float q12 = p12 - __bfloat162float(__float2bfloat16(p12));
            float q13 = p13 - __bfloat162float(__float2bfloat16(p13));
            pal[kj][0] = packbf(q00, q01);
            pal[kj][1] = packbf(q02, q03);
            pal[kj][2] = packbf(q10, q11);
            pal[kj][3] = packbf(q12, q13);
        }
        ls0 += __shfl_xor_sync(0xffffffffu, ls0, 1);
        ls0 += __shfl_xor_sync(0xffffffffu, ls0, 2);
        ls1 += __shfl_xor_sync(0xffffffffu, ls1, 1);
        ls1 += __shfl_xor_sync(0xffffffffu, ls1, 2);
        l0 = l0 * a0 + ls0;
        l1 = l1 * a1 + ls1;
#pragma unroll
        for (int dt = 0; dt < 8; dt++) {
            oacc[dt][0] *= a0; oacc[dt][1] *= a0;
            oacc[dt][2] *= a1; oacc[dt][3] *= a1;
        }

#pragma unroll
        for (int dt = 0; dt < 8; dt++) {
            int rowV = dt * 8 + (li & 7);
#pragma unroll
            for (int kj = 0; kj < 8; kj++) {
                uint32_t off = (uint32_t)((kj >> 2) * 8192) +
                               SWZ128((uint32_t)(rowV * 128 + (li >> 3) * 16 + (kj & 3) * 32));
                uint32_t vh2[2], vl2[2];
                ldsm_x2(vh2, kb + 32768 + off);
                ldsm_x2(vl2, kb + 49152 + off);
                mma16816(oacc[dt], pah[kj], vh2);
                mma16816(oacc[dt], pal[kj], vh2);
                mma16816(oacc[dt], pah[kj], vl2);
            }
        }
        __syncthreads();
    }

    float i0 = 1.f / l0, i1 = 1.f / l1;
    float* stg = (float*)at_smem;   // [128][66]
    int r0 = wid * 16 + (lane >> 2);
#pragma unroll
    for (int dt = 0; dt < 8; dt++) {
        int d = dt * 8 + (lane & 3) * 2;
        stg[r0 * 66 + d]           = oacc[dt][0] * i0;
        stg[r0 * 66 + d + 1]       = oacc[dt][1] * i0;
        stg[(r0 + 8) * 66 + d]     = oacc[dt][2] * i1;
        stg[(r0 + 8) * 66 + d + 1] = oacc[dt][3] * i1;
    }
    __syncthreads();
    for (int e = tid; e < 8192; e += 256) {
        int d = e >> 7, i = e & 127;
        Outp[((long)b * 256 + h * 64 + d) * HW + qt * 128 + i] = stg[i * 66 + d];
    }
}

// ---------------- launch ----------------
extern "C" void kernel_launch(void* const* d_in, const int* in_sizes, int n_in,
                              void* d_out, int out_size)
{
    const float* x      = (const float*)d_in[0];
    const float* cv1_w  = (const float*)d_in[1];
    const float* cv1_bn = (const float*)d_in[2];
    const float* cv2_w  = (const float*)d_in[3];
    const float* cv2_bn = (const float*)d_in[4];
    const float* mcv1w  = (const float*)d_in[5];
    const float* mcv1bn = (const float*)d_in[6];
    const float* mqkvw  = (const float*)d_in[7];
    const float* mrw    = (const float*)d_in[8];
    const float* mrh    = (const float*)d_in[9];
    const float* mcv2w  = (const float*)d_in[10];
    const float* mcv2bn = (const float*)d_in[11];
    float* out = (float*)d_out;

    float *cat, *z, *qkv, *atto, *scl, *bia;
    __nv_bfloat16 *whi, *wlo, *bhi, *blo;
    cudaGetSymbolAddress((void**)&cat,  g_cat);
    cudaGetSymbolAddress((void**)&z,    g_z);
    cudaGetSymbolAddress((void**)&qkv,  g_qkv);
    cudaGetSymbolAddress((void**)&atto, g_atto);
    cudaGetSymbolAddress((void**)&scl,  g_scale);
    cudaGetSymbolAddress((void**)&bia,  g_bias);
    cudaGetSymbolAddress((void**)&whi,  g_Whi);
    cudaGetSymbolAddress((void**)&wlo,  g_Wlo);
    cudaGetSymbolAddress((void**)&bhi,  g_Bhi);
    cudaGetSymbolAddress((void**)&blo,  g_Blo);

    cudaFuncSetAttribute(mgemm_kernel, cudaFuncAttributeMaxDynamicSharedMemorySize, MG_SMEM);
    cudaFuncSetAttribute(attn_mma_kernel, cudaFuncAttributeMaxDynamicSharedMemorySize, AT_SMEM);

    fold_bn_kernel<<<8, 256>>>(cv1_bn, cv2_bn, mcv1bn, mcv2bn);

    // ---- cv1: 512 -> 512, BN+SiLU, into cat[0:512) ----
    convW_kernel<<<(512 * 512 + 255) / 256, 256>>>(cv1_w, 512, 512, 0, whi, wlo);
    convB_kernel<<<dim3(32, 16, 8), dim3(32, 8)>>>(x, (long)512 * HW, 512, bhi, blo);
    mgemm_kernel<<<dim3(8, 4, 8), 256, MG_SMEM>>>(
        bhi, blo, whi, wlo, 512, cat, (long)1024 * HW,
        scl + 0, bia + 0, nullptr, 0, 1);

    for (int i = 0; i < 2; i++) {
        long yin  = (long)(i == 0 ? 256 : 512) * HW;
        long yout = (long)(512 + i * 256) * HW;

        // z = cbs(yi, 3x3) as implicit GEMM, K=2304
        convW_kernel<<<(256 * 2304 + 255) / 256, 256>>>(
            mcv1w + (long)i * 256 * 2304, 256, 2304, 1, whi, wlo);
        im2colB_kernel<<<dim3(32, 8, 72), dim3(32, 8)>>>(cat + yin, (long)1024 * HW, bhi, blo);
        mgemm_kernel<<<dim3(8, 2, 8), 256, MG_SMEM>>>(
            bhi, blo, whi, wlo, 2304, z, (long)256 * HW,
            scl + 1024 + i * 256, bia + 1024 + i * 256, nullptr, 0, 1);

        // qkv = conv1x1(z), 256 -> 768
        convW_kernel<<<(768 * 256 + 255) / 256, 256>>>(
            mqkvw + (long)i * 768 * 256, 768, 256, 0, whi, wlo);
        convB_kernel<<<dim3(32, 8, 8), dim3(32, 8)>>>(z, (long)256 * HW, 256, bhi, blo);
        mgemm_kernel<<<dim3(8, 6, 8), 256, MG_SMEM>>>(
            bhi, blo, whi, wlo, 256, qkv, (long)768 * HW,
            nullptr, nullptr, nullptr, 0, 0);

        // attention operand conversion + MMA flash attention
        convAttn_kernel<<<dim3(32, 2, 32), dim3(32, 8)>>>(
            qkv, mrw + (long)i * 8192, mrh + (long)i * 8192, bhi, blo);
        attn_mma_kernel<<<dim3(8, 4, 8), 256, AT_SMEM>>>(bhi, blo, atto);

        // y_{i+2} = yi + silu(bn(conv1x1(atto)))
        convW_kernel<<<(256 * 256 + 255) / 256, 256>>>(
            mcv2w + (long)i * 256 * 256, 256, 256, 0, whi, wlo);
        convB_kernel<<<dim3(32, 8, 8), dim3(32, 8)>>>(atto, (long)256 * HW, 256, bhi, blo);
        mgemm_kernel<<<dim3(8, 2, 8), 256, MG_SMEM>>>(
            bhi, blo, whi, wlo, 256, cat + yout, (long)1024 * HW,
            scl + 1536 + i * 256, bia + 1536 + i * 256, cat + yin, (long)1024 * HW, 1);
    }

    // ---- final: 1024 -> 512, BN+SiLU ----
    convW_kernel<<<(512 * 1024 + 255) / 256, 256>>>(cv2_w, 512, 1024, 0, whi, wlo);
    convB_kernel<<<dim3(32, 32, 8), dim3(32, 8)>>>(cat, (long)1024 * HW, 1024, bhi, blo);
    mgemm_kernel<<<dim3(8, 4, 8), 256, MG_SMEM>>>(
        bhi, blo, whi, wlo, 1024, out, (long)512 * HW,
        scl + 512, bia + 512, nullptr, 0, 1);
}

// round 7
// speedup vs baseline: 1.1304x; 1.0290x over previous
#include <cuda_runtime.h>
#include <cuda_bf16.h>
#include <cstdint>

#define HW 1024

// ---------------- scratch (__device__ globals: alloc-guard-safe) ----------------
__device__ float g_cat [8u * 1024u * HW];   // 32 MB
__device__ float g_z   [8u * 256u  * HW];   //  8 MB
__device__ float g_qkv [8u * 768u  * HW];   // 24 MB
__device__ float g_atto[8u * 256u  * HW];   //  8 MB
__device__ float g_scale[2048];
__device__ float g_bias [2048];
__device__ __nv_bfloat16 g_Whi[589824];
__device__ __nv_bfloat16 g_Wlo[589824];
__device__ __nv_bfloat16 g_Bhi[18874368];
__device__ __nv_bfloat16 g_Blo[18874368];

// offsets (elements) inside g_Bhi/g_Blo for attention operands
#define QT_OFF 0
#define KT_OFF 2097152
#define V_OFF  4194304

__device__ __forceinline__ float silu_f(float v) { return v / (1.f + __expf(-v)); }

__device__ __forceinline__ uint32_t smem_u32(const void* p) {
    uint32_t a;
    asm("{ .reg .u64 t; cvta.to.shared.u64 t, %1; cvt.u32.u64 %0, t; }" : "=r"(a) : "l"(p));
    return a;
}
#define SWZ128(o) ((o) ^ (((o) >> 3) & 0x70))
#define SWZ64(o)  ((o) ^ (((o) >> 3) & 0x30))

__device__ __forceinline__ void ldsm_x4(uint32_t* r, uint32_t a) {
    asm volatile("ldmatrix.sync.aligned.m8n8.x4.shared.b16 {%0,%1,%2,%3}, [%4];"
        : "=r"(r[0]), "=r"(r[1]), "=r"(r[2]), "=r"(r[3]) : "r"(a));
}
__device__ __forceinline__ void ldsm_x2(uint32_t* r, uint32_t a) {
    asm volatile("ldmatrix.sync.aligned.m8n8.x2.shared.b16 {%0,%1}, [%2];"
        : "=r"(r[0]), "=r"(r[1]) : "r"(a));
}
__device__ __forceinline__ void mma16816(float* d, const uint32_t* a, const uint32_t* b) {
    asm volatile("mma.sync.aligned.m16n8k16.row.col.f32.bf16.bf16.f32 "
        "{%0,%1,%2,%3}, {%4,%5,%6,%7}, {%8,%9}, {%0,%1,%2,%3};"
        : "+f"(d[0]), "+f"(d[1]), "+f"(d[2]), "+f"(d[3])
        : "r"(a[0]), "r"(a[1]), "r"(a[2]), "r"(a[3]), "r"(b[0]), "r"(b[1]));
}
__device__ __forceinline__ void cpa16(uint32_t d, const void* s) {
    asm volatile("cp.async.cg.shared.global [%0], [%1], 16;" :: "r"(d), "l"(s));
}
#define CPA_COMMIT() asm volatile("cp.async.commit_group;" ::: "memory")
#define CPA_WAIT1()  asm volatile("cp.async.wait_group 1;" ::: "memory")
#define CPA_WAIT0()  asm volatile("cp.async.wait_group 0;" ::: "memory")

__device__ __forceinline__ uint32_t packbf(float lo, float hi) {
    uint32_t r;
    asm("cvt.rn.bf16x2.f32 %0, %1, %2;" : "=r"(r) : "f"(hi), "f"(lo));
    return r;
}

// ---------------- BN fold ----------------
__global__ void fold_bn_kernel(const float* __restrict__ cv1, const float* __restrict__ cv2,
                               const float* __restrict__ mcv1, const float* __restrict__ mcv2)
{
    int c = blockIdx.x * 256 + threadIdx.x;
    if (c >= 2048) return;
    const float* p; int C, lc;
    if (c < 512)        { p = cv1;  C = 512; lc = c; }
    else if (c < 1024)  { p = cv2;  C = 512; lc = c - 512; }
    else if (c < 1536)  { int i = (c - 1024) >> 8; p = mcv1 + i * 1024; C = 256; lc = (c - 1024) & 255; }
    else                { int i = (c - 1536) >> 8; p = mcv2 + i * 1024; C = 256; lc = (c - 1536) & 255; }
    float g = p[lc], b = p[C + lc], m = p[2 * C + lc], v = p[3 * C + lc];
    float s = g / sqrtf(v + 1e-3f);
    g_scale[c] = s;
    g_bias[c]  = b - m * s;
}

// ---------------- weight converter ----------------
__global__ void convW_kernel(const float* __restrict__ W, int M, int K, int isConv,
                             __nv_bfloat16* __restrict__ Whi, __nv_bfloat16* __restrict__ Wlo)
{
    long e = (long)blockIdx.x * 256 + threadIdx.x;
    if (e >= (long)M * K) return;
    long m = e / K, k = e % K;
    float v;
    if (isConv) { int off = (int)(k >> 8), ci = (int)(k & 255); v = W[m * 2304 + ci * 9 + off]; }
    else v = W[e];
    __nv_bfloat16 h = __float2bfloat16(v);
    Whi[e] = h;
    Wlo[e] = __float2bfloat16(v - __bfloat162float(h));
}

// ---------------- activation converter: [b][K][HW] -> [b][n][K] hi/lo ----------------
__global__ void convB_kernel(const float* __restrict__ In, long inStride, int K,
                             __nv_bfloat16* __restrict__ Bhi, __nv_bfloat16* __restrict__ Blo)
{
    __shared__ float t[32][33];
    int n0 = blockIdx.x * 32, k0 = blockIdx.y * 32, b = blockIdx.z;
    int tx = threadIdx.x, ty = threadIdx.y;
    const float* in = In + (long)b * inStride;
#pragma unroll
    for (int yy = 0; yy < 32; yy += 8)
        t[yy + ty][tx] = in[(long)(k0 + yy + ty) * HW + n0 + tx];
    __syncthreads();
#pragma unroll
    for (int yy = 0; yy < 32; yy += 8) {
        int n = n0 + yy + ty, k = k0 + tx;
        float v = t[tx][yy + ty];
        long o = ((long)b * 1024 + n) * K + k;
        __nv_bfloat16 h = __float2bfloat16(v);
        Bhi[o] = h;
        Blo[o] = __float2bfloat16(v - __bfloat162float(h));
    }
}

// ---------------- im2col converter: k = (ky*3+kx)*256 + ci ----------------
__global__ void im2colB_kernel(const float* __restrict__ In, long inStride,
                               __nv_bfloat16* __restrict__ Bhi, __nv_bfloat16* __restrict__ Blo)
{
    __shared__ float t[32][33];
    int y = blockIdx.x, ci0 = blockIdx.y * 32;
    int off = blockIdx.z % 9, b = blockIdx.z / 9;
    int ky = off / 3, kx = off % 3;
    int tx = threadIdx.x, ty = threadIdx.y;
    const float* in = In + (long)b * inStride;
    int yy = y + ky - 1;
    int xx = tx + kx - 1;
    bool vy = (yy >= 0 && yy < 32), vx = (xx >= 0 && xx < 32);
#pragma unroll
    for (int d = 0; d < 32; d += 8) {
        float v = 0.f;
        if (vy && vx) v = in[(long)(ci0 + d + ty) * HW + yy * 32 + xx];
        t[d + ty][tx] = v;
    }
    __syncthreads();
#pragma unroll
    for (int d = 0; d < 32; d += 8) {
        int n = y * 32 + d + ty;
        int k = off * 256 + ci0 + tx;
        float v = t[tx][d + ty];
        long o = ((long)b * 1024 + n) * 2304 + k;
        __nv_bfloat16 h = __float2bfloat16(v);
        Bhi[o] = h;
        Blo[o] = __float2bfloat16(v - __bfloat162float(h));
    }
}

// ---------------- warp-MMA GEMM (N-tile 128): cp.async 2-stage, K-chunk 32, SW64 ----------------
#define MG_STAGE 32768
#define MG_SMEM  65536

__device__ __forceinline__ void mg_load(uint32_t smb, int tid,
    const uint4* __restrict__ wHi, const uint4* __restrict__ wLo,
    const uint4* __restrict__ bHi, const uint4* __restrict__ bLo,
    int m0, int n0, int K16, int c, uint32_t stOff)
{
    uint32_t sb = smb + stOff;
    int r = tid >> 1;
    int j = (tid & 1) * 2;
    uint32_t o0 = SWZ64((uint32_t)(r * 64 + j * 16));
    uint32_t o1 = SWZ64((uint32_t)(r * 64 + (j + 1) * 16));
    const uint4* a;
    a = wHi + (long)(m0 + r) * K16 + c * 4 + j;
    cpa16(sb + o0, a); cpa16(sb + o1, a + 1);
    a = wLo + (long)(m0 + r) * K16 + c * 4 + j;
    cpa16(sb + 8192 + o0, a); cpa16(sb + 8192 + o1, a + 1);
    a = bHi + (long)(n0 + r) * K16 + c * 4 + j;
    cpa16(sb + 16384 + o0, a); cpa16(sb + 16384 + o1, a + 1);
    a = bLo + (long)(n0 + r) * K16 + c * 4 + j;
    cpa16(sb + 24576 + o0, a); cpa16(sb + 24576 + o1, a + 1);
}

extern __shared__ char mg_smem[];

__global__ void __launch_bounds__(256, 2) mgemm_kernel(
    const __nv_bfloat16* __restrict__ Bhi, const __nv_bfloat16* __restrict__ Blo,
    const __nv_bfloat16* __restrict__ Whi, const __nv_bfloat16* __restrict__ Wlo,
    int K,
    float* __restrict__ Out, long outStride,
    const float* __restrict__ scale, const float* __restrict__ bias,
    const float* __restrict__ Res, long resStride,
    int doSilu)
{
    int b = blockIdx.z, m0 = blockIdx.y * 128, n0 = blockIdx.x * 128;
    int tid = threadIdx.x, wid = tid >> 5, lane = tid & 31;
    int warp_m = wid & 1, warp_n = wid >> 1;
    uint32_t smb = smem_u32(mg_smem);

    int K16 = K >> 3;
    const uint4* wHi = (const uint4*)Whi;
    const uint4* wLo = (const uint4*)Wlo;
    const uint4* bHi = (const uint4*)(Bhi + (long)b * 1024 * K);
    const uint4* bLo = (const uint4*)(Blo + (long)b * 1024 * K);

    float acc[4][4][4];
#pragma unroll
    for (int i = 0; i < 4; i++)
#pragma unroll
        for (int j = 0; j < 4; j++)
#pragma unroll
            for (int r = 0; r < 4; r++) acc[i][j][r] = 0.f;

    int nChunks = K >> 5;
    mg_load(smb, tid, wHi, wLo, bHi, bLo, m0, n0, K16, 0, 0);
    CPA_COMMIT();

    int aRowL = warp_m * 64 + (lane & 7) + (lane & 8);
    int aColL = ((lane >> 4) & 1) * 16;
    int bRowX4 = warp_n * 32 + (lane >> 4) * 8 + (lane & 7);  // + p*16
    uint32_t bColX4 = (uint32_t)(((lane >> 3) & 1) * 16);

    for (int c = 0; c < nChunks; c++) {
        int s = c & 1;
        if (c + 1 < nChunks) {
            mg_load(smb, tid, wHi, wLo, bHi, bLo, m0, n0, K16, c + 1, (uint32_t)((s ^ 1) * MG_STAGE));
            CPA_COMMIT();
            CPA_WAIT1();
        } else {
            CPA_WAIT0();
        }
        __syncthreads();

        uint32_t base = smb + s * MG_STAGE;
#pragma unroll
        for (int ks = 0; ks < 2; ks++) {
            uint32_t ah[4][4], bh4[2][4];
#pragma unroll
            for (int mt = 0; mt < 4; mt++)
                ldsm_x4(ah[mt], base + SWZ64((uint32_t)((aRowL + mt * 16) * 64 + aColL + ks * 32)));
#pragma unroll
            for (int p = 0; p < 2; p++)
                ldsm_x4(bh4[p], base + 16384 + SWZ64((uint32_t)((bRowX4 + p * 16) * 64 + bColX4 + ks * 32)));
#pragma unroll
            for (int mt = 0; mt < 4; mt++)
#pragma unroll
                for (int p = 0; p < 2; p++) {
                    mma16816(acc[mt][2 * p],     ah[mt], &bh4[p][0]);
                    mma16816(acc[mt][2 * p + 1], ah[mt], &bh4[p][2]);
                }

            uint32_t al[4][4];
#pragma unroll
            for (int mt = 0; mt < 4; mt++)
                ldsm_x4(al[mt], base + 8192 + SWZ64((uint32_t)((aRowL + mt * 16) * 64 + aColL + ks * 32)));
#pragma unroll
            for (int mt = 0; mt < 4; mt++)
#pragma unroll
                for (int p = 0; p < 2; p++) {
                    mma16816(acc[mt][2 * p],     al[mt], &bh4[p][0]);
                    mma16816(acc[mt][2 * p + 1], al[mt], &bh4[p][2]);
                }

            uint32_t bl4[2][4];
#pragma unroll
            for (int p = 0; p < 2; p++)
                ldsm_x4(bl4[p], base + 24576 + SWZ64((uint32_t)((bRowX4 + p * 16) * 64 + bColX4 + ks * 32)));
#pragma unroll
            for (int mt = 0; mt < 4; mt++)
#pragma unroll
                for (int p = 0; p < 2; p++) {
                    mma16816(acc[mt][2 * p],     ah[mt], &bl4[p][0]);
                    mma16816(acc[mt][2 * p + 1], ah[mt], &bl4[p][2]);
                }
        }
        __syncthreads();
    }

#pragma unroll
    for (int mt = 0; mt < 4; mt++) {
        int mb = m0 + warp_m * 64 + mt * 16 + (lane >> 2);
#pragma unroll
        for (int h2 = 0; h2 < 2; h2++) {
            int m = mb + h2 * 8;
            float s = 1.f, bb = 0.f;
            if (scale) { s = scale[m]; bb = bias[m]; }
            long rowOff = (long)b * outStride + (long)m * HW;
            long resOff = Res ? ((long)b * resStride + (long)m * HW) : 0;
#pragma unroll
            for (int nt = 0; nt < 4; nt++) {
                int n = n0 + warp_n * 32 + nt * 8 + (lane & 3) * 2;
                float v0 = acc[mt][nt][h2 * 2 + 0] * s + bb;
                float v1 = acc[mt][nt][h2 * 2 + 1] * s + bb;
                if (doSilu) { v0 = silu_f(v0); v1 = silu_f(v1); }
                if (Res) {
                    float2 r2 = *(const float2*)&Res[resOff + n];
                    v0 += r2.x; v1 += r2.y;
                }
                *(float2*)&Out[rowOff + n] = make_float2(v0, v1);
            }
        }
    }
}

// ---------------- warp-MMA GEMM (N-tile 64): for small-grid GEMMs (3x3 conv, cv2m) ----------------
// M-tile 128 x N-tile 64, warp grid 4(m) x 2(n), warp tile 32x32, K-chunk 32, 2-stage.
#define MG64_STAGE 24576
#define MG64_SMEM  49152

__device__ __forceinline__ void mg64_load(uint32_t smb, int tid,
    const uint4* __restrict__ wHi, const uint4* __restrict__ wLo,
    const uint4* __restrict__ bHi, const uint4* __restrict__ bLo,
    int m0, int n0, int K16, int c, uint32_t stOff)
{
    uint32_t sb = smb + stOff;
    // A: 128 rows x 64B (hi at 0, lo at 8192)
    int r = tid >> 1, j = (tid & 1) * 2;
    uint32_t o0 = SWZ64((uint32_t)(r * 64 + j * 16));
    uint32_t o1 = SWZ64((uint32_t)(r * 64 + (j + 1) * 16));
    const uint4* a;
    a = wHi + (long)(m0 + r) * K16 + c * 4 + j;
    cpa16(sb + o0, a); cpa16(sb + o1, a + 1);
    a = wLo + (long)(m0 + r) * K16 + c * 4 + j;
    cpa16(sb + 8192 + o0, a); cpa16(sb + 8192 + o1, a + 1);
    // B: 64 rows x 64B (hi at 16384, lo at 20480)
    int rb = tid >> 2, jb = tid & 3;
    uint32_t ob = SWZ64((uint32_t)(rb * 64 + jb * 16));
    a = bHi + (long)(n0 + rb) * K16 + c * 4 + jb;
    cpa16(sb + 16384 + ob, a);
    a = bLo + (long)(n0 + rb) * K16 + c * 4 + jb;
    cpa16(sb + 20480 + ob, a);
}

__global__ void __launch_bounds__(256, 2) mgemm64_kernel(
    const __nv_bfloat16* __restrict__ Bhi, const __nv_bfloat16* __restrict__ Blo,
    const __nv_bfloat16* __restrict__ Whi, const __nv_bfloat16* __restrict__ Wlo,
    int K,
    float* __restrict__ Out, long outStride,
    const float* __restrict__ scale, const float* __restrict__ bias,
    const float* __restrict__ Res, long resStride,
    int doSilu)
{
    int b = blockIdx.z, m0 = blockIdx.y * 128, n0 = blockIdx.x * 64;
    int tid = threadIdx.x, wid = tid >> 5, lane = tid & 31;
    int warp_m = wid & 3, warp_n = wid >> 2;
    uint32_t smb = smem_u32(mg_smem);

    int K16 = K >> 3;
    const uint4* wHi = (const uint4*)Whi;
    const uint4* wLo = (const uint4*)Wlo;
    const uint4* bHi = (const uint4*)(Bhi + (long)b * 1024 * K);
    const uint4* bLo = (const uint4*)(Blo + (long)b * 1024 * K);

    float acc[2][4][4];
#pragma unroll
    for (int i = 0; i < 2; i++)
#pragma unroll
        for (int j = 0; j < 4; j++)
#pragma unroll
            for (int r = 0; r < 4; r++) acc[i][j][r] = 0.f;

    int nChunks = K >> 5;
    mg64_load(smb, tid, wHi, wLo, bHi, bLo, m0, n0, K16, 0, 0);
    CPA_COMMIT();

    int aRowL = warp_m * 32 + (lane & 7) + (lane & 8);
    int aColL = ((lane >> 4) & 1) * 16;
    int bRowX4 = warp_n * 32 + (lane >> 4) * 8 + (lane & 7);  // + p*16
    uint32_t bColX4 = (uint32_t)(((lane >> 3) & 1) * 16);

    for (int c = 0; c < nChunks; c++) {
        int s = c & 1;
        if (c + 1 < nChunks) {
            mg64_load(smb, tid, wHi, wLo, bHi, bLo, m0, n0, K16, c + 1, (uint32_t)((s ^ 1) * MG64_STAGE));
            CPA_COMMIT();
            CPA_WAIT1();
        } else {
            CPA_WAIT0();
        }
        __syncthreads();

        uint32_t base = smb + s * MG64_STAGE;
#pragma unroll
        for (int ks = 0; ks < 2; ks++) {
            uint32_t ah[2][4], bh4[2][4];
#pragma unroll
            for (int mt = 0; mt < 2; mt++)
                ldsm_x4(ah[mt], base + SWZ64((uint32_t)((aRowL + mt * 16) * 64 + aColL + ks * 32)));
#pragma unroll
            for (int p = 0; p < 2; p++)
                ldsm_x4(bh4[p], base + 16384 + SWZ64((uint32_t)((bRowX4 + p * 16) * 64 + bColX4 + ks * 32)));
#pragma unroll
            for (int mt = 0; mt < 2; mt++)
#pragma unroll
                for (int p = 0; p < 2; p++) {
                    mma16816(acc[mt][2 * p],     ah[mt], &bh4[p][0]);
                    mma16816(acc[mt][2 * p + 1], ah[mt], &bh4[p][2]);
                }

            uint32_t al[2][4];
#pragma unroll
            for (int mt = 0; mt < 2; mt++)
                ldsm_x4(al[mt], base + 8192 + SWZ64((uint32_t)((aRowL + mt * 16) * 64 + aColL + ks * 32)));
#pragma unroll
            for (int mt = 0; mt < 2; mt++)
#pragma unroll
                for (int p = 0; p < 2; p++) {
                    mma16816(acc[mt][2 * p],     al[mt], &bh4[p][0]);
                    mma16816(acc[mt][2 * p + 1], al[mt], &bh4[p][2]);
                }

            uint32_t bl4[2][4];
#pragma unroll
            for (int p = 0; p < 2; p++)
                ldsm_x4(bl4[p], base + 20480 + SWZ64((uint32_t)((bRowX4 + p * 16) * 64 + bColX4 + ks * 32)));
#pragma unroll
            for (int mt = 0; mt < 2; mt++)
#pragma unroll
                for (int p = 0; p < 2; p++) {
                    mma16816(acc[mt][2 * p],     ah[mt], &bl4[p][0]);
                    mma16816(acc[mt][2 * p + 1], ah[mt], &bl4[p][2]);
                }
        }
        __syncthreads();
    }

#pragma unroll
    for (int mt = 0; mt < 2; mt++) {
        int mb = m0 + warp_m * 32 + mt * 16 + (lane >> 2);
#pragma unroll
        for (int h2 = 0; h2 < 2; h2++) {
            int m = mb + h2 * 8;
            float s = 1.f, bb = 0.f;
            if (scale) { s = scale[m]; bb = bias[m]; }
            long rowOff = (long)b * outStride + (long)m * HW;
            long resOff = Res ? ((long)b * resStride + (long)m * HW) : 0;
#pragma unroll
            for (int nt = 0; nt < 4; nt++) {
                int n = n0 + warp_n * 32 + nt * 8 + (lane & 3) * 2;
                float v0 = acc[mt][nt][h2 * 2 + 0] * s + bb;
                float v1 = acc[mt][nt][h2 * 2 + 1] * s + bb;
                if (doSilu) { v0 = silu_f(v0); v1 = silu_f(v1); }
                if (Res) {
                    float2 r2 = *(const float2*)&Res[resOff + n];
                    v0 += r2.x; v1 += r2.y;
                }
                *(float2*)&Out[rowOff + n] = make_float2(v0, v1);
            }
        }
    }
}

// ---------------- attention converter: qkv fp32 -> qT/kT(+relpos)/v bf16 hi/lo ----------------
__global__ void convAttn_kernel(const float* __restrict__ QKV,
                                const float* __restrict__ RW, const float* __restrict__ RH,
                                __nv_bfloat16* __restrict__ Hi, __nv_bfloat16* __restrict__ Lo)
{
    __shared__ float tq[32][33], tk[32][33];
    int it = blockIdx.x, dt = blockIdx.y, bh = blockIdx.z;
    int b = bh >> 2, hh = bh & 3;
    int tx = threadIdx.x, ty = threadIdx.y;
    const float* base = QKV + (long)b * 768 * HW;
#pragma unroll
    for (int l = 0; l < 4; l++) {
        int d = dt * 32 + ty + l * 8;
        int ch = hh * 64 + d;
        float qv = base[(long)ch * HW + it * 32 + tx] * 0.125f;
        float kv = base[(long)(256 + ch) * HW + it * 32 + tx] + RW[ch * 32 + tx] + RH[ch * 32 + it];
        float vv = base[(long)(512 + ch) * HW + it * 32 + tx];
        tq[ty + l * 8][tx] = qv;
        tk[ty + l * 8][tx] = kv;
        long vo = V_OFF + ((long)bh * 64 + d) * 1024 + it * 32 + tx;
        __nv_bfloat16 vh = __float2bfloat16(vv);
        Hi[vo] = vh;
        Lo[vo] = __float2bfloat16(vv - __bfloat162float(vh));
    }
    __syncthreads();
#pragma unroll
    for (int l = 0; l < 4; l++) {
        int i = it * 32 + ty + l * 8;
        int d = dt * 32 + tx;
        float qv = tq[tx][ty + l * 8];
        float kv = tk[tx][ty + l * 8];
        long qo = ((long)bh * 1024 + i) * 64 + d;
        __nv_bfloat16 qh = __float2bfloat16(qv);
        Hi[QT_OFF + qo] = qh;
        Lo[QT_OFF + qo] = __float2bfloat16(qv - __bfloat162float(qh));
        __nv_bfloat16 kh = __float2bfloat16(kv);
        Hi[KT_OFF + qo] = kh;
        Lo[KT_OFF + qo] = __float2bfloat16(kv - __bfloat162float(kh));
    }
}

// ---------------- MMA flash attention ----------------
#define AT_SMEM 163840

__device__ __forceinline__ void kv_load(uint32_t smb, int tid,
    const __nv_bfloat16* __restrict__ kTh, const __nv_bfloat16* __restrict__ kTl,
    const __nv_bfloat16* __restrict__ vH, const __nv_bfloat16* __restrict__ vL,
    int bh, int t, uint32_t stOff)
{
    uint32_t kb = smb + stOff;
    const uint4* kh4 = (const uint4*)(kTh + ((long)bh * 1024 + t * 128) * 64);
    const uint4* kl4 = (const uint4*)(kTl + ((long)bh * 1024 + t * 128) * 64);
    int r = tid >> 1, j0 = (tid & 1) * 4;
#pragma unroll
    for (int j = 0; j < 4; j++) {
        uint32_t off = SWZ128((uint32_t)(r * 128 + (j0 + j) * 16));
        cpa16(kb + off, kh4 + (long)r * 8 + j0 + j);
        cpa16(kb + 16384 + off, kl4 + (long)r * 8 + j0 + j);
    }
    const uint4* vh4 = (const uint4*)(vH + (long)bh * 65536 + t * 128);
    const uint4* vl4 = (const uint4*)(vL + (long)bh * 65536 + t * 128);
    int d = tid >> 2, jc0 = (tid & 3) * 4;
#pragma unroll
    for (int j = 0; j < 4; j++) {
        int jc = jc0 + j;
        uint32_t off = (uint32_t)((jc >> 3) * 8192) + SWZ128((uint32_t)(d * 128 + (jc & 7) * 16));
        cpa16(kb + 32768 + off, vh4 + (long)d * 128 + jc);
        cpa16(kb + 49152 + off, vl4 + (long)d * 128 + jc);
    }
}

extern __shared__ char at_smem[];

__global__ void __launch_bounds__(256) attn_mma_kernel(
    const __nv_bfloat16* __restrict__ Hi, const __nv_bfloat16* __restrict__ Lo,
    float* __restrict__ Outp)
{
    int qt = blockIdx.x, h = blockIdx.y, b = blockIdx.z;
    int bh = b * 4 + h;
    int tid = threadIdx.x, wid = tid >> 5, lane = tid & 31, li = lane & 15;
    uint32_t smb = smem_u32(at_smem);

    const __nv_bfloat16* qTh = Hi + QT_OFF;
    const __nv_bfloat16* qTl = Lo + QT_OFF;
    const __nv_bfloat16* kTh = Hi + KT_OFF;
    const __nv_bfloat16* kTl = Lo + KT_OFF;
    const __nv_bfloat16* vH  = Hi + V_OFF;
    const __nv_bfloat16* vL  = Lo + V_OFF;

    {
        const uint4* qh4 = (const uint4*)(qTh + ((long)bh * 1024 + qt * 128) * 64);
        const uint4* ql4 = (const uint4*)(qTl + ((long)bh * 1024 + qt * 128) * 64);
        int r = tid >> 1, j0 = (tid & 1) * 4;
        uint32_t qb = smb + 131072;
#pragma unroll
        for (int j = 0; j < 4; j++) {
            uint32_t off = SWZ128((uint32_t)(r * 128 + (j0 + j) * 16));
            cpa16(qb + off, qh4 + (long)r * 8 + j0 + j);
            cpa16(qb + 16384 + off, ql4 + (long)r * 8 + j0 + j);
        }
    }
    CPA_COMMIT();
    kv_load(smb, tid, kTh, kTl, vH, vL, bh, 0, 0);
    CPA_COMMIT();
    CPA_WAIT1();
    __syncthreads();

    uint32_t qfh[4][4], qfl[4][4];
    {
        int aRow = wid * 16 + (lane & 7) + (lane & 8);
        int aCol = ((lane >> 4) & 1) * 16;
#pragma unroll
        for (int ks = 0; ks < 4; ks++) {
            uint32_t off = SWZ128((uint32_t)(aRow * 128 + aCol + ks * 32));
            ldsm_x4(qfh[ks], smb + 131072 + off);
            ldsm_x4(qfl[ks], smb + 131072 + 16384 + off);
        }
    }

    float oacc[8][4];
#pragma unroll
    for (int i = 0; i < 8; i++)
#pragma unroll
        for (int j = 0; j < 4; j++) oacc[i][j] = 0.f;
    float m0 = -1e30f, m1 = -1e30f, l0 = 0.f, l1 = 0.f;

    int sRowX4 = (lane >> 4) * 8 + (lane & 7);
    uint32_t sColX4 = (uint32_t)(((lane >> 3) & 1) * 16);

    for (int t = 0; t < 8; t++) {
        int s = t & 1;
        if (t < 7) {
            kv_load(smb, tid, kTh, kTl, vH, vL, bh, t + 1, (uint32_t)((s ^ 1) * 65536));
            CPA_COMMIT();
            CPA_WAIT1();
        } else {
            CPA_WAIT0();
        }
        __syncthreads();

        uint32_t kb = smb + s * 65536;
        float sacc[16][4];
#pragma unroll
        for (int i = 0; i < 16; i++)
#pragma unroll
            for (int j = 0; j < 4; j++) sacc[i][j] = 0.f;

#pragma unroll
        for (int p = 0; p < 8; p++) {
            int rowB = p * 16 + sRowX4;
#pragma unroll
            for (int ks = 0; ks < 4; ks++) {
                uint32_t off = SWZ128((uint32_t)(rowB * 128 + sColX4 + ks * 32));
                uint32_t kh4[4], kl4[4];
                ldsm_x4(kh4, kb + off);
                ldsm_x4(kl4, kb + 16384 + off);
                mma16816(sacc[2 * p],     qfh[ks], &kh4[0]);
                mma16816(sacc[2 * p + 1], qfh[ks], &kh4[2]);
                mma16816(sacc[2 * p],     qfl[ks], &kh4[0]);
                mma16816(sacc[2 * p + 1], qfl[ks], &kh4[2]);
                mma16816(sacc[2 * p],     qfh[ks], &kl4[0]);
                mma16816(sacc[2 * p + 1], qfh[ks], &kl4[2]);
            }
        }

        float mx0 = m0, mx1 = m1;
#pragma unroll
        for (int nt = 0; nt < 16; nt++) {
            mx0 = fmaxf(mx0, fmaxf(sacc[nt][0], sacc[nt][1]));
            mx1 = fmaxf(mx1, fmaxf(sacc[nt][2], sacc[nt][3]));
        }
        mx0 = fmaxf(mx0, __shfl_xor_sync(0xffffffffu, mx0, 1));
        mx0 = fmaxf(mx0, __shfl_xor_sync(0xffffffffu, mx0, 2));
        mx1 = fmaxf(mx1, __shfl_xor_sync(0xffffffffu, mx1, 1));
        mx1 = fmaxf(mx1, __shfl_xor_sync(0xffffffffu, mx1, 2));
        float a0 = __expf(m0 - mx0), a1 = __expf(m1 - mx1);
        m0 = mx0; m1 = mx1;

        float ls0 = 0.f, ls1 = 0.f;
        uint32_t pah[8][4], pal[8][4];
#pragma unroll
        for (int kj = 0; kj < 8; kj++) {
            float p00 = __expf(sacc[2 * kj][0] - m0);
            float p01 = __expf(sacc[2 * kj][1] - m0);
            float p02 = __expf(sacc[2 * kj][2] - m1);
            float p03 = __expf(sacc[2 * kj][3] - m1);
            float p10 = __expf(sacc[2 * kj + 1][0] - m0);
            float p11 = __expf(sacc[2 * kj + 1][1] - m0);
            float p12 = __expf(sacc[2 * kj + 1][2] - m1);
            float p13 = __expf(sacc[2 * kj + 1][3] - m1);
            ls0 += p00 + p01 + p10 + p11;
            ls1 += p02 + p03 + p12 + p13;
            pah[kj][0] = packbf(p00, p01);
            pah[kj][1] = packbf(p02, p03);
            pah[kj][2] = packbf(p10, p11);
            pah[kj][3] = packbf(p12, p13);
            float q00 = p00 - __bfloat162float(__float2bfloat16(p00));
            float q01 = p01 - __bfloat162float(__float2bfloat16(p01));
            float q02 = p02 - __bfloat162float(__float2bfloat16(p02));
            float q03 = p03 - __bfloat162float(__float2bfloat16(p03));
            float q10 = p10 - __bfloat162float(__float2bfloat16(p10));
            float q11 = p11 - __bfloat162float(__float2bfloat16(p11));
            float q12 = p12 - __bfloat162float(__float2bfloat16(p12));
            float q13 = p13 - __bfloat162float(__float2bfloat16(p13));
            pal[kj][0] = packbf(q00, q01);
            pal[kj][1] = packbf(q02, q03);
            pal[kj][2] = packbf(q10, q11);
            pal[kj][3] = packbf(q12, q13);
        }
        ls0 += __shfl_xor_sync(0xffffffffu, ls0, 1);
        ls0 += __shfl_xor_sync(0xffffffffu, ls0, 2);
        ls1 += __shfl_xor_sync(0xffffffffu, ls1, 1);
        ls1 += __shfl_xor_sync(0xffffffffu, ls1, 2);
        l0 = l0 * a0 + ls0;
        l1 = l1 * a1 + ls1;
#pragma unroll
        for (int dt = 0; dt < 8; dt++) {
            oacc[dt][0] *= a0; oacc[dt][1] *= a0;
            oacc[dt][2] *= a1; oacc[dt][3] *= a1;
        }

#pragma unroll
        for (int dt = 0; dt < 8; dt++) {
            int rowV = dt * 8 + (li & 7);
#pragma unroll
            for (int kj = 0; kj < 8; kj++) {
                uint32_t off = (uint32_t)((kj >> 2) * 8192) +
                               SWZ128((uint32_t)(rowV * 128 + (li >> 3) * 16 + (kj & 3) * 32));
                uint32_t vh2[2], vl2[2];
                ldsm_x2(vh2, kb + 32768 + off);
                ldsm_x2(vl2, kb + 49152 + off);
                mma16816(oacc[dt], pah[kj], vh2);
                mma16816(oacc[dt], pal[kj], vh2);
                mma16816(oacc[dt], pah[kj], vl2);
            }
        }
        __syncthreads();
    }

    float i0 = 1.f / l0, i1 = 1.f / l1;
    float* stg = (float*)at_smem;   // [128][66]
    int r0 = wid * 16 + (lane >> 2);
#pragma unroll
    for (int dt = 0; dt < 8; dt++) {
        int d = dt * 8 + (lane & 3) * 2;
        stg[r0 * 66 + d]           = oacc[dt][0] * i0;
        stg[r0 * 66 + d + 1]       = oacc[dt][1] * i0;
        stg[(r0 + 8) * 66 + d]     = oacc[dt][2] * i1;
        stg[(r0 + 8) * 66 + d + 1] = oacc[dt][3] * i1;
    }
    __syncthreads();
    for (int e = tid; e < 8192; e += 256) {
        int d = e >> 7, i = e & 127;
        Outp[((long)b * 256 + h * 64 + d) * HW + qt * 128 + i] = stg[i * 66 + d];
    }
}

// ---------------- launch ----------------
extern "C" void kernel_launch(void* const* d_in, const int* in_sizes, int n_in,
                              void* d_out, int out_size)
{
    const float* x      = (const float*)d_in[0];
    const float* cv1_w  = (const float*)d_in[1];
    const float* cv1_bn = (const float*)d_in[2];
    const float* cv2_w  = (const float*)d_in[3];
    const float* cv2_bn = (const float*)d_in[4];
    const float* mcv1w  = (const float*)d_in[5];
    const float* mcv1bn = (const float*)d_in[6];
    const float* mqkvw  = (const float*)d_in[7];
    const float* mrw    = (const float*)d_in[8];
    const float* mrh    = (const float*)d_in[9];
    const float* mcv2w  = (const float*)d_in[10];
    const float* mcv2bn = (const float*)d_in[11];
    float* out = (float*)d_out;

    float *cat, *z, *qkv, *atto, *scl, *bia;
    __nv_bfloat16 *whi, *wlo, *bhi, *blo;
    cudaGetSymbolAddress((void**)&cat,  g_cat);
    cudaGetSymbolAddress((void**)&z,    g_z);
    cudaGetSymbolAddress((void**)&qkv,  g_qkv);
    cudaGetSymbolAddress((void**)&atto, g_atto);
    cudaGetSymbolAddress((void**)&scl,  g_scale);
    cudaGetSymbolAddress((void**)&bia,  g_bias);
    cudaGetSymbolAddress((void**)&whi,  g_Whi);
    cudaGetSymbolAddress((void**)&wlo,  g_Wlo);
    cudaGetSymbolAddress((void**)&bhi,  g_Bhi);
    cudaGetSymbolAddress((void**)&blo,  g_Blo);

    cudaFuncSetAttribute(mgemm_kernel, cudaFuncAttributeMaxDynamicSharedMemorySize, MG_SMEM);
    cudaFuncSetAttribute(mgemm64_kernel, cudaFuncAttributeMaxDynamicSharedMemorySize, MG64_SMEM);
    cudaFuncSetAttribute(attn_mma_kernel, cudaFuncAttributeMaxDynamicSharedMemorySize, AT_SMEM);

    fold_bn_kernel<<<8, 256>>>(cv1_bn, cv2_bn, mcv1bn, mcv2bn);

    // ---- cv1: 512 -> 512, BN+SiLU, into cat[0:512) ----
    convW_kernel<<<(512 * 512 + 255) / 256, 256>>>(cv1_w, 512, 512, 0, whi, wlo);
    convB_kernel<<<dim3(32, 16, 8), dim3(32, 8)>>>(x, (long)512 * HW, 512, bhi, blo);
    mgemm_kernel<<<dim3(8, 4, 8), 256, MG_SMEM>>>(
        bhi, blo, whi, wlo, 512, cat, (long)1024 * HW,
        scl + 0, bia + 0, nullptr, 0, 1);

    for (int i = 0; i < 2; i++) {
        long yin  = (long)(i == 0 ? 256 : 512) * HW;
        long yout = (long)(512 + i * 256) * HW;

        // z = cbs(yi, 3x3) as implicit GEMM, K=2304 — N-tile 64 => 256 CTAs
        convW_kernel<<<(256 * 2304 + 255) / 256, 256>>>(
            mcv1w + (long)i * 256 * 2304, 256, 2304, 1, whi, wlo);
        im2colB_kernel<<<dim3(32, 8, 72), dim3(32, 8)>>>(cat + yin, (long)1024 * HW, bhi, blo);
        mgemm64_kernel<<<dim3(16, 2, 8), 256, MG64_SMEM>>>(
            bhi, blo, whi, wlo, 2304, z, (long)256 * HW,
            scl + 1024 + i * 256, bia + 1024 + i * 256, nullptr, 0, 1);

        // qkv = conv1x1(z), 256 -> 768
        convW_kernel<<<(768 * 256 + 255) / 256, 256>>>(
            mqkvw + (long)i * 768 * 256, 768, 256, 0, whi, wlo);
        convB_kernel<<<dim3(32, 8, 8), dim3(32, 8)>>>(z, (long)256 * HW, 256, bhi, blo);
        mgemm_kernel<<<dim3(8, 6, 8), 256, MG_SMEM>>>(
            bhi, blo, whi, wlo, 256, qkv, (long)768 * HW,
            nullptr, nullptr, nullptr, 0, 0);

        // attention operand conversion + MMA flash attention
        convAttn_kernel<<<dim3(32, 2, 32), dim3(32, 8)>>>(
            qkv, mrw + (long)i * 8192, mrh + (long)i * 8192, bhi, blo);
        attn_mma_kernel<<<dim3(8, 4, 8), 256, AT_SMEM>>>(bhi, blo, atto);

        // y_{i+2} = yi + silu(bn(conv1x1(atto))) — N-tile 64 => 256 CTAs
        convW_kernel<<<(256 * 256 + 255) / 256, 256>>>(
            mcv2w + (long)i * 256 * 256, 256, 256, 0, whi, wlo);
        convB_kernel<<<dim3(32, 8, 8), dim3(32, 8)>>>(atto, (long)256 * HW, 256, bhi, blo);
        mgemm64_kernel<<<dim3(16, 2, 8), 256, MG64_SMEM>>>(
            bhi, blo, whi, wlo, 256, cat + yout, (long)1024 * HW,
            scl + 1536 + i * 256, bia + 1536 + i * 256, cat + yin, (long)1024 * HW, 1);
    }

    // ---- final: 1024 -> 512, BN+SiLU ----
    convW_kernel<<<(512 * 1024 + 255) / 256, 256>>>(cv2_w, 512, 1024, 0, whi, wlo);
    convB_kernel<<<dim3(32, 32, 8), dim3(32, 8)>>>(cat, (long)1024 * HW, 1024, bhi, blo);
    mgemm_kernel<<<dim3(8, 4, 8), 256, MG_SMEM>>>(
        bhi, blo, whi, wlo, 1024, out, (long)512 * HW,
        scl + 512, bia + 512, nullptr, 0, 1);
}

// round 8
// speedup vs baseline: 1.1800x; 1.0439x over previous
#include <cuda_runtime.h>
#include <cuda_bf16.h>
#include <cstdint>

#define HW 1024

// ---------------- scratch (__device__ globals: alloc-guard-safe) ----------------
__device__ float g_cat [8u * 1024u * HW];   // 32 MB
__device__ float g_z   [8u * 256u  * HW];   //  8 MB
__device__ float g_qkv [8u * 768u  * HW];   // 24 MB
__device__ float g_atto[8u * 256u  * HW];   //  8 MB
__device__ float g_scale[2048];
__device__ float g_bias [2048];
__device__ __nv_bfloat16 g_Whi[589824];
__device__ __nv_bfloat16 g_Wlo[589824];
__device__ __nv_bfloat16 g_Bhi[18874368];
__device__ __nv_bfloat16 g_Blo[18874368];

// offsets (elements) inside g_Bhi/g_Blo for attention operands
#define QT_OFF 0
#define KT_OFF 2097152
#define V_OFF  4194304

__device__ __forceinline__ float silu_f(float v) { return v / (1.f + __expf(-v)); }

__device__ __forceinline__ uint32_t smem_u32(const void* p) {
    uint32_t a;
    asm("{ .reg .u64 t; cvta.to.shared.u64 t, %1; cvt.u32.u64 %0, t; }" : "=r"(a) : "l"(p));
    return a;
}
#define SWZ128(o) ((o) ^ (((o) >> 3) & 0x70))
#define SWZ64(o)  ((o) ^ (((o) >> 3) & 0x30))

__device__ __forceinline__ void ldsm_x4(uint32_t* r, uint32_t a) {
    asm volatile("ldmatrix.sync.aligned.m8n8.x4.shared.b16 {%0,%1,%2,%3}, [%4];"
        : "=r"(r[0]), "=r"(r[1]), "=r"(r[2]), "=r"(r[3]) : "r"(a));
}
__device__ __forceinline__ void ldsm_x2(uint32_t* r, uint32_t a) {
    asm volatile("ldmatrix.sync.aligned.m8n8.x2.shared.b16 {%0,%1}, [%2];"
        : "=r"(r[0]), "=r"(r[1]) : "r"(a));
}
__device__ __forceinline__ void mma16816(float* d, const uint32_t* a, const uint32_t* b) {
    asm volatile("mma.sync.aligned.m16n8k16.row.col.f32.bf16.bf16.f32 "
        "{%0,%1,%2,%3}, {%4,%5,%6,%7}, {%8,%9}, {%0,%1,%2,%3};"
        : "+f"(d[0]), "+f"(d[1]), "+f"(d[2]), "+f"(d[3])
        : "r"(a[0]), "r"(a[1]), "r"(a[2]), "r"(a[3]), "r"(b[0]), "r"(b[1]));
}
__device__ __forceinline__ void cpa16(uint32_t d, const void* s) {
    asm volatile("cp.async.cg.shared.global [%0], [%1], 16;" :: "r"(d), "l"(s));
}
__device__ __forceinline__ void cpa16z(uint32_t d, const void* s, int sz) {
    asm volatile("cp.async.cg.shared.global [%0], [%1], 16, %2;" :: "r"(d), "l"(s), "r"(sz));
}
#define CPA_COMMIT() asm volatile("cp.async.commit_group;" ::: "memory")
#define CPA_WAIT1()  asm volatile("cp.async.wait_group 1;" ::: "memory")
#define CPA_WAIT0()  asm volatile("cp.async.wait_group 0;" ::: "memory")

__device__ __forceinline__ uint32_t packbf(float lo, float hi) {
    uint32_t r;
    asm("cvt.rn.bf16x2.f32 %0, %1, %2;" : "=r"(r) : "f"(hi), "f"(lo));
    return r;
}

// ---------------- BN fold ----------------
__global__ void fold_bn_kernel(const float* __restrict__ cv1, const float* __restrict__ cv2,
                               const float* __restrict__ mcv1, const float* __restrict__ mcv2)
{
    int c = blockIdx.x * 256 + threadIdx.x;
    if (c >= 2048) return;
    const float* p; int C, lc;
    if (c < 512)        { p = cv1;  C = 512; lc = c; }
    else if (c < 1024)  { p = cv2;  C = 512; lc = c - 512; }
    else if (c < 1536)  { int i = (c - 1024) >> 8; p = mcv1 + i * 1024; C = 256; lc = (c - 1024) & 255; }
    else                { int i = (c - 1536) >> 8; p = mcv2 + i * 1024; C = 256; lc = (c - 1536) & 255; }
    float g = p[lc], b = p[C + lc], m = p[2 * C + lc], v = p[3 * C + lc];
    float s = g / sqrtf(v + 1e-3f);
    g_scale[c] = s;
    g_bias[c]  = b - m * s;
}

// ---------------- weight converter ----------------
__global__ void convW_kernel(const float* __restrict__ W, int M, int K, int isConv,
                             __nv_bfloat16* __restrict__ Whi, __nv_bfloat16* __restrict__ Wlo)
{
    long e = (long)blockIdx.x * 256 + threadIdx.x;
    if (e >= (long)M * K) return;
    long m = e / K, k = e % K;
    float v;
    if (isConv) { int off = (int)(k >> 8), ci = (int)(k & 255); v = W[m * 2304 + ci * 9 + off]; }
    else v = W[e];
    __nv_bfloat16 h = __float2bfloat16(v);
    Whi[e] = h;
    Wlo[e] = __float2bfloat16(v - __bfloat162float(h));
}

// ---------------- activation converter: [b][K][HW] -> [b][n][K] hi/lo ----------------
__global__ void convB_kernel(const float* __restrict__ In, long inStride, int K,
                             __nv_bfloat16* __restrict__ Bhi, __nv_bfloat16* __restrict__ Blo)
{
    __shared__ float t[32][33];
    int n0 = blockIdx.x * 32, k0 = blockIdx.y * 32, b = blockIdx.z;
    int tx = threadIdx.x, ty = threadIdx.y;
    const float* in = In + (long)b * inStride;
#pragma unroll
    for (int yy = 0; yy < 32; yy += 8)
        t[yy + ty][tx] = in[(long)(k0 + yy + ty) * HW + n0 + tx];
    __syncthreads();
#pragma unroll
    for (int yy = 0; yy < 32; yy += 8) {
        int n = n0 + yy + ty, k = k0 + tx;
        float v = t[tx][yy + ty];
        long o = ((long)b * 1024 + n) * K + k;
        __nv_bfloat16 h = __float2bfloat16(v);
        Bhi[o] = h;
        Blo[o] = __float2bfloat16(v - __bfloat162float(h));
    }
}

// ---------------- warp-MMA GEMM (N-tile 128): cp.async 2-stage, K-chunk 32, SW64 ----------------
#define MG_STAGE 32768
#define MG_SMEM  65536

__device__ __forceinline__ void mg_load(uint32_t smb, int tid,
    const uint4* __restrict__ wHi, const uint4* __restrict__ wLo,
    const uint4* __restrict__ bHi, const uint4* __restrict__ bLo,
    int m0, int n0, int K16, int c, uint32_t stOff)
{
    uint32_t sb = smb + stOff;
    int r = tid >> 1;
    int j = (tid & 1) * 2;
    uint32_t o0 = SWZ64((uint32_t)(r * 64 + j * 16));
    uint32_t o1 = SWZ64((uint32_t)(r * 64 + (j + 1) * 16));
    const uint4* a;
    a = wHi + (long)(m0 + r) * K16 + c * 4 + j;
    cpa16(sb + o0, a); cpa16(sb + o1, a + 1);
    a = wLo + (long)(m0 + r) * K16 + c * 4 + j;
    cpa16(sb + 8192 + o0, a); cpa16(sb + 8192 + o1, a + 1);
    a = bHi + (long)(n0 + r) * K16 + c * 4 + j;
    cpa16(sb + 16384 + o0, a); cpa16(sb + 16384 + o1, a + 1);
    a = bLo + (long)(n0 + r) * K16 + c * 4 + j;
    cpa16(sb + 24576 + o0, a); cpa16(sb + 24576 + o1, a + 1);
}

extern __shared__ char mg_smem[];

__global__ void __launch_bounds__(256, 2) mgemm_kernel(
    const __nv_bfloat16* __restrict__ Bhi, const __nv_bfloat16* __restrict__ Blo,
    const __nv_bfloat16* __restrict__ Whi, const __nv_bfloat16* __restrict__ Wlo,
    int K,
    float* __restrict__ Out, long outStride,
    const float* __restrict__ scale, const float* __restrict__ bias,
    const float* __restrict__ Res, long resStride,
    int doSilu)
{
    int b = blockIdx.z, m0 = blockIdx.y * 128, n0 = blockIdx.x * 128;
    int tid = threadIdx.x, wid = tid >> 5, lane = tid & 31;
    int warp_m = wid & 1, warp_n = wid >> 1;
    uint32_t smb = smem_u32(mg_smem);

    int K16 = K >> 3;
    const uint4* wHi = (const uint4*)Whi;
    const uint4* wLo = (const uint4*)Wlo;
    const uint4* bHi = (const uint4*)(Bhi + (long)b * 1024 * K);
    const uint4* bLo = (const uint4*)(Blo + (long)b * 1024 * K);

    float acc[4][4][4];
#pragma unroll
    for (int i = 0; i < 4; i++)
#pragma unroll
        for (int j = 0; j < 4; j++)
#pragma unroll
            for (int r = 0; r < 4; r++) acc[i][j][r] = 0.f;

    int nChunks = K >> 5;
    mg_load(smb, tid, wHi, wLo, bHi, bLo, m0, n0, K16, 0, 0);
    CPA_COMMIT();

    int aRowL = warp_m * 64 + (lane & 7) + (lane & 8);
    int aColL = ((lane >> 4) & 1) * 16;
    int bRowX4 = warp_n * 32 + (lane >> 4) * 8 + (lane & 7);  // + p*16
    uint32_t bColX4 = (uint32_t)(((lane >> 3) & 1) * 16);

    for (int c = 0; c < nChunks; c++) {
        int s = c & 1;
        if (c + 1 < nChunks) {
            mg_load(smb, tid, wHi, wLo, bHi, bLo, m0, n0, K16, c + 1, (uint32_t)((s ^ 1) * MG_STAGE));
            CPA_COMMIT();
            CPA_WAIT1();
        } else {
            CPA_WAIT0();
        }
        __syncthreads();

        uint32_t base = smb + s * MG_STAGE;
#pragma unroll
        for (int ks = 0; ks < 2; ks++) {
            uint32_t ah[4][4], bh4[2][4];
#pragma unroll
            for (int mt = 0; mt < 4; mt++)
                ldsm_x4(ah[mt], base + SWZ64((uint32_t)((aRowL + mt * 16) * 64 + aColL + ks * 32)));
#pragma unroll
            for (int p = 0; p < 2; p++)
                ldsm_x4(bh4[p], base + 16384 + SWZ64((uint32_t)((bRowX4 + p * 16) * 64 + bColX4 + ks * 32)));
#pragma unroll
            for (int mt = 0; mt < 4; mt++)
#pragma unroll
                for (int p = 0; p < 2; p++) {
                    mma16816(acc[mt][2 * p],     ah[mt], &bh4[p][0]);
                    mma16816(acc[mt][2 * p + 1], ah[mt], &bh4[p][2]);
                }

            uint32_t al[4][4];
#pragma unroll
            for (int mt = 0; mt < 4; mt++)
                ldsm_x4(al[mt], base + 8192 + SWZ64((uint32_t)((aRowL + mt * 16) * 64 + aColL + ks * 32)));
#pragma unroll
            for (int mt = 0; mt < 4; mt++)
#pragma unroll
                for (int p = 0; p < 2; p++) {
                    mma16816(acc[mt][2 * p],     al[mt], &bh4[p][0]);
                    mma16816(acc[mt][2 * p + 1], al[mt], &bh4[p][2]);
                }

            uint32_t bl4[2][4];
#pragma unroll
            for (int p = 0; p < 2; p++)
                ldsm_x4(bl4[p], base + 24576 + SWZ64((uint32_t)((bRowX4 + p * 16) * 64 + bColX4 + ks * 32)));
#pragma unroll
            for (int mt = 0; mt < 4; mt++)
#pragma unroll
                for (int p = 0; p < 2; p++) {
                    mma16816(acc[mt][2 * p],     ah[mt], &bl4[p][0]);
                    mma16816(acc[mt][2 * p + 1], ah[mt], &bl4[p][2]);
                }
        }
        __syncthreads();
    }

#pragma unroll
    for (int mt = 0; mt < 4; mt++) {
        int mb = m0 + warp_m * 64 + mt * 16 + (lane >> 2);
#pragma unroll
        for (int h2 = 0; h2 < 2; h2++) {
            int m = mb + h2 * 8;
            float s = 1.f, bb = 0.f;
            if (scale) { s = scale[m]; bb = bias[m]; }
            long rowOff = (long)b * outStride + (long)m * HW;
            long resOff = Res ? ((long)b * resStride + (long)m * HW) : 0;
#pragma unroll
            for (int nt = 0; nt < 4; nt++) {
                int n = n0 + warp_n * 32 + nt * 8 + (lane & 3) * 2;
                float v0 = acc[mt][nt][h2 * 2 + 0] * s + bb;
                float v1 = acc[mt][nt][h2 * 2 + 1] * s + bb;
                if (doSilu) { v0 = silu_f(v0); v1 = silu_f(v1); }
                if (Res) {
                    float2 r2 = *(const float2*)&Res[resOff + n];
                    v0 += r2.x; v1 += r2.y;
                }
                *(float2*)&Out[rowOff + n] = make_float2(v0, v1);
            }
        }
    }
}

// ---------------- warp-MMA GEMM (N-tile 64): generic B (cv2m) ----------------
#define MG64_STAGE 24576
#define MG64_SMEM  49152

__device__ __forceinline__ void mg64_load(uint32_t smb, int tid,
    const uint4* __restrict__ wHi, const uint4* __restrict__ wLo,
    const uint4* __restrict__ bHi, const uint4* __restrict__ bLo,
    int m0, int n0, int K16, int c, uint32_t stOff)
{
    uint32_t sb = smb + stOff;
    int r = tid >> 1, j = (tid & 1) * 2;
    uint32_t o0 = SWZ64((uint32_t)(r * 64 + j * 16));
    uint32_t o1 = SWZ64((uint32_t)(r * 64 + (j + 1) * 16));
    const uint4* a;
    a = wHi + (long)(m0 + r) * K16 + c * 4 + j;
    cpa16(sb + o0, a); cpa16(sb + o1, a + 1);
    a = wLo + (long)(m0 + r) * K16 + c * 4 + j;
    cpa16(sb + 8192 + o0, a); cpa16(sb + 8192 + o1, a + 1);
    int rb = tid >> 2, jb = tid & 3;
    uint32_t ob = SWZ64((uint32_t)(rb * 64 + jb * 16));
    a = bHi + (long)(n0 + rb) * K16 + c * 4 + jb;
    cpa16(sb + 16384 + ob, a);
    a = bLo + (long)(n0 + rb) * K16 + c * 4 + jb;
    cpa16(sb + 20480 + ob, a);
}

// implicit 3x3 conv B loader: B is yi in [n][256] layout; chunk c -> tap (c>>3), ci-block (c&7)
__device__ __forceinline__ void mgc_load(uint32_t smb, int tid,
    const uint4* __restrict__ wHi, const uint4* __restrict__ wLo,
    const uint4* __restrict__ bHi, const uint4* __restrict__ bLo,
    int m0, int n0, int K16, int c, uint32_t stOff)
{
    uint32_t sb = smb + stOff;
    int r = tid >> 1, j = (tid & 1) * 2;
    uint32_t o0 = SWZ64((uint32_t)(r * 64 + j * 16));
    uint32_t o1 = SWZ64((uint32_t)(r * 64 + (j + 1) * 16));
    const uint4* a;
    a = wHi + (long)(m0 + r) * K16 + c * 4 + j;
    cpa16(sb + o0, a); cpa16(sb + o1, a + 1);
    a = wLo + (long)(m0 + r) * K16 + c * 4 + j;
    cpa16(sb + 8192 + o0, a); cpa16(sb + 8192 + o1, a + 1);

    int off = c >> 3, cik = c & 7;
    int dy = off / 3 - 1, dx = off % 3 - 1;
    int rb = tid >> 2, jb = tid & 3;
    int pix = n0 + rb;
    int y = (pix >> 5) + dy, x = (pix & 31) + dx;
    bool ok = ((unsigned)y < 32u) && ((unsigned)x < 32u);
    int ps = ok ? (y * 32 + x) : 0;
    int sz = ok ? 16 : 0;
    uint32_t ob = SWZ64((uint32_t)(rb * 64 + jb * 16));
    cpa16z(sb + 16384 + ob, bHi + (long)ps * 32 + cik * 4 + jb, sz);
    cpa16z(sb + 20480 + ob, bLo + (long)ps * 32 + cik * 4 + jb, sz);
}

template <int CONV>
__global__ void __launch_bounds__(256, 2) mgemm64_kernel_t(
    const __nv_bfloat16* __restrict__ Bhi, const __nv_bfloat16* __restrict__ Blo,
    const __nv_bfloat16* __restrict__ Whi, const __nv_bfloat16* __restrict__ Wlo,
    int K, int bK,
    float* __restrict__ Out, long outStride,
    const float* __restrict__ scale, const float* __restrict__ bias,
    const float* __restrict__ Res, long resStride,
    int doSilu)
{
    int b = blockIdx.z, m0 = blockIdx.y * 128, n0 = blockIdx.x * 64;
    int tid = threadIdx.x, wid = tid >> 5, lane = tid & 31;
    int warp_m = wid & 3, warp_n = wid >> 2;
    uint32_t smb = smem_u32(mg_smem);

    int K16 = K >> 3;
    const uint4* wHi = (const uint4*)Whi;
    const uint4* wLo = (const uint4*)Wlo;
    const uint4* bHi = (const uint4*)(Bhi + (long)b * 1024 * bK);
    const uint4* bLo = (const uint4*)(Blo + (long)b * 1024 * bK);

    float acc[2][4][4];
#pragma unroll
    for (int i = 0; i < 2; i++)
#pragma unroll
        for (int j = 0; j < 4; j++)
#pragma unroll
            for (int r = 0; r < 4; r++) acc[i][j][r] = 0.f;

    int nChunks = K >> 5;
    if (CONV) mgc_load(smb, tid, wHi, wLo, bHi, bLo, m0, n0, K16, 0, 0);
    else      mg64_load(smb, tid, wHi, wLo, bHi, bLo, m0, n0, K16, 0, 0);
    CPA_COMMIT();

    int aRowL = warp_m * 32 + (lane & 7) + (lane & 8);
    int aColL = ((lane >> 4) & 1) * 16;
    int bRowX4 = warp_n * 32 + (lane >> 4) * 8 + (lane & 7);  // + p*16
    uint32_t bColX4 = (uint32_t)(((lane >> 3) & 1) * 16);

    for (int c = 0; c < nChunks; c++) {
        int s = c & 1;
        if (c + 1 < nChunks) {
            if (CONV) mgc_load(smb, tid, wHi, wLo, bHi, bLo, m0, n0, K16, c + 1, (uint32_t)((s ^ 1) * MG64_STAGE));
            else      mg64_load(smb, tid, wHi, wLo, bHi, bLo, m0, n0, K16, c + 1, (uint32_t)((s ^ 1) * MG64_STAGE));
            CPA_COMMIT();
            CPA_WAIT1();
        } else {
            CPA_WAIT0();
        }
        __syncthreads();

        uint32_t base = smb + s * MG64_STAGE;
#pragma unroll
        for (int ks = 0; ks < 2; ks++) {
            uint32_t ah[2][4], bh4[2][4];
#pragma unroll
            for (int mt = 0; mt < 2; mt++)
                ldsm_x4(ah[mt], base + SWZ64((uint32_t)((aRowL + mt * 16) * 64 + aColL + ks * 32)));
#pragma unroll
            for (int p = 0; p < 2; p++)
                ldsm_x4(bh4[p], base + 16384 + SWZ64((uint32_t)((bRowX4 + p * 16) * 64 + bColX4 + ks * 32)));
#pragma unroll
            for (int mt = 0; mt < 2; mt++)
#pragma unroll
                for (int p = 0; p < 2; p++) {
                    mma16816(acc[mt][2 * p],     ah[mt], &bh4[p][0]);
                    mma16816(acc[mt][2 * p + 1], ah[mt], &bh4[p][2]);
                }

            uint32_t al[2][4];
#pragma unroll
            for (int mt = 0; mt < 2; mt++)
                ldsm_x4(al[mt], base + 8192 + SWZ64((uint32_t)((aRowL + mt * 16) * 64 + aColL + ks * 32)));
#pragma unroll
            for (int mt = 0; mt < 2; mt++)
#pragma unroll
                for (int p = 0; p < 2; p++) {
                    mma16816(acc[mt][2 * p],     al[mt], &bh4[p][0]);
                    mma16816(acc[mt][2 * p + 1], al[mt], &bh4[p][2]);
                }

            uint32_t bl4[2][4];
#pragma unroll
            for (int p = 0; p < 2; p++)
                ldsm_x4(bl4[p], base + 20480 + SWZ64((uint32_t)((bRowX4 + p * 16) * 64 + bColX4 + ks * 32)));
#pragma unroll
            for (int mt = 0; mt < 2; mt++)
#pragma unroll
                for (int p = 0; p < 2; p++) {
                    mma16816(acc[mt][2 * p],     ah[mt], &bl4[p][0]);
                    mma16816(acc[mt][2 * p + 1], ah[mt], &bl4[p][2]);
                }
        }
        __syncthreads();
    }

#pragma unroll
    for (int mt = 0; mt < 2; mt++) {
        int mb = m0 + warp_m * 32 + mt * 16 + (lane >> 2);
#pragma unroll
        for (int h2 = 0; h2 < 2; h2++) {
            int m = mb + h2 * 8;
            float s = 1.f, bb = 0.f;
            if (scale) { s = scale[m]; bb = bias[m]; }
            long rowOff = (long)b * outStride + (long)m * HW;
            long resOff = Res ? ((long)b * resStride + (long)m * HW) : 0;
#pragma unroll
            for (int nt = 0; nt < 4; nt++) {
                int n = n0 + warp_n * 32 + nt * 8 + (lane & 3) * 2;
                float v0 = acc[mt][nt][h2 * 2 + 0] * s + bb;
                float v1 = acc[mt][nt][h2 * 2 + 1] * s + bb;
                if (doSilu) { v0 = silu_f(v0); v1 = silu_f(v1); }
                if (Res) {
                    float2 r2 = *(const float2*)&Res[resOff + n];
                    v0 += r2.x; v1 += r2.y;
                }
                *(float2*)&Out[rowOff + n] = make_float2(v0, v1);
            }
        }
    }
}

// ---------------- attention converter: qkv fp32 -> qT/kT(+relpos)/v bf16 hi/lo ----------------
__global__ void convAttn_kernel(const float* __restrict__ QKV,
                                const float* __restrict__ RW, const float* __restrict__ RH,
                                __nv_bfloat16* __restrict__ Hi, __nv_bfloat16* __restrict__ Lo)
{
    __shared__ float tq[32][33], tk[32][33];
    int it = blockIdx.x, dt = blockIdx.y, bh = blockIdx.z;
    int b = bh >> 2, hh = bh & 3;
    int tx = threadIdx.x, ty = threadIdx.y;
    const float* base = QKV + (long)b * 768 * HW;
#pragma unroll
    for (int l = 0; l < 4; l++) {
        int d = dt * 32 + ty + l * 8;
        int ch = hh * 64 + d;
        float qv = base[(long)ch * HW + it * 32 + tx] * 0.125f;
        float kv = base[(long)(256 + ch) * HW + it * 32 + tx] + RW[ch * 32 + tx] + RH[ch * 32 + it];
        float vv = base[(long)(512 + ch) * HW + it * 32 + tx];
        tq[ty + l * 8][tx] = qv;
        tk[ty + l * 8][tx] = kv;
        long vo = V_OFF + ((long)bh * 64 + d) * 1024 + it * 32 + tx;
        __nv_bfloat16 vh = __float2bfloat16(vv);
        Hi[vo] = vh;
        Lo[vo] = __float2bfloat16(vv - __bfloat162float(vh));
    }
    __syncthreads();
#pragma unroll
    for (int l = 0; l < 4; l++) {
        int i = it * 32 + ty + l * 8;
        int d = dt * 32 + tx;
        float qv = tq[tx][ty + l * 8];
        float kv = tk[tx][ty + l * 8];
        long qo = ((long)bh * 1024 + i) * 64 + d;
        __nv_bfloat16 qh = __float2bfloat16(qv);
        Hi[QT_OFF + qo] = qh;
        Lo[QT_OFF + qo] = __float2bfloat16(qv - __bfloat162float(qh));
        __nv_bfloat16 kh = __float2bfloat16(kv);
        Hi[KT_OFF + qo] = kh;
        Lo[KT_OFF + qo] = __float2bfloat16(kv - __bfloat162float(kh));
    }
}

// ---------------- MMA flash attention ----------------
#define AT_SMEM 163840

__device__ __forceinline__ void kv_load(uint32_t smb, int tid,
    const __nv_bfloat16* __restrict__ kTh, const __nv_bfloat16* __restrict__ kTl,
    const __nv_bfloat16* __restrict__ vH, const __nv_bfloat16* __restrict__ vL,
    int bh, int t, uint32_t stOff)
{
    uint32_t kb = smb + stOff;
    const uint4* kh4 = (const uint4*)(kTh + ((long)bh * 1024 + t * 128) * 64);
    const uint4* kl4 = (const uint4*)(kTl + ((long)bh * 1024 + t * 128) * 64);
    int r = tid >> 1, j0 = (tid & 1) * 4;
#pragma unroll
    for (int j = 0; j < 4; j++) {
        uint32_t off = SWZ128((uint32_t)(r * 128 + (j0 + j) * 16));
        cpa16(kb + off, kh4 + (long)r * 8 + j0 + j);
        cpa16(kb + 16384 + off, kl4 + (long)r * 8 + j0 + j);
    }
    const uint4* vh4 = (const uint4*)(vH + (long)bh * 65536 + t * 128);
    const uint4* vl4 = (const uint4*)(vL + (long)bh * 65536 + t * 128);
    int d = tid >> 2, jc0 = (tid & 3) * 4;
#pragma unroll
    for (int j = 0; j < 4; j++) {
        int jc = jc0 + j;
        uint32_t off = (uint32_t)((jc >> 3) * 8192) + SWZ128((uint32_t)(d * 128 + (jc & 7) * 16));
        cpa16(kb + 32768 + off, vh4 + (long)d * 128 + jc);
        cpa16(kb + 49152 + off, vl4 + (long)d * 128 + jc);
    }
}

extern __shared__ char at_smem[];

__global__ void __launch_bounds__(256) attn_mma_kernel(
    const __nv_bfloat16* __restrict__ Hi, const __nv_bfloat16* __restrict__ Lo,
    float* __restrict__ Outp)
{
    int qt = blockIdx.x, h = blockIdx.y, b = blockIdx.z;
    int bh = b * 4 + h;
    int tid = threadIdx.x, wid = tid >> 5, lane = tid & 31, li = lane & 15;
    uint32_t smb = smem_u32(at_smem);

    const __nv_bfloat16* qTh = Hi + QT_OFF;
    const __nv_bfloat16* qTl = Lo + QT_OFF;
    const __nv_bfloat16* kTh = Hi + KT_OFF;
    const __nv_bfloat16* kTl = Lo + KT_OFF;
    const __nv_bfloat16* vH  = Hi + V_OFF;
    const __nv_bfloat16* vL  = Lo + V_OFF;

    {
        const uint4* qh4 = (const uint4*)(qTh + ((long)bh * 1024 + qt * 128) * 64);
        const uint4* ql4 = (const uint4*)(qTl + ((long)bh * 1024 + qt * 128) * 64);
        int r = tid >> 1, j0 = (tid & 1) * 4;
        uint32_t qb = smb + 131072;
#pragma unroll
        for (int j = 0; j < 4; j++) {
            uint32_t off = SWZ128((uint32_t)(r * 128 + (j0 + j) * 16));
            cpa16(qb + off, qh4 + (long)r * 8 + j0 + j);
            cpa16(qb + 16384 + off, ql4 + (long)r * 8 + j0 + j);
        }
    }
    CPA_COMMIT();
    kv_load(smb, tid, kTh, kTl, vH, vL, bh, 0, 0);
    CPA_COMMIT();
    CPA_WAIT1();
    __syncthreads();

    uint32_t qfh[4][4], qfl[4][4];
    {
        int aRow = wid * 16 + (lane & 7) + (lane & 8);
        int aCol = ((lane >> 4) & 1) * 16;
#pragma unroll
        for (int ks = 0; ks < 4; ks++) {
            uint32_t off = SWZ128((uint32_t)(aRow * 128 + aCol + ks * 32));
            ldsm_x4(qfh[ks], smb + 131072 + off);
            ldsm_x4(qfl[ks], smb + 131072 + 16384 + off);
        }
    }

    float oacc[8][4];
#pragma unroll
    for (int i = 0; i < 8; i++)
#pragma unroll
        for (int j = 0; j < 4; j++) oacc[i][j] = 0.f;
    float m0 = -1e30f, m1 = -1e30f, l0 = 0.f, l1 = 0.f;

    int sRowX4 = (lane >> 4) * 8 + (lane & 7);
    uint32_t sColX4 = (uint32_t)(((lane >> 3) & 1) * 16);

    for (int t = 0; t < 8; t++) {
        int s = t & 1;
        if (t < 7) {
            kv_load(smb, tid, kTh, kTl, vH, vL, bh, t + 1, (uint32_t)((s ^ 1) * 65536));
            CPA_COMMIT();
            CPA_WAIT1();
        } else {
            CPA_WAIT0();
        }
        __syncthreads();

        uint32_t kb = smb + s * 65536;
        float sacc[16][4];
#pragma unroll
        for (int i = 0; i < 16; i++)
#pragma unroll
            for (int j = 0; j < 4; j++) sacc[i][j] = 0.f;

#pragma unroll
        for (int p = 0; p < 8; p++) {
            int rowB = p * 16 + sRowX4;
#pragma unroll
            for (int ks = 0; ks < 4; ks++) {
                uint32_t off = SWZ128((uint32_t)(rowB * 128 + sColX4 + ks * 32));
                uint32_t kh4[4], kl4[4];
                ldsm_x4(kh4, kb + off);
                ldsm_x4(kl4, kb + 16384 + off);
                mma16816(sacc[2 * p],     qfh[ks], &kh4[0]);
                mma16816(sacc[2 * p + 1], qfh[ks], &kh4[2]);
                mma16816(sacc[2 * p],     qfl[ks], &kh4[0]);
                mma16816(sacc[2 * p + 1], qfl[ks], &kh4[2]);
                mma16816(sacc[2 * p],     qfh[ks], &kl4[0]);
                mma16816(sacc[2 * p + 1], qfh[ks], &kl4[2]);
            }
        }

        float mx0 = m0, mx1 = m1;
#pragma unroll
        for (int nt = 0; nt < 16; nt++) {
            mx0 = fmaxf(mx0, fmaxf(sacc[nt][0], sacc[nt][1]));
            mx1 = fmaxf(mx1, fmaxf(sacc[nt][2], sacc[nt][3]));
        }
        mx0 = fmaxf(mx0, __shfl_xor_sync(0xffffffffu, mx0, 1));
        mx0 = fmaxf(mx0, __shfl_xor_sync(0xffffffffu, mx0, 2));
        mx1 = fmaxf(mx1, __shfl_xor_sync(0xffffffffu, mx1, 1));
        mx1 = fmaxf(mx1, __shfl_xor_sync(0xffffffffu, mx1, 2));
        float a0 = __expf(m0 - mx0), a1 = __expf(m1 - mx1);
        m0 = mx0; m1 = mx1;

        float ls0 = 0.f, ls1 = 0.f;
        uint32_t pah[8][4], pal[8][4];
#pragma unroll
        for (int kj = 0; kj < 8; kj++) {
            float p00 = __expf(sacc[2 * kj][0] - m0);
            float p01 = __expf(sacc[2 * kj][1] - m0);
            float p02 = __expf(sacc[2 * kj][2] - m1);
            float p03 = __expf(sacc[2 * kj][3] - m1);
            float p10 = __expf(sacc[2 * kj + 1][0] - m0);
            float p11 = __expf(sacc[2 * kj + 1][1] - m0);
            float p12 = __expf(sacc[2 * kj + 1][2] - m1);
            float p13 = __expf(sacc[2 * kj + 1][3] - m1);
            ls0 += p00 + p01 + p10 + p11;
            ls1 += p02 + p03 + p12 + p13;
            pah[kj][0] = packbf(p00, p01);
            pah[kj][1] = packbf(p02, p03);
            pah[kj][2] = packbf(p10, p11);
            pah[kj][3] = packbf(p12, p13);
            float q00 = p00 - __bfloat162float(__float2bfloat16(p00));
            float q01 = p01 - __bfloat162float(__float2bfloat16(p01));
            float q02 = p02 - __bfloat162float(__float2bfloat16(p02));
            float q03 = p03 - __bfloat162float(__float2bfloat16(p03));
            float q10 = p10 - __bfloat162float(__float2bfloat16(p10));
            float q11 = p11 - __bfloat162float(__float2bfloat16(p11));
            float q12 = p12 - __bfloat162float(__float2bfloat16(p12));
            float q13 = p13 - __bfloat162float(__float2bfloat16(p13));
            pal[kj][0] = packbf(q00, q01);
            pal[kj][1] = packbf(q02, q03);
            pal[kj][2] = packbf(q10, q11);
            pal[kj][3] = packbf(q12, q13);
        }
        ls0 += __shfl_xor_sync(0xffffffffu, ls0, 1);
        ls0 += __shfl_xor_sync(0xffffffffu, ls0, 2);
        ls1 += __shfl_xor_sync(0xffffffffu, ls1, 1);
        ls1 += __shfl_xor_sync(0xffffffffu, ls1, 2);
        l0 = l0 * a0 + ls0;
        l1 = l1 * a1 + ls1;
#pragma unroll
        for (int dt = 0; dt < 8; dt++) {
            oacc[dt][0] *= a0; oacc[dt][1] *= a0;
            oacc[dt][2] *= a1; oacc[dt][3] *= a1;
        }

#pragma unroll
        for (int dt = 0; dt < 8; dt++) {
            int rowV = dt * 8 + (li & 7);
#pragma unroll
            for (int kj = 0; kj < 8; kj++) {
                uint32_t off = (uint32_t)((kj >> 2) * 8192) +
                               SWZ128((uint32_t)(rowV * 128 + (li >> 3) * 16 + (kj & 3) * 32));
                uint32_t vh2[2], vl2[2];
                ldsm_x2(vh2, kb + 32768 + off);
                ldsm_x2(vl2, kb + 49152 + off);
                mma16816(oacc[dt], pah[kj], vh2);
                mma16816(oacc[dt], pal[kj], vh2);
                mma16816(oacc[dt], pah[kj], vl2);
            }
        }
        __syncthreads();
    }

    float i0 = 1.f / l0, i1 = 1.f / l1;
    float* stg = (float*)at_smem;   // [128][66]
    int r0 = wid * 16 + (lane >> 2);
#pragma unroll
    for (int dt = 0; dt < 8; dt++) {
        int d = dt * 8 + (lane & 3) * 2;
        stg[r0 * 66 + d]           = oacc[dt][0] * i0;
        stg[r0 * 66 + d + 1]       = oacc[dt][1] * i0;
        stg[(r0 + 8) * 66 + d]     = oacc[dt][2] * i1;
        stg[(r0 + 8) * 66 + d + 1] = oacc[dt][3] * i1;
    }
    __syncthreads();
    for (int e = tid; e < 8192; e += 256) {
        int d = e >> 7, i = e & 127;
        Outp[((long)b * 256 + h * 64 + d) * HW + qt * 128 + i] = stg[i * 66 + d];
    }
}

// ---------------- launch ----------------
extern "C" void kernel_launch(void* const* d_in, const int* in_sizes, int n_in,
                              void* d_out, int out_size)
{
    const float* x      = (const float*)d_in[0];
    const float* cv1_w  = (const float*)d_in[1];
    const float* cv1_bn = (const float*)d_in[2];
    const float* cv2_w  = (const float*)d_in[3];
    const float* cv2_bn = (const float*)d_in[4];
    const float* mcv1w  = (const float*)d_in[5];
    const float* mcv1bn = (const float*)d_in[6];
    const float* mqkvw  = (const float*)d_in[7];
    const float* mrw    = (const float*)d_in[8];
    const float* mrh    = (const float*)d_in[9];
    const float* mcv2w  = (const float*)d_in[10];
    const float* mcv2bn = (const float*)d_in[11];
    float* out = (float*)d_out;

    float *cat, *z, *qkv, *atto, *scl, *bia;
    __nv_bfloat16 *whi, *wlo, *bhi, *blo;
    cudaGetSymbolAddress((void**)&cat,  g_cat);
    cudaGetSymbolAddress((void**)&z,    g_z);
    cudaGetSymbolAddress((void**)&qkv,  g_qkv);
    cudaGetSymbolAddress((void**)&atto, g_atto);
    cudaGetSymbolAddress((void**)&scl,  g_scale);
    cudaGetSymbolAddress((void**)&bia,  g_bias);
    cudaGetSymbolAddress((void**)&whi,  g_Whi);
    cudaGetSymbolAddress((void**)&wlo,  g_Wlo);
    cudaGetSymbolAddress((void**)&bhi,  g_Bhi);
    cudaGetSymbolAddress((void**)&blo,  g_Blo);

    cudaFuncSetAttribute(mgemm_kernel, cudaFuncAttributeMaxDynamicSharedMemorySize, MG_SMEM);
    cudaFuncSetAttribute(mgemm64_kernel_t<0>, cudaFuncAttributeMaxDynamicSharedMemorySize, MG64_SMEM);
    cudaFuncSetAttribute(mgemm64_kernel_t<1>, cudaFuncAttributeMaxDynamicSharedMemorySize, MG64_SMEM);
    cudaFuncSetAttribute(attn_mma_kernel, cudaFuncAttributeMaxDynamicSharedMemorySize, AT_SMEM);

    fold_bn_kernel<<<8, 256>>>(cv1_bn, cv2_bn, mcv1bn, mcv2bn);

    // ---- cv1: 512 -> 512, BN+SiLU, into cat[0:512) ----
    convW_kernel<<<(512 * 512 + 255) / 256, 256>>>(cv1_w, 512, 512, 0, whi, wlo);
    convB_kernel<<<dim3(32, 16, 8), dim3(32, 8)>>>(x, (long)512 * HW, 512, bhi, blo);
    mgemm_kernel<<<dim3(8, 4, 8), 256, MG_SMEM>>>(
        bhi, blo, whi, wlo, 512, cat, (long)1024 * HW,
        scl + 0, bia + 0, nullptr, 0, 1);

    for (int i = 0; i < 2; i++) {
        long yin  = (long)(i == 0 ? 256 : 512) * HW;
        long yout = (long)(512 + i * 256) * HW;

        // z = cbs(yi, 3x3) as IMPLICIT GEMM: yi -> B-layout (K=256), shifted loads, K=2304
        convW_kernel<<<(256 * 2304 + 255) / 256, 256>>>(
            mcv1w + (long)i * 256 * 2304, 256, 2304, 1, whi, wlo);
        convB_kernel<<<dim3(32, 8, 8), dim3(32, 8)>>>(cat + yin, (long)1024 * HW, 256, bhi, blo);
        mgemm64_kernel_t<1><<<dim3(16, 2, 8), 256, MG64_SMEM>>>(
            bhi, blo, whi, wlo, 2304, 256, z, (long)256 * HW,
            scl + 1024 + i * 256, bia + 1024 + i * 256, nullptr, 0, 1);

        // qkv = conv1x1(z), 256 -> 768
        convW_kernel<<<(768 * 256 + 255) / 256, 256>>>(
            mqkvw + (long)i * 768 * 256, 768, 256, 0, whi, wlo);
        convB_kernel<<<dim3(32, 8, 8), dim3(32, 8)>>>(z, (long)256 * HW, 256, bhi, blo);
        mgemm_kernel<<<dim3(8, 6, 8), 256, MG_SMEM>>>(
            bhi, blo, whi, wlo, 256, qkv, (long)768 * HW,
            nullptr, nullptr, nullptr, 0, 0);

        // attention operand conversion + MMA flash attention
        convAttn_kernel<<<dim3(32, 2, 32), dim3(32, 8)>>>(
            qkv, mrw + (long)i * 8192, mrh + (long)i * 8192, bhi, blo);
        attn_mma_kernel<<<dim3(8, 4, 8), 256, AT_SMEM>>>(bhi, blo, atto);

        // y_{i+2} = yi + silu(bn(conv1x1(atto)))
        convW_kernel<<<(256 * 256 + 255) / 256, 256>>>(
            mcv2w + (long)i * 256 * 256, 256, 256, 0, whi, wlo);
        convB_kernel<<<dim3(32, 8, 8), dim3(32, 8)>>>(atto, (long)256 * HW, 256, bhi, blo);
        mgemm64_kernel_t<0><<<dim3(16, 2, 8), 256, MG64_SMEM>>>(
            bhi, blo, whi, wlo, 256, 256, cat + yout, (long)1024 * HW,
            scl + 1536 + i * 256, bia + 1536 + i * 256, cat + yin, (long)1024 * HW, 1);
    }

    // ---- final: 1024 -> 512, BN+SiLU ----
    convW_kernel<<<(512 * 1024 + 255) / 256, 256>>>(cv2_w, 512, 1024, 0, whi, wlo);
    convB_kernel<<<dim3(32, 32, 8), dim3(32, 8)>>>(cat, (long)1024 * HW, 1024, bhi, blo);
    mgemm_kernel<<<dim3(8, 4, 8), 256, MG_SMEM>>>(
        bhi, blo, whi, wlo, 1024, out, (long)512 * HW,
        scl + 512, bia + 512, nullptr, 0, 1);
}

// round 9
// speedup vs baseline: 1.3645x; 1.1563x over previous
#include <cuda_runtime.h>
#include <cuda_bf16.h>
#include <cuda_fp16.h>
#include <cstdint>

#define HW 1024

// ---------------- scratch (__device__ globals: alloc-guard-safe) ----------------
__device__ float g_cat [8u * 1024u * HW];   // 32 MB
__device__ float g_z   [8u * 256u  * HW];   //  8 MB
__device__ float g_qkv [8u * 768u  * HW];   // 24 MB
__device__ float g_atto[8u * 256u  * HW];   //  8 MB
__device__ float g_scale[2048];
__device__ float g_bias [2048];
__device__ uint16_t g_Whi[589824];          // fp16 weight hi
__device__ uint16_t g_Wlo[589824];          // fp16 weight lo
__device__ uint16_t g_Bhi[18874368];        // fp16 activations (GEMM) / bf16 attn hi
__device__ uint16_t g_Blo[18874368];        // bf16 attn lo only

// offsets (elements) inside g_Bhi/g_Blo for attention operands
#define QT_OFF 0
#define KT_OFF 2097152
#define V_OFF  4194304

__device__ __forceinline__ float silu_f(float v) { return v / (1.f + __expf(-v)); }

__device__ __forceinline__ uint32_t smem_u32(const void* p) {
    uint32_t a;
    asm("{ .reg .u64 t; cvta.to.shared.u64 t, %1; cvt.u32.u64 %0, t; }" : "=r"(a) : "l"(p));
    return a;
}
#define SWZ128(o) ((o) ^ (((o) >> 3) & 0x70))
#define SWZ64(o)  ((o) ^ (((o) >> 3) & 0x30))

__device__ __forceinline__ void ldsm_x4(uint32_t* r, uint32_t a) {
    asm volatile("ldmatrix.sync.aligned.m8n8.x4.shared.b16 {%0,%1,%2,%3}, [%4];"
        : "=r"(r[0]), "=r"(r[1]), "=r"(r[2]), "=r"(r[3]) : "r"(a));
}
__device__ __forceinline__ void ldsm_x2(uint32_t* r, uint32_t a) {
    asm volatile("ldmatrix.sync.aligned.m8n8.x2.shared.b16 {%0,%1}, [%2];"
        : "=r"(r[0]), "=r"(r[1]) : "r"(a));
}
// bf16 mma (attention)
__device__ __forceinline__ void mma16816(float* d, const uint32_t* a, const uint32_t* b) {
    asm volatile("mma.sync.aligned.m16n8k16.row.col.f32.bf16.bf16.f32 "
        "{%0,%1,%2,%3}, {%4,%5,%6,%7}, {%8,%9}, {%0,%1,%2,%3};"
        : "+f"(d[0]), "+f"(d[1]), "+f"(d[2]), "+f"(d[3])
        : "r"(a[0]), "r"(a[1]), "r"(a[2]), "r"(a[3]), "r"(b[0]), "r"(b[1]));
}
// fp16 mma (GEMMs)
__device__ __forceinline__ void mma16816f(float* d, const uint32_t* a, const uint32_t* b) {
    asm volatile("mma.sync.aligned.m16n8k16.row.col.f32.f16.f16.f32 "
        "{%0,%1,%2,%3}, {%4,%5,%6,%7}, {%8,%9}, {%0,%1,%2,%3};"
        : "+f"(d[0]), "+f"(d[1]), "+f"(d[2]), "+f"(d[3])
        : "r"(a[0]), "r"(a[1]), "r"(a[2]), "r"(a[3]), "r"(b[0]), "r"(b[1]));
}
__device__ __forceinline__ void cpa16(uint32_t d, const void* s) {
    asm volatile("cp.async.cg.shared.global [%0], [%1], 16;" :: "r"(d), "l"(s));
}
__device__ __forceinline__ void cpa16z(uint32_t d, const void* s, int sz) {
    asm volatile("cp.async.cg.shared.global [%0], [%1], 16, %2;" :: "r"(d), "l"(s), "r"(sz));
}
#define CPA_COMMIT() asm volatile("cp.async.commit_group;" ::: "memory")
#define CPA_WAIT1()  asm volatile("cp.async.wait_group 1;" ::: "memory")
#define CPA_WAIT0()  asm volatile("cp.async.wait_group 0;" ::: "memory")

__device__ __forceinline__ uint32_t packbf(float lo, float hi) {
    uint32_t r;
    asm("cvt.rn.bf16x2.f32 %0, %1, %2;" : "=r"(r) : "f"(hi), "f"(lo));
    return r;
}

// ---------------- BN fold ----------------
__global__ void fold_bn_kernel(const float* __restrict__ cv1, const float* __restrict__ cv2,
                               const float* __restrict__ mcv1, const float* __restrict__ mcv2)
{
    int c = blockIdx.x * 256 + threadIdx.x;
    if (c >= 2048) return;
    const float* p; int C, lc;
    if (c < 512)        { p = cv1;  C = 512; lc = c; }
    else if (c < 1024)  { p = cv2;  C = 512; lc = c - 512; }
    else if (c < 1536)  { int i = (c - 1024) >> 8; p = mcv1 + i * 1024; C = 256; lc = (c - 1024) & 255; }
    else                { int i = (c - 1536) >> 8; p = mcv2 + i * 1024; C = 256; lc = (c - 1536) & 255; }
    float g = p[lc], b = p[C + lc], m = p[2 * C + lc], v = p[3 * C + lc];
    float s = g / sqrtf(v + 1e-3f);
    g_scale[c] = s;
    g_bias[c]  = b - m * s;
}

// ---------------- weight converter: fp32 -> fp16 hi/lo ----------------
__global__ void convW_kernel(const float* __restrict__ W, int M, int K, int isConv,
                             uint16_t* __restrict__ Whi, uint16_t* __restrict__ Wlo)
{
    long e = (long)blockIdx.x * 256 + threadIdx.x;
    if (e >= (long)M * K) return;
    long m = e / K, k = e % K;
    float v;
    if (isConv) { int off = (int)(k >> 8), ci = (int)(k & 255); v = W[m * 2304 + ci * 9 + off]; }
    else v = W[e];
    __half h = __float2half(v);
    __half l = __float2half(v - __half2float(h));
    Whi[e] = __half_as_ushort(h);
    Wlo[e] = __half_as_ushort(l);
}

// ---------------- activation converter: [b][K][HW] -> fp16 [b][n][K] (hi only) ----------------
__global__ void convB_kernel(const float* __restrict__ In, long inStride, int K,
                             uint16_t* __restrict__ Bhi)
{
    __shared__ float t[32][33];
    int n0 = blockIdx.x * 32, k0 = blockIdx.y * 32, b = blockIdx.z;
    int tx = threadIdx.x, ty = threadIdx.y;
    const float* in = In + (long)b * inStride;
#pragma unroll
    for (int yy = 0; yy < 32; yy += 8)
        t[yy + ty][tx] = in[(long)(k0 + yy + ty) * HW + n0 + tx];
    __syncthreads();
#pragma unroll
    for (int yy = 0; yy < 32; yy += 8) {
        int n = n0 + yy + ty, k = k0 + tx;
        float v = t[tx][yy + ty];
        long o = ((long)b * 1024 + n) * K + k;
        Bhi[o] = __half_as_ushort(__float2half(v));
    }
}

// ---------------- warp-MMA GEMM (N-tile 128): fp16 split-2, 2-stage, K-chunk 32 ----------------
#define MG_STAGE 24576
#define MG_SMEM  49152

__device__ __forceinline__ void mg_load(uint32_t smb, int tid,
    const uint4* __restrict__ wHi, const uint4* __restrict__ wLo,
    const uint4* __restrict__ bHi,
    int m0, int n0, int K16, int c, uint32_t stOff)
{
    uint32_t sb = smb + stOff;
    int r = tid >> 1;
    int j = (tid & 1) * 2;
    uint32_t o0 = SWZ64((uint32_t)(r * 64 + j * 16));
    uint32_t o1 = SWZ64((uint32_t)(r * 64 + (j + 1) * 16));
    const uint4* a;
    a = wHi + (long)(m0 + r) * K16 + c * 4 + j;
    cpa16(sb + o0, a); cpa16(sb + o1, a + 1);
    a = wLo + (long)(m0 + r) * K16 + c * 4 + j;
    cpa16(sb + 8192 + o0, a); cpa16(sb + 8192 + o1, a + 1);
    a = bHi + (long)(n0 + r) * K16 + c * 4 + j;
    cpa16(sb + 16384 + o0, a); cpa16(sb + 16384 + o1, a + 1);
}

extern __shared__ char mg_smem[];

__global__ void __launch_bounds__(256, 2) mgemm_kernel(
    const uint16_t* __restrict__ Bhi,
    const uint16_t* __restrict__ Whi, const uint16_t* __restrict__ Wlo,
    int K,
    float* __restrict__ Out, long outStride,
    const float* __restrict__ scale, const float* __restrict__ bias,
    const float* __restrict__ Res, long resStride,
    int doSilu)
{
    int b = blockIdx.z, m0 = blockIdx.y * 128, n0 = blockIdx.x * 128;
    int tid = threadIdx.x, wid = tid >> 5, lane = tid & 31;
    int warp_m = wid & 1, warp_n = wid >> 1;
    uint32_t smb = smem_u32(mg_smem);

    int K16 = K >> 3;
    const uint4* wHi = (const uint4*)Whi;
    const uint4* wLo = (const uint4*)Wlo;
    const uint4* bHi = (const uint4*)(Bhi + (long)b * 1024 * K);

    float acc[4][4][4];
#pragma unroll
    for (int i = 0; i < 4; i++)
#pragma unroll
        for (int j = 0; j < 4; j++)
#pragma unroll
            for (int r = 0; r < 4; r++) acc[i][j][r] = 0.f;

    int nChunks = K >> 5;
    mg_load(smb, tid, wHi, wLo, bHi, m0, n0, K16, 0, 0);
    CPA_COMMIT();

    int aRowL = warp_m * 64 + (lane & 7) + (lane & 8);
    int aColL = ((lane >> 4) & 1) * 16;
    int bRowX4 = warp_n * 32 + (lane >> 4) * 8 + (lane & 7);  // + p*16
    uint32_t bColX4 = (uint32_t)(((lane >> 3) & 1) * 16);

    for (int c = 0; c < nChunks; c++) {
        int s = c & 1;
        if (c + 1 < nChunks) {
            mg_load(smb, tid, wHi, wLo, bHi, m0, n0, K16, c + 1, (uint32_t)((s ^ 1) * MG_STAGE));
            CPA_COMMIT();
            CPA_WAIT1();
        } else {
            CPA_WAIT0();
        }
        __syncthreads();

        uint32_t base = smb + s * MG_STAGE;
#pragma unroll
        for (int ks = 0; ks < 2; ks++) {
            uint32_t ah[4][4], bh4[2][4];
#pragma unroll
            for (int mt = 0; mt < 4; mt++)
                ldsm_x4(ah[mt], base + SWZ64((uint32_t)((aRowL + mt * 16) * 64 + aColL + ks * 32)));
#pragma unroll
            for (int p = 0; p < 2; p++)
                ldsm_x4(bh4[p], base + 16384 + SWZ64((uint32_t)((bRowX4 + p * 16) * 64 + bColX4 + ks * 32)));
#pragma unroll
            for (int mt = 0; mt < 4; mt++)
#pragma unroll
                for (int p = 0; p < 2; p++) {
                    mma16816f(acc[mt][2 * p],     ah[mt], &bh4[p][0]);
                    mma16816f(acc[mt][2 * p + 1], ah[mt], &bh4[p][2]);
                }

            uint32_t al[4][4];
#pragma unroll
            for (int mt = 0; mt < 4; mt++)
                ldsm_x4(al[mt], base + 8192 + SWZ64((uint32_t)((aRowL + mt * 16) * 64 + aColL + ks * 32)));
#pragma unroll
            for (int mt = 0; mt < 4; mt++)
#pragma unroll
                for (int p = 0; p < 2; p++) {
                    mma16816f(acc[mt][2 * p],     al[mt], &bh4[p][0]);
                    mma16816f(acc[mt][2 * p + 1], al[mt], &bh4[p][2]);
                }
        }
        __syncthreads();
    }

#pragma unroll
    for (int mt = 0; mt < 4; mt++) {
        int mb = m0 + warp_m * 64 + mt * 16 + (lane >> 2);
#pragma unroll
        for (int h2 = 0; h2 < 2; h2++) {
            int m = mb + h2 * 8;
            float s = 1.f, bb = 0.f;
            if (scale) { s = scale[m]; bb = bias[m]; }
            long rowOff = (long)b * outStride + (long)m * HW;
            long resOff = Res ? ((long)b * resStride + (long)m * HW) : 0;
#pragma unroll
            for (int nt = 0; nt < 4; nt++) {
                int n = n0 + warp_n * 32 + nt * 8 + (lane & 3) * 2;
                float v0 = acc[mt][nt][h2 * 2 + 0] * s + bb;
                float v1 = acc[mt][nt][h2 * 2 + 1] * s + bb;
                if (doSilu) { v0 = silu_f(v0); v1 = silu_f(v1); }
                if (Res) {
                    float2 r2 = *(const float2*)&Res[resOff + n];
                    v0 += r2.x; v1 += r2.y;
                }
                *(float2*)&Out[rowOff + n] = make_float2(v0, v1);
            }
        }
    }
}

// ---------------- warp-MMA GEMM (N-tile 64): fp16 split-2; generic or implicit-conv B ----------------
#define MG64_STAGE 20480
#define MG64_SMEM  40960

__device__ __forceinline__ void mg64_load(uint32_t smb, int tid,
    const uint4* __restrict__ wHi, const uint4* __restrict__ wLo,
    const uint4* __restrict__ bHi,
    int m0, int n0, int K16, int c, uint32_t stOff)
{
    uint32_t sb = smb + stOff;
    int r = tid >> 1, j = (tid & 1) * 2;
    uint32_t o0 = SWZ64((uint32_t)(r * 64 + j * 16));
    uint32_t o1 = SWZ64((uint32_t)(r * 64 + (j + 1) * 16));
    const uint4* a;
    a = wHi + (long)(m0 + r) * K16 + c * 4 + j;
    cpa16(sb + o0, a); cpa16(sb + o1, a + 1);
    a = wLo + (long)(m0 + r) * K16 + c * 4 + j;
    cpa16(sb + 8192 + o0, a); cpa16(sb + 8192 + o1, a + 1);
    int rb = tid >> 2, jb = tid & 3;
    uint32_t ob = SWZ64((uint32_t)(rb * 64 + jb * 16));
    a = bHi + (long)(n0 + rb) * K16 + c * 4 + jb;
    cpa16(sb + 16384 + ob, a);
}

// implicit 3x3 conv B loader: B is yi in fp16 [n][256]; chunk c -> tap (c>>3), ci-block (c&7)
__device__ __forceinline__ void mgc_load(uint32_t smb, int tid,
    const uint4* __restrict__ wHi, const uint4* __restrict__ wLo,
    const uint4* __restrict__ bHi,
    int m0, int n0, int K16, int c, uint32_t stOff)
{
    uint32_t sb = smb + stOff;
    int r = tid >> 1, j = (tid & 1) * 2;
    uint32_t o0 = SWZ64((uint32_t)(r * 64 + j * 16));
    uint32_t o1 = SWZ64((uint32_t)(r * 64 + (j + 1) * 16));
    const uint4* a;
    a = wHi + (long)(m0 + r) * K16 + c * 4 + j;
    cpa16(sb + o0, a); cpa16(sb + o1, a + 1);
    a = wLo + (long)(m0 + r) * K16 + c * 4 + j;
    cpa16(sb + 8192 + o0, a); cpa16(sb + 8192 + o1, a + 1);

    int off = c >> 3, cik = c & 7;
    int dy = off / 3 - 1, dx = off % 3 - 1;
    int rb = tid >> 2, jb = tid & 3;
    int pix = n0 + rb;
    int y = (pix >> 5) + dy, x = (pix & 31) + dx;
    bool ok = ((unsigned)y < 32u) && ((unsigned)x < 32u);
    int ps = ok ? (y * 32 + x) : 0;
    int sz = ok ? 16 : 0;
    uint32_t ob = SWZ64((uint32_t)(rb * 64 + jb * 16));
    cpa16z(sb + 16384 + ob, bHi + (long)ps * 32 + cik * 4 + jb, sz);
}

template <int CONV>
__global__ void __launch_bounds__(256, 2) mgemm64_kernel_t(
    const uint16_t* __restrict__ Bhi,
    const uint16_t* __restrict__ Whi, const uint16_t* __restrict__ Wlo,
    int K, int bK,
    float* __restrict__ Out, long outStride,
    const float* __restrict__ scale, const float* __restrict__ bias,
    const float* __restrict__ Res, long resStride,
    int doSilu)
{
    int b = blockIdx.z, m0 = blockIdx.y * 128, n0 = blockIdx.x * 64;
    int tid = threadIdx.x, wid = tid >> 5, lane = tid & 31;
    int warp_m = wid & 3, warp_n = wid >> 2;
    uint32_t smb = smem_u32(mg_smem);

    int K16 = K >> 3;
    const uint4* wHi = (const uint4*)Whi;
    const uint4* wLo = (const uint4*)Wlo;
    const uint4* bHi = (const uint4*)(Bhi + (long)b * 1024 * bK);

    float acc[2][4][4];
#pragma unroll
    for (int i = 0; i < 2; i++)
#pragma unroll
        for (int j = 0; j < 4; j++)
#pragma unroll
            for (int r = 0; r < 4; r++) acc[i][j][r] = 0.f;

    int nChunks = K >> 5;
    if (CONV) mgc_load(smb, tid, wHi, wLo, bHi, m0, n0, K16, 0, 0);
    else      mg64_load(smb, tid, wHi, wLo, bHi, m0, n0, K16, 0, 0);
    CPA_COMMIT();

    int aRowL = warp_m * 32 + (lane & 7) + (lane & 8);
    int aColL = ((lane >> 4) & 1) * 16;
    int bRowX4 = warp_n * 32 + (lane >> 4) * 8 + (lane & 7);  // + p*16
    uint32_t bColX4 = (uint32_t)(((lane >> 3) & 1) * 16);

    for (int c = 0; c < nChunks; c++) {
        int s = c & 1;
        if (c + 1 < nChunks) {
            if (CONV) mgc_load(smb, tid, wHi, wLo, bHi, m0, n0, K16, c + 1, (uint32_t)((s ^ 1) * MG64_STAGE));
            else      mg64_load(smb, tid, wHi, wLo, bHi, m0, n0, K16, c + 1, (uint32_t)((s ^ 1) * MG64_STAGE));
            CPA_COMMIT();
            CPA_WAIT1();
        } else {
            CPA_WAIT0();
        }
        __syncthreads();

        uint32_t base = smb + s * MG64_STAGE;
#pragma unroll
        for (int ks = 0; ks < 2; ks++) {
            uint32_t ah[2][4], bh4[2][4];
#pragma unroll
            for (int mt = 0; mt < 2; mt++)
                ldsm_x4(ah[mt], base + SWZ64((uint32_t)((aRowL + mt * 16) * 64 + aColL + ks * 32)));
#pragma unroll
            for (int p = 0; p < 2; p++)
                ldsm_x4(bh4[p], base + 16384 + SWZ64((uint32_t)((bRowX4 + p * 16) * 64 + bColX4 + ks * 32)));
#pragma unroll
            for (int mt = 0; mt < 2; mt++)
#pragma unroll
                for (int p = 0; p < 2; p++) {
                    mma16816f(acc[mt][2 * p],     ah[mt], &bh4[p][0]);
                    mma16816f(acc[mt][2 * p + 1], ah[mt], &bh4[p][2]);
                }

            uint32_t al[2][4];
#pragma unroll
            for (int mt = 0; mt < 2; mt++)
                ldsm_x4(al[mt], base + 8192 + SWZ64((uint32_t)((aRowL + mt * 16) * 64 + aColL + ks * 32)));
#pragma unroll
            for (int mt = 0; mt < 2; mt++)
#pragma unroll
                for (int p = 0; p < 2; p++) {
                    mma16816f(acc[mt][2 * p],     al[mt], &bh4[p][0]);
                    mma16816f(acc[mt][2 * p + 1], al[mt], &bh4[p][2]);
                }
        }
        __syncthreads();
    }

#pragma unroll
    for (int mt = 0; mt < 2; mt++) {
        int mb = m0 + warp_m * 32 + mt * 16 + (lane >> 2);
#pragma unroll
        for (int h2 = 0; h2 < 2; h2++) {
            int m = mb + h2 * 8;
            float s = 1.f, bb = 0.f;
            if (scale) { s = scale[m]; bb = bias[m]; }
            long rowOff = (long)b * outStride + (long)m * HW;
            long resOff = Res ? ((long)b * resStride + (long)m * HW) : 0;
#pragma unroll
            for (int nt = 0; nt < 4; nt++) {
                int n = n0 + warp_n * 32 + nt * 8 + (lane & 3) * 2;
                float v0 = acc[mt][nt][h2 * 2 + 0] * s + bb;
                float v1 = acc[mt][nt][h2 * 2 + 1] * s + bb;
                if (doSilu) { v0 = silu_f(v0); v1 = silu_f(v1); }
                if (Res) {
                    float2 r2 = *(const float2*)&Res[resOff + n];
                    v0 += r2.x; v1 += r2.y;
                }
                *(float2*)&Out[rowOff + n] = make_float2(v0, v1);
            }
        }
    }
}

// ---------------- attention converter: qkv fp32 -> qT/kT(+relpos)/v bf16 hi/lo ----------------
__global__ void convAttn_kernel(const float* __restrict__ QKV,
                                const float* __restrict__ RW, const float* __restrict__ RH,
                                __nv_bfloat16* __restrict__ Hi, __nv_bfloat16* __restrict__ Lo)
{
    __shared__ float tq[32][33], tk[32][33];
    int it = blockIdx.x, dt = blockIdx.y, bh = blockIdx.z;
    int b = bh >> 2, hh = bh & 3;
    int tx = threadIdx.x, ty = threadIdx.y;
    const float* base = QKV + (long)b * 768 * HW;
#pragma unroll
    for (int l = 0; l < 4; l++) {
        int d = dt * 32 + ty + l * 8;
        int ch = hh * 64 + d;
        float qv = base[(long)ch * HW + it * 32 + tx] * 0.125f;
        float kv = base[(long)(256 + ch) * HW + it * 32 + tx] + RW[ch * 32 + tx] + RH[ch * 32 + it];
        float vv = base[(long)(512 + ch) * HW + it * 32 + tx];
        tq[ty + l * 8][tx] = qv;
        tk[ty + l * 8][tx] = kv;
        long vo = V_OFF + ((long)bh * 64 + d) * 1024 + it * 32 + tx;
        __nv_bfloat16 vh = __float2bfloat16(vv);
        Hi[vo] = vh;
        Lo[vo] = __float2bfloat16(vv - __bfloat162float(vh));
    }
    __syncthreads();
#pragma unroll
    for (int l = 0; l < 4; l++) {
        int i = it * 32 + ty + l * 8;
        int d = dt * 32 + tx;
        float qv = tq[tx][ty + l * 8];
        float kv = tk[tx][ty + l * 8];
        long qo = ((long)bh * 1024 + i) * 64 + d;
        __nv_bfloat16 qh = __float2bfloat16(qv);
        Hi[QT_OFF + qo] = qh;
        Lo[QT_OFF + qo] = __float2bfloat16(qv - __bfloat162float(qh));
        __nv_bfloat16 kh = __float2bfloat16(kv);
        Hi[KT_OFF + qo] = kh;
        Lo[KT_OFF + qo] = __float2bfloat16(kv - __bfloat162float(kh));
    }
}

// ---------------- MMA flash attention (bf16 split-3, unchanged) ----------------
#define AT_SMEM 163840

__device__ __forceinline__ void kv_load(uint32_t smb, int tid,
    const __nv_bfloat16* __restrict__ kTh, const __nv_bfloat16* __restrict__ kTl,
    const __nv_bfloat16* __restrict__ vH, const __nv_bfloat16* __restrict__ vL,
    int bh, int t, uint32_t stOff)
{
    uint32_t kb = smb + stOff;
    const uint4* kh4 = (const uint4*)(kTh + ((long)bh * 1024 + t * 128) * 64);
    const uint4* kl4 = (const uint4*)(kTl + ((long)bh * 1024 + t * 128) * 64);
    int r = tid >> 1, j0 = (tid & 1) * 4;
#pragma unroll
    for (int j = 0; j < 4; j++) {
        uint32_t off = SWZ128((uint32_t)(r * 128 + (j0 + j) * 16));
        cpa16(kb + off, kh4 + (long)r * 8 + j0 + j);
        cpa16(kb + 16384 + off, kl4 + (long)r * 8 + j0 + j);
    }
    const uint4* vh4 = (const uint4*)(vH + (long)bh * 65536 + t * 128);
    const uint4* vl4 = (const uint4*)(vL + (long)bh * 65536 + t * 128);
    int d = tid >> 2, jc0 = (tid & 3) * 4;
#pragma unroll
    for (int j = 0; j < 4; j++) {
        int jc = jc0 + j;
        uint32_t off = (uint32_t)((jc >> 3) * 8192) + SWZ128((uint32_t)(d * 128 + (jc & 7) * 16));
        cpa16(kb + 32768 + off, vh4 + (long)d * 128 + jc);
        cpa16(kb + 49152 + off, vl4 + (long)d * 128 + jc);
    }
}

extern __shared__ char at_smem[];

__global__ void __launch_bounds__(256) attn_mma_kernel(
    const __nv_bfloat16* __restrict__ Hi, const __nv_bfloat16* __restrict__ Lo,
    float* __restrict__ Outp)
{
    int qt = blockIdx.x, h = blockIdx.y, b = blockIdx.z;
    int bh = b * 4 + h;
    int tid = threadIdx.x, wid = tid >> 5, lane = tid & 31, li = lane & 15;
    uint32_t smb = smem_u32(at_smem);

    const __nv_bfloat16* qTh = Hi + QT_OFF;
    const __nv_bfloat16* qTl = Lo + QT_OFF;
    const __nv_bfloat16* kTh = Hi + KT_OFF;
    const __nv_bfloat16* kTl = Lo + KT_OFF;
    const __nv_bfloat16* vH  = Hi + V_OFF;
    const __nv_bfloat16* vL  = Lo + V_OFF;

    {
        const uint4* qh4 = (const uint4*)(qTh + ((long)bh * 1024 + qt * 128) * 64);
        const uint4* ql4 = (const uint4*)(qTl + ((long)bh * 1024 + qt * 128) * 64);
        int r = tid >> 1, j0 = (tid & 1) * 4;
        uint32_t qb = smb + 131072;
#pragma unroll
        for (int j = 0; j < 4; j++) {
            uint32_t off = SWZ128((uint32_t)(r * 128 + (j0 + j) * 16));
            cpa16(qb + off, qh4 + (long)r * 8 + j0 + j);
            cpa16(qb + 16384 + off, ql4 + (long)r * 8 + j0 + j);
        }
    }
    CPA_COMMIT();
    kv_load(smb, tid, kTh, kTl, vH, vL, bh, 0, 0);
    CPA_COMMIT();
    CPA_WAIT1();
    __syncthreads();

    uint32_t qfh[4][4], qfl[4][4];
    {
        int aRow = wid * 16 + (lane & 7) + (lane & 8);
        int aCol = ((lane >> 4) & 1) * 16;
#pragma unroll
        for (int ks = 0; ks < 4; ks++) {
            uint32_t off = SWZ128((uint32_t)(aRow * 128 + aCol + ks * 32));
            ldsm_x4(qfh[ks], smb + 131072 + off);
            ldsm_x4(qfl[ks], smb + 131072 + 16384 + off);
        }
    }

    float oacc[8][4];
#pragma unroll
    for (int i = 0; i < 8; i++)
#pragma unroll
        for (int j = 0; j < 4; j++) oacc[i][j] = 0.f;
    float m0 = -1e30f, m1 = -1e30f, l0 = 0.f, l1 = 0.f;

    int sRowX4 = (lane >> 4) * 8 + (lane & 7);
    uint32_t sColX4 = (uint32_t)(((lane >> 3) & 1) * 16);

    for (int t = 0; t < 8; t++) {
        int s = t & 1;
        if (t < 7) {
            kv_load(smb, tid, kTh, kTl, vH, vL, bh, t + 1, (uint32_t)((s ^ 1) * 65536));
            CPA_COMMIT();
            CPA_WAIT1();
        } else {
            CPA_WAIT0();
        }
        __syncthreads();

        uint32_t kb = smb + s * 65536;
        float sacc[16][4];
#pragma unroll
        for (int i = 0; i < 16; i++)
#pragma unroll
            for (int j = 0; j < 4; j++) sacc[i][j] = 0.f;

#pragma unroll
        for (int p = 0; p < 8; p++) {
            int rowB = p * 16 + sRowX4;
#pragma unroll
            for (int ks = 0; ks < 4; ks++) {
                uint32_t off = SWZ128((uint32_t)(rowB * 128 + sColX4 + ks * 32));
                uint32_t kh4[4], kl4[4];
                ldsm_x4(kh4, kb + off);
                ldsm_x4(kl4, kb + 16384 + off);
                mma16816(sacc[2 * p],     qfh[ks], &kh4[0]);
                mma16816(sacc[2 * p + 1], qfh[ks], &kh4[2]);
                mma16816(sacc[2 * p],     qfl[ks], &kh4[0]);
                mma16816(sacc[2 * p + 1], qfl[ks], &kh4[2]);
                mma16816(sacc[2 * p],     qfh[ks], &kl4[0]);
                mma16816(sacc[2 * p + 1], qfh[ks], &kl4[2]);
            }
        }

        float mx0 = m0, mx1 = m1;
#pragma unroll
        for (int nt = 0; nt < 16; nt++) {
            mx0 = fmaxf(mx0, fmaxf(sacc[nt][0], sacc[nt][1]));
            mx1 = fmaxf(mx1, fmaxf(sacc[nt][2], sacc[nt][3]));
        }
        mx0 = fmaxf(mx0, __shfl_xor_sync(0xffffffffu, mx0, 1));
        mx0 = fmaxf(mx0, __shfl_xor_sync(0xffffffffu, mx0, 2));
        mx1 = fmaxf(mx1, __shfl_xor_sync(0xffffffffu, mx1, 1));
        mx1 = fmaxf(mx1, __shfl_xor_sync(0xffffffffu, mx1, 2));
        float a0 = __expf(m0 - mx0), a1 = __expf(m1 - mx1);
        m0 = mx0; m1 = mx1;

        float ls0 = 0.f, ls1 = 0.f;
        uint32_t pah[8][4], pal[8][4];
#pragma unroll
        for (int kj = 0; kj < 8; kj++) {
            float p00 = __expf(sacc[2 * kj][0] - m0);
            float p01 = __expf(sacc[2 * kj][1] - m0);
            float p02 = __expf(sacc[2 * kj][2] - m1);
            float p03 = __expf(sacc[2 * kj][3] - m1);
            float p10 = __expf(sacc[2 * kj + 1][0] - m0);
            float p11 = __expf(sacc[2 * kj + 1][1] - m0);
            float p12 = __expf(sacc[2 * kj + 1][2] - m1);
            float p13 = __expf(sacc[2 * kj + 1][3] - m1);
            ls0 += p00 + p01 + p10 + p11;
            ls1 += p02 + p03 + p12 + p13;
            pah[kj][0] = packbf(p00, p01);
            pah[kj][1] = packbf(p02, p03);
            pah[kj][2] = packbf(p10, p11);
            pah[kj][3] = packbf(p12, p13);
            float q00 = p00 - __bfloat162float(__float2bfloat16(p00));
            float q01 = p01 - __bfloat162float(__float2bfloat16(p01));
            float q02 = p02 - __bfloat162float(__float2bfloat16(p02));
            float q03 = p03 - __bfloat162float(__float2bfloat16(p03));
            float q10 = p10 - __bfloat162float(__float2bfloat16(p10));
            float q11 = p11 - __bfloat162float(__float2bfloat16(p11));
            float q12 = p12 - __bfloat162float(__float2bfloat16(p12));
            float q13 = p13 - __bfloat162float(__float2bfloat16(p13));
            pal[kj][0] = packbf(q00, q01);
            pal[kj][1] = packbf(q02, q03);
            pal[kj][2] = packbf(q10, q11);
            pal[kj][3] = packbf(q12, q13);
        }
        ls0 += __shfl_xor_sync(0xffffffffu, ls0, 1);
        ls0 += __shfl_xor_sync(0xffffffffu, ls0, 2);
        ls1 += __shfl_xor_sync(0xffffffffu, ls1, 1);
        ls1 += __shfl_xor_sync(0xffffffffu, ls1, 2);
        l0 = l0 * a0 + ls0;
        l1 = l1 * a1 + ls1;
#pragma unroll
        for (int dt = 0; dt < 8; dt++) {
            oacc[dt][0] *= a0; oacc[dt][1] *= a0;
            oacc[dt][2] *= a1; oacc[dt][3] *= a1;
        }

#pragma unroll
        for (int dt = 0; dt < 8; dt++) {
            int rowV = dt * 8 + (li & 7);
#pragma unroll
            for (int kj = 0; kj < 8; kj++) {
                uint32_t off = (uint32_t)((kj >> 2) * 8192) +
                               SWZ128((uint32_t)(rowV * 128 + (li >> 3) * 16 + (kj & 3) * 32));
                uint32_t vh2[2], vl2[2];
                ldsm_x2(vh2, kb + 32768 + off);
                ldsm_x2(vl2, kb + 49152 + off);
                mma16816(oacc[dt], pah[kj], vh2);
                mma16816(oacc[dt], pal[kj], vh2);
                mma16816(oacc[dt], pah[kj], vl2);
            }
        }
        __syncthreads();
    }

    float i0 = 1.f / l0, i1 = 1.f / l1;
    float* stg = (float*)at_smem;   // [128][66]
    int r0 = wid * 16 + (lane >> 2);
#pragma unroll
    for (int dt = 0; dt < 8; dt++) {
        int d = dt * 8 + (lane & 3) * 2;
        stg[r0 * 66 + d]           = oacc[dt][0] * i0;
        stg[r0 * 66 + d + 1]       = oacc[dt][1] * i0;
        stg[(r0 + 8) * 66 + d]     = oacc[dt][2] * i1;
        stg[(r0 + 8) * 66 + d + 1] = oacc[dt][3] * i1;
    }
    __syncthreads();
    for (int e = tid; e < 8192; e += 256) {
        int d = e >> 7, i = e & 127;
        Outp[((long)b * 256 + h * 64 + d) * HW + qt * 128 + i] = stg[i * 66 + d];
    }
}

// ---------------- launch ----------------
extern "C" void kernel_launch(void* const* d_in, const int* in_sizes, int n_in,
                              void* d_out, int out_size)
{
    const float* x      = (const float*)d_in[0];
    const float* cv1_w  = (const float*)d_in[1];
    const float* cv1_bn = (const float*)d_in[2];
    const float* cv2_w  = (const float*)d_in[3];
    const float* cv2_bn = (const float*)d_in[4];
    const float* mcv1w  = (const float*)d_in[5];
    const float* mcv1bn = (const float*)d_in[6];
    const float* mqkvw  = (const float*)d_in[7];
    const float* mrw    = (const float*)d_in[8];
    const float* mrh    = (const float*)d_in[9];
    const float* mcv2w  = (const float*)d_in[10];
    const float* mcv2bn = (const float*)d_in[11];
    float* out = (float*)d_out;

    float *cat, *z, *qkv, *atto, *scl, *bia;
    uint16_t *whi, *wlo, *bhi, *blo;
    cudaGetSymbolAddress((void**)&cat,  g_cat);
    cudaGetSymbolAddress((void**)&z,    g_z);
    cudaGetSymbolAddress((void**)&qkv,  g_qkv);
    cudaGetSymbolAddress((void**)&atto, g_atto);
    cudaGetSymbolAddress((void**)&scl,  g_scale);
    cudaGetSymbolAddress((void**)&bia,  g_bias);
    cudaGetSymbolAddress((void**)&whi,  g_Whi);
    cudaGetSymbolAddress((void**)&wlo,  g_Wlo);
    cudaGetSymbolAddress((void**)&bhi,  g_Bhi);
    cudaGetSymbolAddress((void**)&blo,  g_Blo);
    __nv_bfloat16* bhiB = (__nv_bfloat16*)bhi;
    __nv_bfloat16* bloB = (__nv_bfloat16*)blo;

    cudaFuncSetAttribute(mgemm_kernel, cudaFuncAttributeMaxDynamicSharedMemorySize, MG_SMEM);
    cudaFuncSetAttribute(mgemm64_kernel_t<0>, cudaFuncAttributeMaxDynamicSharedMemorySize, MG64_SMEM);
    cudaFuncSetAttribute(mgemm64_kernel_t<1>, cudaFuncAttributeMaxDynamicSharedMemorySize, MG64_SMEM);
    cudaFuncSetAttribute(attn_mma_kernel, cudaFuncAttributeMaxDynamicSharedMemorySize, AT_SMEM);

    fold_bn_kernel<<<8, 256>>>(cv1_bn, cv2_bn, mcv1bn, mcv2bn);

    // ---- cv1: 512 -> 512, BN+SiLU, into cat[0:512) ----
    convW_kernel<<<(512 * 512 + 255) / 256, 256>>>(cv1_w, 512, 512, 0, whi, wlo);
    convB_kernel<<<dim3(32, 16, 8), dim3(32, 8)>>>(x, (long)512 * HW, 512, bhi);
    mgemm_kernel<<<dim3(8, 4, 8), 256, MG_SMEM>>>(
        bhi, whi, wlo, 512, cat, (long)1024 * HW,
        scl + 0, bia + 0, nullptr, 0, 1);

    for (int i = 0; i < 2; i++) {
        long yin  = (long)(i == 0 ? 256 : 512) * HW;
        long yout = (long)(512 + i * 256) * HW;

        // z = cbs(yi, 3x3) as IMPLICIT GEMM: yi -> fp16 B-layout (K=256), shifted loads, K=2304
        convW_kernel<<<(256 * 2304 + 255) / 256, 256>>>(
            mcv1w + (long)i * 256 * 2304, 256, 2304, 1, whi, wlo);
        convB_kernel<<<dim3(32, 8, 8), dim3(32, 8)>>>(cat + yin, (long)1024 * HW, 256, bhi);
        mgemm64_kernel_t<1><<<dim3(16, 2, 8), 256, MG64_SMEM>>>(
            bhi, whi, wlo, 2304, 256, z, (long)256 * HW,
            scl + 1024 + i * 256, bia + 1024 + i * 256, nullptr, 0, 1);

        // qkv = conv1x1(z), 256 -> 768
        convW_kernel<<<(768 * 256 + 255) / 256, 256>>>(
            mqkvw + (long)i * 768 * 256, 768, 256, 0, whi, wlo);
        convB_kernel<<<dim3(32, 8, 8), dim3(32, 8)>>>(z, (long)256 * HW, 256, bhi);
        mgemm_kernel<<<dim3(8, 6, 8), 256, MG_SMEM>>>(
            bhi, whi, wlo, 256, qkv, (long)768 * HW,
            nullptr, nullptr, nullptr, 0, 0);

        // attention operand conversion (bf16 split-3) + MMA flash attention
        convAttn_kernel<<<dim3(32, 2, 32), dim3(32, 8)>>>(
            qkv, mrw + (long)i * 8192, mrh + (long)i * 8192, bhiB, bloB);
        attn_mma_kernel<<<dim3(8, 4, 8), 256, AT_SMEM>>>(bhiB, bloB, atto);

        // y_{i+2} = yi + silu(bn(conv1x1(atto)))
        convW_kernel<<<(256 * 256 + 255) / 256, 256>>>(
            mcv2w + (long)i * 256 * 256, 256, 256, 0, whi, wlo);
        convB_kernel<<<dim3(32, 8, 8), dim3(32, 8)>>>(atto, (long)256 * HW, 256, bhi);
        mgemm64_kernel_t<0><<<dim3(16, 2, 8), 256, MG64_SMEM>>>(
            bhi, whi, wlo, 256, 256, cat + yout, (long)1024 * HW,
            scl + 1536 + i * 256, bia + 1536 + i * 256, cat + yin, (long)1024 * HW, 1);
    }

    // ---- final: 1024 -> 512, BN+SiLU ----
    convW_kernel<<<(512 * 1024 + 255) / 256, 256>>>(cv2_w, 512, 1024, 0, whi, wlo);
    convB_kernel<<<dim3(32, 32, 8), dim3(32, 8)>>>(cat, (long)1024 * HW, 1024, bhi);
    mgemm_kernel<<<dim3(8, 4, 8), 256, MG_SMEM>>>(
        bhi, whi, wlo, 1024, out, (long)512 * HW,
        scl + 512, bia + 512, nullptr, 0, 1);
}

// round 10
// speedup vs baseline: 1.4425x; 1.0572x over previous
#include <cuda_runtime.h>
#include <cuda_bf16.h>
#include <cuda_fp16.h>
#include <cstdint>

#define HW 1024

// ---------------- scratch (__device__ globals: alloc-guard-safe) ----------------
__device__ float    g_cat  [8u * 1024u * HW];   // 32 MB fp32 (residual path)
__device__ uint16_t g_catH [8u * 1024u * HW];   // 16 MB fp16 shadow
__device__ uint16_t g_zH   [8u * 256u  * HW];   // fp16 conv output
__device__ uint16_t g_qkvH [8u * 768u  * HW];   // fp16 qkv
__device__ uint16_t g_attoH[8u * 256u  * HW];   // fp16 attention output
__device__ float g_scale[2048];
__device__ float g_bias [2048];
__device__ uint16_t g_Whi[589824];
__device__ uint16_t g_Wlo[589824];
__device__ uint16_t g_Bhi[18874368];
__device__ uint16_t g_Blo[18874368];

// offsets (elements) inside g_Bhi/g_Blo for attention operands
#define QT_OFF 0
#define KT_OFF 2097152
#define V_OFF  4194304

__device__ __forceinline__ float silu_f(float v) { return v / (1.f + __expf(-v)); }

__device__ __forceinline__ uint32_t smem_u32(const void* p) {
    uint32_t a;
    asm("{ .reg .u64 t; cvta.to.shared.u64 t, %1; cvt.u32.u64 %0, t; }" : "=r"(a) : "l"(p));
    return a;
}
#define SWZ128(o) ((o) ^ (((o) >> 3) & 0x70))
#define SWZ64(o)  ((o) ^ (((o) >> 3) & 0x30))

__device__ __forceinline__ void ldsm_x4(uint32_t* r, uint32_t a) {
    asm volatile("ldmatrix.sync.aligned.m8n8.x4.shared.b16 {%0,%1,%2,%3}, [%4];"
        : "=r"(r[0]), "=r"(r[1]), "=r"(r[2]), "=r"(r[3]) : "r"(a));
}
__device__ __forceinline__ void ldsm_x2(uint32_t* r, uint32_t a) {
    asm volatile("ldmatrix.sync.aligned.m8n8.x2.shared.b16 {%0,%1}, [%2];"
        : "=r"(r[0]), "=r"(r[1]) : "r"(a));
}
// bf16 mma (attention)
__device__ __forceinline__ void mma16816(float* d, const uint32_t* a, const uint32_t* b) {
    asm volatile("mma.sync.aligned.m16n8k16.row.col.f32.bf16.bf16.f32 "
        "{%0,%1,%2,%3}, {%4,%5,%6,%7}, {%8,%9}, {%0,%1,%2,%3};"
        : "+f"(d[0]), "+f"(d[1]), "+f"(d[2]), "+f"(d[3])
        : "r"(a[0]), "r"(a[1]), "r"(a[2]), "r"(a[3]), "r"(b[0]), "r"(b[1]));
}
// fp16 mma (GEMMs)
__device__ __forceinline__ void mma16816f(float* d, const uint32_t* a, const uint32_t* b) {
    asm volatile("mma.sync.aligned.m16n8k16.row.col.f32.f16.f16.f32 "
        "{%0,%1,%2,%3}, {%4,%5,%6,%7}, {%8,%9}, {%0,%1,%2,%3};"
        : "+f"(d[0]), "+f"(d[1]), "+f"(d[2]), "+f"(d[3])
        : "r"(a[0]), "r"(a[1]), "r"(a[2]), "r"(a[3]), "r"(b[0]), "r"(b[1]));
}
__device__ __forceinline__ void cpa16(uint32_t d, const void* s) {
    asm volatile("cp.async.cg.shared.global [%0], [%1], 16;" :: "r"(d), "l"(s));
}
__device__ __forceinline__ void cpa16z(uint32_t d, const void* s, int sz) {
    asm volatile("cp.async.cg.shared.global [%0], [%1], 16, %2;" :: "r"(d), "l"(s), "r"(sz));
}
#define CPA_COMMIT() asm volatile("cp.async.commit_group;" ::: "memory")
#define CPA_WAIT1()  asm volatile("cp.async.wait_group 1;" ::: "memory")
#define CPA_WAIT0()  asm volatile("cp.async.wait_group 0;" ::: "memory")

__device__ __forceinline__ uint32_t packbf(float lo, float hi) {
    uint32_t r;
    asm("cvt.rn.bf16x2.f32 %0, %1, %2;" : "=r"(r) : "f"(hi), "f"(lo));
    return r;
}

// ---------------- BN fold ----------------
__global__ void fold_bn_kernel(const float* __restrict__ cv1, const float* __restrict__ cv2,
                               const float* __restrict__ mcv1, const float* __restrict__ mcv2)
{
    int c = blockIdx.x * 256 + threadIdx.x;
    if (c >= 2048) return;
    const float* p; int C, lc;
    if (c < 512)        { p = cv1;  C = 512; lc = c; }
    else if (c < 1024)  { p = cv2;  C = 512; lc = c - 512; }
    else if (c < 1536)  { int i = (c - 1024) >> 8; p = mcv1 + i * 1024; C = 256; lc = (c - 1024) & 255; }
    else                { int i = (c - 1536) >> 8; p = mcv2 + i * 1024; C = 256; lc = (c - 1536) & 255; }
    float g = p[lc], b = p[C + lc], m = p[2 * C + lc], v = p[3 * C + lc];
    float s = g / sqrtf(v + 1e-3f);
    g_scale[c] = s;
    g_bias[c]  = b - m * s;
}

// ---------------- weight converter: fp32 -> fp16 hi/lo ----------------
__global__ void convW_kernel(const float* __restrict__ W, int M, int K, int isConv,
                             uint16_t* __restrict__ Whi, uint16_t* __restrict__ Wlo)
{
    long e = (long)blockIdx.x * 256 + threadIdx.x;
    if (e >= (long)M * K) return;
    long m = e / K, k = e % K;
    float v;
    if (isConv) { int off = (int)(k >> 8), ci = (int)(k & 255); v = W[m * 2304 + ci * 9 + off]; }
    else v = W[e];
    __half h = __float2half(v);
    __half l = __float2half(v - __half2float(h));
    Whi[e] = __half_as_ushort(h);
    Wlo[e] = __half_as_ushort(l);
}

// ---------------- activation transposer: [b][K][HW] (T) -> fp16 [b][n][K] ----------------
template <typename T>
__global__ void convB_kernel(const T* __restrict__ In, long inStride, int K,
                             uint16_t* __restrict__ Bhi)
{
    __shared__ float t[32][33];
    int n0 = blockIdx.x * 32, k0 = blockIdx.y * 32, b = blockIdx.z;
    int tx = threadIdx.x, ty = threadIdx.y;
    const T* in = In + (long)b * inStride;
#pragma unroll
    for (int yy = 0; yy < 32; yy += 8)
        t[yy + ty][tx] = (float)in[(long)(k0 + yy + ty) * HW + n0 + tx];
    __syncthreads();
#pragma unroll
    for (int yy = 0; yy < 32; yy += 8) {
        int n = n0 + yy + ty, k = k0 + tx;
        float v = t[tx][yy + ty];
        long o = ((long)b * 1024 + n) * K + k;
        Bhi[o] = __half_as_ushort(__float2half(v));
    }
}

// ---------------- warp-MMA GEMM (N-tile 128): fp16 split-2, K-chunk 64, 2-stage ----------------
#define MG_STAGE 49152
#define MG_SMEM  98304

__device__ __forceinline__ void mg_load(uint32_t smb, int tid,
    const uint4* __restrict__ wHi, const uint4* __restrict__ wLo,
    const uint4* __restrict__ bHi,
    int m0, int n0, int K16, int c, uint32_t stOff)
{
    uint32_t sb = smb + stOff;
#pragma unroll
    for (int l = 0; l < 4; l++) {
        int e = tid + l * 256;
        int r = e >> 3, j = e & 7;
        uint32_t off = SWZ128((uint32_t)(r * 128 + j * 16));
        cpa16(sb + off,         wHi + (long)(m0 + r) * K16 + c * 8 + j);
        cpa16(sb + 16384 + off, wLo + (long)(m0 + r) * K16 + c * 8 + j);
        cpa16(sb + 32768 + off, bHi + (long)(n0 + r) * K16 + c * 8 + j);
    }
}

extern __shared__ char mg_smem[];

__global__ void __launch_bounds__(256, 2) mgemm_kernel(
    const uint16_t* __restrict__ Bhi,
    const uint16_t* __restrict__ Whi, const uint16_t* __restrict__ Wlo,
    int K,
    float* __restrict__ Out, uint16_t* __restrict__ OutH, long outStride,
    const float* __restrict__ scale, const float* __restrict__ bias,
    const float* __restrict__ Res, long resStride,
    int doSilu)
{
    int b = blockIdx.z, m0 = blockIdx.y * 128, n0 = blockIdx.x * 128;
    int tid = threadIdx.x, wid = tid >> 5, lane = tid & 31;
    int warp_m = wid & 1, warp_n = wid >> 1;
    uint32_t smb = smem_u32(mg_smem);

    int K16 = K >> 3;
    const uint4* wHi = (const uint4*)Whi;
    const uint4* wLo = (const uint4*)Wlo;
    const uint4* bHi = (const uint4*)(Bhi + (long)b * 1024 * K);

    float acc[4][4][4];
#pragma unroll
    for (int i = 0; i < 4; i++)
#pragma unroll
        for (int j = 0; j < 4; j++)
#pragma unroll
            for (int r = 0; r < 4; r++) acc[i][j][r] = 0.f;

    int nChunks = K >> 6;
    mg_load(smb, tid, wHi, wLo, bHi, m0, n0, K16, 0, 0);
    CPA_COMMIT();

    int aRowL = warp_m * 64 + (lane & 7) + (lane & 8);
    int aColL = ((lane >> 4) & 1) * 16;
    int bRowX4 = warp_n * 32 + (lane >> 4) * 8 + (lane & 7);  // + p*16
    uint32_t bColX4 = (uint32_t)(((lane >> 3) & 1) * 16);

    for (int c = 0; c < nChunks; c++) {
        int s = c & 1;
        CPA_WAIT0();
        __syncthreads();
        if (c + 1 < nChunks) {
            mg_load(smb, tid, wHi, wLo, bHi, m0, n0, K16, c + 1, (uint32_t)((s ^ 1) * MG_STAGE));
            CPA_COMMIT();
        }

        uint32_t base = smb + (uint32_t)(s * MG_STAGE);
#pragma unroll
        for (int ks = 0; ks < 4; ks++) {
            uint32_t ah[4][4], bh4[2][4];
#pragma unroll
            for (int mt = 0; mt < 4; mt++)
                ldsm_x4(ah[mt], base + SWZ128((uint32_t)((aRowL + mt * 16) * 128 + aColL + ks * 32)));
#pragma unroll
            for (int p = 0; p < 2; p++)
                ldsm_x4(bh4[p], base + 32768 + SWZ128((uint32_t)((bRowX4 + p * 16) * 128 + bColX4 + ks * 32)));
#pragma unroll
            for (int mt = 0; mt < 4; mt++)
#pragma unroll
                for (int p = 0; p < 2; p++) {
                    mma16816f(acc[mt][2 * p],     ah[mt], &bh4[p][0]);
                    mma16816f(acc[mt][2 * p + 1], ah[mt], &bh4[p][2]);
                }

            uint32_t al[4][4];
#pragma unroll
            for (int mt = 0; mt < 4; mt++)
                ldsm_x4(al[mt], base + 16384 + SWZ128((uint32_t)((aRowL + mt * 16) * 128 + aColL + ks * 32)));
#pragma unroll
            for (int mt = 0; mt < 4; mt++)
#pragma unroll
                for (int p = 0; p < 2; p++) {
                    mma16816f(acc[mt][2 * p],     al[mt], &bh4[p][0]);
                    mma16816f(acc[mt][2 * p + 1], al[mt], &bh4[p][2]);
                }
        }
    }

#pragma unroll
    for (int mt = 0; mt < 4; mt++) {
        int mb = m0 + warp_m * 64 + mt * 16 + (lane >> 2);
#pragma unroll
        for (int h2 = 0; h2 < 2; h2++) {
            int m = mb + h2 * 8;
            float s = 1.f, bb = 0.f;
            if (scale) { s = scale[m]; bb = bias[m]; }
            long rowOff = (long)b * outStride + (long)m * HW;
            long resOff = Res ? ((long)b * resStride + (long)m * HW) : 0;
#pragma unroll
            for (int nt = 0; nt < 4; nt++) {
                int n = n0 + warp_n * 32 + nt * 8 + (lane & 3) * 2;
                float v0 = acc[mt][nt][h2 * 2 + 0] * s + bb;
                float v1 = acc[mt][nt][h2 * 2 + 1] * s + bb;
                if (doSilu) { v0 = silu_f(v0); v1 = silu_f(v1); }
                if (Res) {
                    float2 r2 = *(const float2*)&Res[resOff + n];
                    v0 += r2.x; v1 += r2.y;
                }
                if (Out) *(float2*)&Out[rowOff + n] = make_float2(v0, v1);
                if (OutH) {
                    __half2 hv = __floats2half2_rn(v0, v1);
                    *(__half2*)&OutH[rowOff + n] = hv;
                }
            }
        }
    }
}

// ---------------- warp-MMA GEMM (N-tile 64): fp16 split-2; generic or implicit-conv B ----------------
#define MG64_STAGE 20480
#define MG64_SMEM  40960

__device__ __forceinline__ void mg64_load(uint32_t smb, int tid,
    const uint4* __restrict__ wHi, const uint4* __restrict__ wLo,
    const uint4* __restrict__ bHi,
    int m0, int n0, int K16, int c, uint32_t stOff)
{
    uint32_t sb = smb + stOff;
    int r = tid >> 1, j = (tid & 1) * 2;
    uint32_t o0 = SWZ64((uint32_t)(r * 64 + j * 16));
    uint32_t o1 = SWZ64((uint32_t)(r * 64 + (j + 1) * 16));
    const uint4* a;
    a = wHi + (long)(m0 + r) * K16 + c * 4 + j;
    cpa16(sb + o0, a); cpa16(sb + o1, a + 1);
    a = wLo + (long)(m0 + r) * K16 + c * 4 + j;
    cpa16(sb + 8192 + o0, a); cpa16(sb + 8192 + o1, a + 1);
    int rb = tid >> 2, jb = tid & 3;
    uint32_t ob = SWZ64((uint32_t)(rb * 64 + jb * 16));
    a = bHi + (long)(n0 + rb) * K16 + c * 4 + jb;
    cpa16(sb + 16384 + ob, a);
}

// implicit 3x3 conv B loader: B is yi in fp16 [n][256]; chunk c -> tap (c>>3), ci-block (c&7)
__device__ __forceinline__ void mgc_load(uint32_t smb, int tid,
    const uint4* __restrict__ wHi, const uint4* __restrict__ wLo,
    const uint4* __restrict__ bHi,
    int m0, int n0, int K16, int c, uint32_t stOff)
{
    uint32_t sb = smb + stOff;
    int r = tid >> 1, j = (tid & 1) * 2;
    uint32_t o0 = SWZ64((uint32_t)(r * 64 + j * 16));
    uint32_t o1 = SWZ64((uint32_t)(r * 64 + (j + 1) * 16));
    const uint4* a;
    a = wHi + (long)(m0 + r) * K16 + c * 4 + j;
    cpa16(sb + o0, a); cpa16(sb + o1, a + 1);
    a = wLo + (long)(m0 + r) * K16 + c * 4 + j;
    cpa16(sb + 8192 + o0, a); cpa16(sb + 8192 + o1, a + 1);

    int off = c >> 3, cik = c & 7;
    int dy = off / 3 - 1, dx = off % 3 - 1;
    int rb = tid >> 2, jb = tid & 3;
    int pix = n0 + rb;
    int y = (pix >> 5) + dy, x = (pix & 31) + dx;
    bool ok = ((unsigned)y < 32u) && ((unsigned)x < 32u);
    int ps = ok ? (y * 32 + x) : 0;
    int sz = ok ? 16 : 0;
    uint32_t ob = SWZ64((uint32_t)(rb * 64 + jb * 16));
    cpa16z(sb + 16384 + ob, bHi + (long)ps * 32 + cik * 4 + jb, sz);
}

template <int CONV>
__global__ void __launch_bounds__(256, 2) mgemm64_kernel_t(
    const uint16_t* __restrict__ Bhi,
    const uint16_t* __restrict__ Whi, const uint16_t* __restrict__ Wlo,
    int K, int bK,
    float* __restrict__ Out, uint16_t* __restrict__ OutH, long outStride,
    const float* __restrict__ scale, const float* __restrict__ bias,
    const float* __restrict__ Res, long resStride,
    int doSilu)
{
    int b = blockIdx.z, m0 = blockIdx.y * 128, n0 = blockIdx.x * 64;
    int tid = threadIdx.x, wid = tid >> 5, lane = tid & 31;
    int warp_m = wid & 3, warp_n = wid >> 2;
    uint32_t smb = smem_u32(mg_smem);

    int K16 = K >> 3;
    const uint4* wHi = (const uint4*)Whi;
    const uint4* wLo = (const uint4*)Wlo;
    const uint4* bHi = (const uint4*)(Bhi + (long)b * 1024 * bK);

    float acc[2][4][4];
#pragma unroll
    for (int i = 0; i < 2; i++)
#pragma unroll
        for (int j = 0; j < 4; j++)
#pragma unroll
            for (int r = 0; r < 4; r++) acc[i][j][r] = 0.f;

    int nChunks = K >> 5;
    if (CONV) mgc_load(smb, tid, wHi, wLo, bHi, m0, n0, K16, 0, 0);
    else      mg64_load(smb, tid, wHi, wLo, bHi, m0, n0, K16, 0, 0);
    CPA_COMMIT();

    int aRowL = warp_m * 32 + (lane & 7) + (lane & 8);
    int aColL = ((lane >> 4) & 1) * 16;
    int bRowX4 = warp_n * 32 + (lane >> 4) * 8 + (lane & 7);  // + p*16
    uint32_t bColX4 = (uint32_t)(((lane >> 3) & 1) * 16);

    for (int c = 0; c < nChunks; c++) {
        int s = c & 1;
        if (c + 1 < nChunks) {
            if (CONV) mgc_load(smb, tid, wHi, wLo, bHi, m0, n0, K16, c + 1, (uint32_t)((s ^ 1) * MG64_STAGE));
            else      mg64_load(smb, tid, wHi, wLo, bHi, m0, n0, K16, c + 1, (uint32_t)((s ^ 1) * MG64_STAGE));
            CPA_COMMIT();
            CPA_WAIT1();
        } else {
            CPA_WAIT0();
        }
        __syncthreads();

        uint32_t base = smb + s * MG64_STAGE;
#pragma unroll
        for (int ks = 0; ks < 2; ks++) {
            uint32_t ah[2][4], bh4[2][4];
#pragma unroll
            for (int mt = 0; mt < 2; mt++)
                ldsm_x4(ah[mt], base + SWZ64((uint32_t)((aRowL + mt * 16) * 64 + aColL + ks * 32)));
#pragma unroll
            for (int p = 0; p < 2; p++)
                ldsm_x4(bh4[p], base + 16384 + SWZ64((uint32_t)((bRowX4 + p * 16) * 64 + bColX4 + ks * 32)));
#pragma unroll
            for (int mt = 0; mt < 2; mt++)
#pragma unroll
                for (int p = 0; p < 2; p++) {
                    mma16816f(acc[mt][2 * p],     ah[mt], &bh4[p][0]);
                    mma16816f(acc[mt][2 * p + 1], ah[mt], &bh4[p][2]);
                }

            uint32_t al[2][4];
#pragma unroll
            for (int mt = 0; mt < 2; mt++)
                ldsm_x4(al[mt], base + 8192 + SWZ64((uint32_t)((aRowL + mt * 16) * 64 + aColL + ks * 32)));
#pragma unroll
            for (int mt = 0; mt < 2; mt++)
#pragma unroll
                for (int p = 0; p < 2; p++) {
                    mma16816f(acc[mt][2 * p],     al[mt], &bh4[p][0]);
                    mma16816f(acc[mt][2 * p + 1], al[mt], &bh4[p][2]);
                }
        }
        __syncthreads();
    }

#pragma unroll
    for (int mt = 0; mt < 2; mt++) {
        int mb = m0 + warp_m * 32 + mt * 16 + (lane >> 2);
#pragma unroll
        for (int h2 = 0; h2 < 2; h2++) {
            int m = mb + h2 * 8;
            float s = 1.f, bb = 0.f;
            if (scale) { s = scale[m]; bb = bias[m]; }
            long rowOff = (long)b * outStride + (long)m * HW;
            long resOff = Res ? ((long)b * resStride + (long)m * HW) : 0;
#pragma unroll
            for (int nt = 0; nt < 4; nt++) {
                int n = n0 + warp_n * 32 + nt * 8 + (lane & 3) * 2;
                float v0 = acc[mt][nt][h2 * 2 + 0] * s + bb;
                float v1 = acc[mt][nt][h2 * 2 + 1] * s + bb;
                if (doSilu) { v0 = silu_f(v0); v1 = silu_f(v1); }
                if (Res) {
                    float2 r2 = *(const float2*)&Res[resOff + n];
                    v0 += r2.x; v1 += r2.y;
                }
                if (Out) *(float2*)&Out[rowOff + n] = make_float2(v0, v1);
                if (OutH) {
                    __half2 hv = __floats2half2_rn(v0, v1);
                    *(__half2*)&OutH[rowOff + n] = hv;
                }
            }
        }
    }
}

// ---------------- attention converter: qkv fp16 -> qT/kT(+relpos)/v bf16 hi/lo ----------------
__global__ void convAttn_kernel(const uint16_t* __restrict__ QKVH,
                                const float* __restrict__ RW, const float* __restrict__ RH,
                                __nv_bfloat16* __restrict__ Hi, __nv_bfloat16* __restrict__ Lo)
{
    __shared__ float tq[32][33], tk[32][33];
    int it = blockIdx.x, dt = blockIdx.y, bh = blockIdx.z;
    int b = bh >> 2, hh = bh & 3;
    int tx = threadIdx.x, ty = threadIdx.y;
    const __half* base = (const __half*)QKVH + (long)b * 768 * HW;
#pragma unroll
    for (int l = 0; l < 4; l++) {
        int d = dt * 32 + ty + l * 8;
        int ch = hh * 64 + d;
        float qv = __half2float(base[(long)ch * HW + it * 32 + tx]) * 0.125f;
        float kv = __half2float(base[(long)(256 + ch) * HW + it * 32 + tx]) + RW[ch * 32 + tx] + RH[ch * 32 + it];
        float vv = __half2float(base[(long)(512 + ch) * HW + it * 32 + tx]);
        tq[ty + l * 8][tx] = qv;
        tk[ty + l * 8][tx] = kv;
        long vo = V_OFF + ((long)bh * 64 + d) * 1024 + it * 32 + tx;
        __nv_bfloat16 vh = __float2bfloat16(vv);
        Hi[vo] = vh;
        Lo[vo] = __float2bfloat16(vv - __bfloat162float(vh));
    }
    __syncthreads();
#pragma unroll
    for (int l = 0; l < 4; l++) {
        int i = it * 32 + ty + l * 8;
        int d = dt * 32 + tx;
        float qv = tq[tx][ty + l * 8];
        float kv = tk[tx][ty + l * 8];
        long qo = ((long)bh * 1024 + i) * 64 + d;
        __nv_bfloat16 qh = __float2bfloat16(qv);
        Hi[QT_OFF + qo] = qh;
        Lo[QT_OFF + qo] = __float2bfloat16(qv - __bfloat162float(qh));
        __nv_bfloat16 kh = __float2bfloat16(kv);
        Hi[KT_OFF + qo] = kh;
        Lo[KT_OFF + qo] = __float2bfloat16(kv - __bfloat162float(kh));
    }
}

// ---------------- MMA flash attention (bf16 split-3) ----------------
#define AT_SMEM 163840

__device__ __forceinline__ void kv_load(uint32_t smb, int tid,
    const __nv_bfloat16* __restrict__ kTh, const __nv_bfloat16* __restrict__ kTl,
    const __nv_bfloat16* __restrict__ vH, const __nv_bfloat16* __restrict__ vL,
    int bh, int t, uint32_t stOff)
{
    uint32_t kb = smb + stOff;
    const uint4* kh4 = (const uint4*)(kTh + ((long)bh * 1024 + t * 128) * 64);
    const uint4* kl4 = (const uint4*)(kTl + ((long)bh * 1024 + t * 128) * 64);
    int r = tid >> 1, j0 = (tid & 1) * 4;
#pragma unroll
    for (int j = 0; j < 4; j++) {
        uint32_t off = SWZ128((uint32_t)(r * 128 + (j0 + j) * 16));
        cpa16(kb + off, kh4 + (long)r * 8 + j0 + j);
        cpa16(kb + 16384 + off, kl4 + (long)r * 8 + j0 + j);
    }
    const uint4* vh4 = (const uint4*)(vH + (long)bh * 65536 + t * 128);
    const uint4* vl4 = (const uint4*)(vL + (long)bh * 65536 + t * 128);
    int d = tid >> 2, jc0 = (tid & 3) * 4;
#pragma unroll
    for (int j = 0; j < 4; j++) {
        int jc = jc0 + j;
        uint32_t off = (uint32_t)((jc >> 3) * 8192) + SWZ128((uint32_t)(d * 128 + (jc & 7) * 16));
        cpa16(kb + 32768 + off, vh4 + (long)d * 128 + jc);
        cpa16(kb + 49152 + off, vl4 + (long)d * 128 + jc);
    }
}

extern __shared__ char at_smem[];

__global__ void __launch_bounds__(256) attn_mma_kernel(
    const __nv_bfloat16* __restrict__ Hi, const __nv_bfloat16* __restrict__ Lo,
    uint16_t* __restrict__ OutpH)
{
    int qt = blockIdx.x, h = blockIdx.y, b = blockIdx.z;
    int bh = b * 4 + h;
    int tid = threadIdx.x, wid = tid >> 5, lane = tid & 31, li = lane & 15;
    uint32_t smb = smem_u32(at_smem);

    const __nv_bfloat16* qTh = Hi + QT_OFF;
    const __nv_bfloat16* qTl = Lo + QT_OFF;
    const __nv_bfloat16* kTh = Hi + KT_OFF;
    const __nv_bfloat16* kTl = Lo + KT_OFF;
    const __nv_bfloat16* vH  = Hi + V_OFF;
    const __nv_bfloat16* vL  = Lo + V_OFF;

    {
        const uint4* qh4 = (const uint4*)(qTh + ((long)bh * 1024 + qt * 128) * 64);
        const uint4* ql4 = (const uint4*)(qTl + ((long)bh * 1024 + qt * 128) * 64);
        int r = tid >> 1, j0 = (tid & 1) * 4;
        uint32_t qb = smb + 131072;
#pragma unroll
        for (int j = 0; j < 4; j++) {
            uint32_t off = SWZ128((uint32_t)(r * 128 + (j0 + j) * 16));
            cpa16(qb + off, qh4 + (long)r * 8 + j0 + j);
            cpa16(qb + 16384 + off, ql4 + (long)r * 8 + j0 + j);
        }
    }
    CPA_COMMIT();
    kv_load(smb, tid, kTh, kTl, vH, vL, bh, 0, 0);
    CPA_COMMIT();
    CPA_WAIT1();
    __syncthreads();

    uint32_t qfh[4][4], qfl[4][4];
    {
        int aRow = wid * 16 + (lane & 7) + (lane & 8);
        int aCol = ((lane >> 4) & 1) * 16;
#pragma unroll
        for (int ks = 0; ks < 4; ks++) {
            uint32_t off = SWZ128((uint32_t)(aRow * 128 + aCol + ks * 32));
            ldsm_x4(qfh[ks], smb + 131072 + off);
            ldsm_x4(qfl[ks], smb + 131072 + 16384 + off);
        }
    }

    float oacc[8][4];
#pragma unroll
    for (int i = 0; i < 8; i++)
#pragma unroll
        for (int j = 0; j < 4; j++) oacc[i][j] = 0.f;
    float m0 = -1e30f, m1 = -1e30f, l0 = 0.f, l1 = 0.f;

    int sRowX4 = (lane >> 4) * 8 + (lane & 7);
    uint32_t sColX4 = (uint32_t)(((lane >> 3) & 1) * 16);

    for (int t = 0; t < 8; t++) {
        int s = t & 1;
        if (t < 7) {
            kv_load(smb, tid, kTh, kTl, vH, vL, bh, t + 1, (uint32_t)((s ^ 1) * 65536));
            CPA_COMMIT();
            CPA_WAIT1();
        } else {
            CPA_WAIT0();
        }
        __syncthreads();

        uint32_t kb = smb + s * 65536;
        float sacc[16][4];
#pragma unroll
        for (int i = 0; i < 16; i++)
#pragma unroll
            for (int j = 0; j < 4; j++) sacc[i][j] = 0.f;

#pragma unroll
        for (int p = 0; p < 8; p++) {
            int rowB = p * 16 + sRowX4;
#pragma unroll
            for (int ks = 0; ks < 4; ks++) {
                uint32_t off = SWZ128((uint32_t)(rowB * 128 + sColX4 + ks * 32));
                uint32_t kh4[4], kl4[4];
                ldsm_x4(kh4, kb + off);
                ldsm_x4(kl4, kb + 16384 + off);
                mma16816(sacc[2 * p],     qfh[ks], &kh4[0]);
                mma16816(sacc[2 * p + 1], qfh[ks], &kh4[2]);
                mma16816(sacc[2 * p],     qfl[ks], &kh4[0]);
                mma16816(sacc[2 * p + 1], qfl[ks], &kh4[2]);
                mma16816(sacc[2 * p],     qfh[ks], &kl4[0]);
                mma16816(sacc[2 * p + 1], qfh[ks], &kl4[2]);
            }
        }

        float mx0 = m0, mx1 = m1;
#pragma unroll
        for (int nt = 0; nt < 16; nt++) {
            mx0 = fmaxf(mx0, fmaxf(sacc[nt][0], sacc[nt][1]));
            mx1 = fmaxf(mx1, fmaxf(sacc[nt][2], sacc[nt][3]));
        }
        mx0 = fmaxf(mx0, __shfl_xor_sync(0xffffffffu, mx0, 1));
        mx0 = fmaxf(mx0, __shfl_xor_sync(0xffffffffu, mx0, 2));
        mx1 = fmaxf(mx1, __shfl_xor_sync(0xffffffffu, mx1, 1));
        mx1 = fmaxf(mx1, __shfl_xor_sync(0xffffffffu, mx1, 2));
        float a0 = __expf(m0 - mx0), a1 = __expf(m1 - mx1);
        m0 = mx0; m1 = mx1;

        float ls0 = 0.f, ls1 = 0.f;
        uint32_t pah[8][4], pal[8][4];
#pragma unroll
        for (int kj = 0; kj < 8; kj++) {
            float p00 = __expf(sacc[2 * kj][0] - m0);
            float p01 = __expf(sacc[2 * kj][1] - m0);
            float p02 = __expf(sacc[2 * kj][2] - m1);
            float p03 = __expf(sacc[2 * kj][3] - m1);
            float p10 = __expf(sacc[2 * kj + 1][0] - m0);
            float p11 = __expf(sacc[2 * kj + 1][1] - m0);
            float p12 = __expf(sacc[2 * kj + 1][2] - m1);
            float p13 = __expf(sacc[2 * kj + 1][3] - m1);
            ls0 += p00 + p01 + p10 + p11;
            ls1 += p02 + p03 + p12 + p13;
            pah[kj][0] = packbf(p00, p01);
            pah[kj][1] = packbf(p02, p03);
            pah[kj][2] = packbf(p10, p11);
            pah[kj][3] = packbf(p12, p13);
            float q00 = p00 - __bfloat162float(__float2bfloat16(p00));
            float q01 = p01 - __bfloat162float(__float2bfloat16(p01));
            float q02 = p02 - __bfloat162float(__float2bfloat16(p02));
            float q03 = p03 - __bfloat162float(__float2bfloat16(p03));
            float q10 = p10 - __bfloat162float(__float2bfloat16(p10));
            float q11 = p11 - __bfloat162float(__float2bfloat16(p11));
            float q12 = p12 - __bfloat162float(__float2bfloat16(p12));
            float q13 = p13 - __bfloat162float(__float2bfloat16(p13));
            pal[kj][0] = packbf(q00, q01);
            pal[kj][1] = packbf(q02, q03);
            pal[kj][2] = packbf(q10, q11);
            pal[kj][3] = packbf(q12, q13);
        }
        ls0 += __shfl_xor_sync(0xffffffffu, ls0, 1);
        ls0 += __shfl_xor_sync(0xffffffffu, ls0, 2);
        ls1 += __shfl_xor_sync(0xffffffffu, ls1, 1);
        ls1 += __shfl_xor_sync(0xffffffffu, ls1, 2);
        l0 = l0 * a0 + ls0;
        l1 = l1 * a1 + ls1;
#pragma unroll
        for (int dt = 0; dt < 8; dt++) {
            oacc[dt][0] *= a0; oacc[dt][1] *= a0;
            oacc[dt][2] *= a1; oacc[dt][3] *= a1;
        }

#pragma unroll
        for (int dt = 0; dt < 8; dt++) {
            int rowV = dt * 8 + (li & 7);
#pragma unroll
            for (int kj = 0; kj < 8; kj++) {
                uint32_t off = (uint32_t)((kj >> 2) * 8192) +
                               SWZ128((uint32_t)(rowV * 128 + (li >> 3) * 16 + (kj & 3) * 32));
                uint32_t vh2[2], vl2[2];
                ldsm_x2(vh2, kb + 32768 + off);
                ldsm_x2(vl2, kb + 49152 + off);
                mma16816(oacc[dt], pah[kj], vh2);
                mma16816(oacc[dt], pal[kj], vh2);
                mma16816(oacc[dt], pah[kj], vl2);
            }
        }
        __syncthreads();
    }

    float i0 = 1.f / l0, i1 = 1.f / l1;
    float* stg = (float*)at_smem;   // [128][66]
    int r0 = wid * 16 + (lane >> 2);
#pragma unroll
    for (int dt = 0; dt < 8; dt++) {
        int d = dt * 8 + (lane & 3) * 2;
        stg[r0 * 66 + d]           = oacc[dt][0] * i0;
        stg[r0 * 66 + d + 1]       = oacc[dt][1] * i0;
        stg[(r0 + 8) * 66 + d]     = oacc[dt][2] * i1;
        stg[(r0 + 8) * 66 + d + 1] = oacc[dt][3] * i1;
    }
    __syncthreads();
    for (int e = tid; e < 8192; e += 256) {
        int d = e >> 7, i = e & 127;
        OutpH[((long)b * 256 + h * 64 + d) * HW + qt * 128 + i] =
            __half_as_ushort(__float2half(stg[i * 66 + d]));
    }
}

// ---------------- launch ----------------
extern "C" void kernel_launch(void* const* d_in, const int* in_sizes, int n_in,
                              void* d_out, int out_size)
{
    const float* x      = (const float*)d_in[0];
    const float* cv1_w  = (const float*)d_in[1];
    const float* cv1_bn = (const float*)d_in[2];
    const float* cv2_w  = (const float*)d_in[3];
    const float* cv2_bn = (const float*)d_in[4];
    const float* mcv1w  = (const float*)d_in[5];
    const float* mcv1bn = (const float*)d_in[6];
    const float* mqkvw  = (const float*)d_in[7];
    const float* mrw    = (const float*)d_in[8];
    const float* mrh    = (const float*)d_in[9];
    const float* mcv2w  = (const float*)d_in[10];
    const float* mcv2bn = (const float*)d_in[11];
    float* out = (float*)d_out;

    float *cat, *scl, *bia;
    uint16_t *catH, *zH, *qkvH, *attoH, *whi, *wlo, *bhi, *blo;
    cudaGetSymbolAddress((void**)&cat,   g_cat);
    cudaGetSymbolAddress((void**)&catH,  g_catH);
    cudaGetSymbolAddress((void**)&zH,    g_zH);
    cudaGetSymbolAddress((void**)&qkvH,  g_qkvH);
    cudaGetSymbolAddress((void**)&attoH, g_attoH);
    cudaGetSymbolAddress((void**)&scl,   g_scale);
    cudaGetSymbolAddress((void**)&bia,   g_bias);
    cudaGetSymbolAddress((void**)&whi,   g_Whi);
    cudaGetSymbolAddress((void**)&wlo,   g_Wlo);
    cudaGetSymbolAddress((void**)&bhi,   g_Bhi);
    cudaGetSymbolAddress((void**)&blo,   g_Blo);
    __nv_bfloat16* bhiB = (__nv_bfloat16*)bhi;
    __nv_bfloat16* bloB = (__nv_bfloat16*)blo;

    cudaFuncSetAttribute(mgemm_kernel, cudaFuncAttributeMaxDynamicSharedMemorySize, MG_SMEM);
    cudaFuncSetAttribute(mgemm64_kernel_t<0>, cudaFuncAttributeMaxDynamicSharedMemorySize, MG64_SMEM);
    cudaFuncSetAttribute(mgemm64_kernel_t<1>, cudaFuncAttributeMaxDynamicSharedMemorySize, MG64_SMEM);
    cudaFuncSetAttribute(attn_mma_kernel, cudaFuncAttributeMaxDynamicSharedMemorySize, AT_SMEM);

    fold_bn_kernel<<<8, 256>>>(cv1_bn, cv2_bn, mcv1bn, mcv2bn);

    // ---- cv1: 512 -> 512, BN+SiLU -> fp32 cat[0:512) + fp16 catH[0:512) ----
    convW_kernel<<<(512 * 512 + 255) / 256, 256>>>(cv1_w, 512, 512, 0, whi, wlo);
    convB_kernel<float><<<dim3(32, 16, 8), dim3(32, 8)>>>(x, (long)512 * HW, 512, bhi);
    mgemm_kernel<<<dim3(8, 4, 8), 256, MG_SMEM>>>(
        bhi, whi, wlo, 512, cat, catH, (long)1024 * HW,
        scl + 0, bia + 0, nullptr, 0, 1);

    for (int i = 0; i < 2; i++) {
        long yin  = (long)(i == 0 ? 256 : 512) * HW;
        long yout = (long)(512 + i * 256) * HW;

        // z = cbs(yi, 3x3) as IMPLICIT GEMM from catH fp16; output fp16 zH only
        convW_kernel<<<(256 * 2304 + 255) / 256, 256>>>(
            mcv1w + (long)i * 256 * 2304, 256, 2304, 1, whi, wlo);
        convB_kernel<__half><<<dim3(32, 8, 8), dim3(32, 8)>>>(
            (const __half*)(catH + yin), (long)1024 * HW, 256, bhi);
        mgemm64_kernel_t<1><<<dim3(16, 2, 8), 256, MG64_SMEM>>>(
            bhi, whi, wlo, 2304, 256, nullptr, zH, (long)256 * HW,
            scl + 1024 + i * 256, bia + 1024 + i * 256, nullptr, 0, 1);

        // qkv = conv1x1(z), 256 -> 768; output fp16 qkvH only
        convW_kernel<<<(768 * 256 + 255) / 256, 256>>>(
            mqkvw + (long)i * 768 * 256, 768, 256, 0, whi, wlo);
        convB_kernel<__half><<<dim3(32, 8, 8), dim3(32, 8)>>>(
            (const __half*)zH, (long)256 * HW, 256, bhi);
        mgemm_kernel<<<dim3(8, 6, 8), 256, MG_SMEM>>>(
            bhi, whi, wlo, 256, nullptr, qkvH, (long)768 * HW,
            nullptr, nullptr, nullptr, 0, 0);

        // attention operand conversion (bf16 split-3) + MMA flash attention -> fp16 attoH
        convAttn_kernel<<<dim3(32, 2, 32), dim3(32, 8)>>>(
            qkvH, mrw + (long)i * 8192, mrh + (long)i * 8192, bhiB, bloB);
        attn_mma_kernel<<<dim3(8, 4, 8), 256, AT_SMEM>>>(bhiB, bloB, attoH);

        // y_{i+2} = yi + silu(bn(conv1x1(atto))) -> fp32 cat slice + fp16 catH slice
        convW_kernel<<<(256 * 256 + 255) / 256, 256>>>(
            mcv2w + (long)i * 256 * 256, 256, 256, 0, whi, wlo);
        convB_kernel<__half><<<dim3(32, 8, 8), dim3(32, 8)>>>(
            (const __half*)attoH, (long)256 * HW, 256, bhi);
        mgemm64_kernel_t<0><<<dim3(16, 2, 8), 256, MG64_SMEM>>>(
            bhi, whi, wlo, 256, 256, cat + yout, catH + yout, (long)1024 * HW,
            scl + 1536 + i * 256, bia + 1536 + i * 256, cat + yin, (long)1024 * HW, 1);
    }

    // ---- final: 1024 -> 512, BN+SiLU, fp32 out only ----
    convW_kernel<<<(512 * 1024 + 255) / 256, 256>>>(cv2_w, 512, 1024, 0, whi, wlo);
    convB_kernel<__half><<<dim3(32, 32, 8), dim3(32, 8)>>>(
        (const __half*)catH, (long)1024 * HW, 1024, bhi);
    mgemm_kernel<<<dim3(8, 4, 8), 256, MG_SMEM>>>(
        bhi, whi, wlo, 1024, out, nullptr, (long)512 * HW,
        scl + 512, bia + 512, nullptr, 0, 1);
}

// round 11
// speedup vs baseline: 1.6035x; 1.1116x over previous
#include <cuda_runtime.h>
#include <cuda_bf16.h>
#include <cuda_fp16.h>
#include <cstdint>

#define HW 1024

// ---------------- scratch (__device__ globals: alloc-guard-safe) ----------------
__device__ float    g_cat  [8u * 1024u * HW];   // 32 MB fp32 (residual path)
__device__ uint16_t g_catH [8u * 1024u * HW];   // 16 MB fp16 shadow
__device__ uint16_t g_zH   [8u * 256u  * HW];   // fp16 conv output
__device__ uint16_t g_qkvH [8u * 768u  * HW];   // fp16 qkv
__device__ uint16_t g_attoH[8u * 256u  * HW];   // fp16 attention output
__device__ float g_scale[2048];
__device__ float g_bias [2048];
__device__ uint16_t g_Whi[589824];
__device__ uint16_t g_Wlo[589824];
__device__ uint16_t g_Bhi[18874368];
__device__ uint16_t g_Blo[18874368];

// offsets (elements) inside g_Bhi/g_Blo for attention operands
#define QT_OFF 0
#define KT_OFF 2097152
#define V_OFF  4194304

__device__ __forceinline__ float silu_f(float v) { return v / (1.f + __expf(-v)); }

__device__ __forceinline__ uint32_t smem_u32(const void* p) {
    uint32_t a;
    asm("{ .reg .u64 t; cvta.to.shared.u64 t, %1; cvt.u32.u64 %0, t; }" : "=r"(a) : "l"(p));
    return a;
}
#define SWZ128(o) ((o) ^ (((o) >> 3) & 0x70))
#define SWZ64(o)  ((o) ^ (((o) >> 3) & 0x30))

__device__ __forceinline__ void ldsm_x4(uint32_t* r, uint32_t a) {
    asm volatile("ldmatrix.sync.aligned.m8n8.x4.shared.b16 {%0,%1,%2,%3}, [%4];"
        : "=r"(r[0]), "=r"(r[1]), "=r"(r[2]), "=r"(r[3]) : "r"(a));
}
__device__ __forceinline__ void ldsm_x2(uint32_t* r, uint32_t a) {
    asm volatile("ldmatrix.sync.aligned.m8n8.x2.shared.b16 {%0,%1}, [%2];"
        : "=r"(r[0]), "=r"(r[1]) : "r"(a));
}
// bf16 mma (attention)
__device__ __forceinline__ void mma16816(float* d, const uint32_t* a, const uint32_t* b) {
    asm volatile("mma.sync.aligned.m16n8k16.row.col.f32.bf16.bf16.f32 "
        "{%0,%1,%2,%3}, {%4,%5,%6,%7}, {%8,%9}, {%0,%1,%2,%3};"
        : "+f"(d[0]), "+f"(d[1]), "+f"(d[2]), "+f"(d[3])
        : "r"(a[0]), "r"(a[1]), "r"(a[2]), "r"(a[3]), "r"(b[0]), "r"(b[1]));
}
// fp16 mma (GEMMs)
__device__ __forceinline__ void mma16816f(float* d, const uint32_t* a, const uint32_t* b) {
    asm volatile("mma.sync.aligned.m16n8k16.row.col.f32.f16.f16.f32 "
        "{%0,%1,%2,%3}, {%4,%5,%6,%7}, {%8,%9}, {%0,%1,%2,%3};"
        : "+f"(d[0]), "+f"(d[1]), "+f"(d[2]), "+f"(d[3])
        : "r"(a[0]), "r"(a[1]), "r"(a[2]), "r"(a[3]), "r"(b[0]), "r"(b[1]));
}
__device__ __forceinline__ void cpa16(uint32_t d, const void* s) {
    asm volatile("cp.async.cg.shared.global [%0], [%1], 16;" :: "r"(d), "l"(s));
}
__device__ __forceinline__ void cpa16z(uint32_t d, const void* s, int sz) {
    asm volatile("cp.async.cg.shared.global [%0], [%1], 16, %2;" :: "r"(d), "l"(s), "r"(sz));
}
#define CPA_COMMIT() asm volatile("cp.async.commit_group;" ::: "memory")
#define CPA_WAIT1()  asm volatile("cp.async.wait_group 1;" ::: "memory")
#define CPA_WAIT0()  asm volatile("cp.async.wait_group 0;" ::: "memory")

__device__ __forceinline__ uint32_t packbf(float lo, float hi) {
    uint32_t r;
    asm("cvt.rn.bf16x2.f32 %0, %1, %2;" : "=r"(r) : "f"(hi), "f"(lo));
    return r;
}

// ---------------- BN fold ----------------
__global__ void fold_bn_kernel(const float* __restrict__ cv1, const float* __restrict__ cv2,
                               const float* __restrict__ mcv1, const float* __restrict__ mcv2)
{
    int c = blockIdx.x * 256 + threadIdx.x;
    if (c >= 2048) return;
    const float* p; int C, lc;
    if (c < 512)        { p = cv1;  C = 512; lc = c; }
    else if (c < 1024)  { p = cv2;  C = 512; lc = c - 512; }
    else if (c < 1536)  { int i = (c - 1024) >> 8; p = mcv1 + i * 1024; C = 256; lc = (c - 1024) & 255; }
    else                { int i = (c - 1536) >> 8; p = mcv2 + i * 1024; C = 256; lc = (c - 1536) & 255; }
    float g = p[lc], b = p[C + lc], m = p[2 * C + lc], v = p[3 * C + lc];
    float s = g / sqrtf(v + 1e-3f);
    g_scale[c] = s;
    g_bias[c]  = b - m * s;
}

// ---------------- weight converter: fp32 -> fp16 hi/lo ----------------
__global__ void convW_kernel(const float* __restrict__ W, int M, int K, int isConv,
                             uint16_t* __restrict__ Whi, uint16_t* __restrict__ Wlo)
{
    long e = (long)blockIdx.x * 256 + threadIdx.x;
    if (e >= (long)M * K) return;
    long m = e / K, k = e % K;
    float v;
    if (isConv) { int off = (int)(k >> 8), ci = (int)(k & 255); v = W[m * 2304 + ci * 9 + off]; }
    else v = W[e];
    __half h = __float2half(v);
    __half l = __float2half(v - __half2float(h));
    Whi[e] = __half_as_ushort(h);
    Wlo[e] = __half_as_ushort(l);
}

// ---------------- activation transposer: [b][K][HW] (T) -> fp16 [b][n][K] ----------------
template <typename T>
__global__ void convB_kernel(const T* __restrict__ In, long inStride, int K,
                             uint16_t* __restrict__ Bhi)
{
    __shared__ float t[32][33];
    int n0 = blockIdx.x * 32, k0 = blockIdx.y * 32, b = blockIdx.z;
    int tx = threadIdx.x, ty = threadIdx.y;
    const T* in = In + (long)b * inStride;
#pragma unroll
    for (int yy = 0; yy < 32; yy += 8)
        t[yy + ty][tx] = (float)in[(long)(k0 + yy + ty) * HW + n0 + tx];
    __syncthreads();
#pragma unroll
    for (int yy = 0; yy < 32; yy += 8) {
        int n = n0 + yy + ty, k = k0 + tx;
        float v = t[tx][yy + ty];
        long o = ((long)b * 1024 + n) * K + k;
        Bhi[o] = __half_as_ushort(__float2half(v));
    }
}

// ---------------- warp-MMA GEMM (N-tile 128): fp16 split-2, K-chunk 64, 2-stage ----------------
#define MG_STAGE 49152
#define MG_SMEM  98304

__device__ __forceinline__ void mg_load(uint32_t smb, int tid,
    const uint4* __restrict__ wHi, const uint4* __restrict__ wLo,
    const uint4* __restrict__ bHi,
    int m0, int n0, int K16, int c, uint32_t stOff)
{
    uint32_t sb = smb + stOff;
#pragma unroll
    for (int l = 0; l < 4; l++) {
        int e = tid + l * 256;
        int r = e >> 3, j = e & 7;
        uint32_t off = SWZ128((uint32_t)(r * 128 + j * 16));
        cpa16(sb + off,         wHi + (long)(m0 + r) * K16 + c * 8 + j);
        cpa16(sb + 16384 + off, wLo + (long)(m0 + r) * K16 + c * 8 + j);
        cpa16(sb + 32768 + off, bHi + (long)(n0 + r) * K16 + c * 8 + j);
    }
}

extern __shared__ char mg_smem[];

__global__ void __launch_bounds__(256, 2) mgemm_kernel(
    const uint16_t* __restrict__ Bhi,
    const uint16_t* __restrict__ Whi, const uint16_t* __restrict__ Wlo,
    int K,
    float* __restrict__ Out, uint16_t* __restrict__ OutH, long outStride,
    const float* __restrict__ scale, const float* __restrict__ bias,
    const float* __restrict__ Res, long resStride,
    int doSilu)
{
    int b = blockIdx.z, m0 = blockIdx.y * 128, n0 = blockIdx.x * 128;
    int tid = threadIdx.x, wid = tid >> 5, lane = tid & 31;
    int warp_m = wid & 1, warp_n = wid >> 1;
    uint32_t smb = smem_u32(mg_smem);

    int K16 = K >> 3;
    const uint4* wHi = (const uint4*)Whi;
    const uint4* wLo = (const uint4*)Wlo;
    const uint4* bHi = (const uint4*)(Bhi + (long)b * 1024 * K);

    float acc[4][4][4];
#pragma unroll
    for (int i = 0; i < 4; i++)
#pragma unroll
        for (int j = 0; j < 4; j++)
#pragma unroll
            for (int r = 0; r < 4; r++) acc[i][j][r] = 0.f;

    int nChunks = K >> 6;
    mg_load(smb, tid, wHi, wLo, bHi, m0, n0, K16, 0, 0);
    CPA_COMMIT();

    int aRowL = warp_m * 64 + (lane & 7) + (lane & 8);
    int aColL = ((lane >> 4) & 1) * 16;
    int bRowX4 = warp_n * 32 + (lane >> 4) * 8 + (lane & 7);  // + p*16
    uint32_t bColX4 = (uint32_t)(((lane >> 3) & 1) * 16);

    for (int c = 0; c < nChunks; c++) {
        int s = c & 1;
        CPA_WAIT0();
        __syncthreads();
        if (c + 1 < nChunks) {
            mg_load(smb, tid, wHi, wLo, bHi, m0, n0, K16, c + 1, (uint32_t)((s ^ 1) * MG_STAGE));
            CPA_COMMIT();
        }

        uint32_t base = smb + (uint32_t)(s * MG_STAGE);
#pragma unroll
        for (int ks = 0; ks < 4; ks++) {
            uint32_t ah[4][4], bh4[2][4];
#pragma unroll
            for (int mt = 0; mt < 4; mt++)
                ldsm_x4(ah[mt], base + SWZ128((uint32_t)((aRowL + mt * 16) * 128 + aColL + ks * 32)));
#pragma unroll
            for (int p = 0; p < 2; p++)
                ldsm_x4(bh4[p], base + 32768 + SWZ128((uint32_t)((bRowX4 + p * 16) * 128 + bColX4 + ks * 32)));
#pragma unroll
            for (int mt = 0; mt < 4; mt++)
#pragma unroll
                for (int p = 0; p < 2; p++) {
                    mma16816f(acc[mt][2 * p],     ah[mt], &bh4[p][0]);
                    mma16816f(acc[mt][2 * p + 1], ah[mt], &bh4[p][2]);
                }

            uint32_t al[4][4];
#pragma unroll
            for (int mt = 0; mt < 4; mt++)
                ldsm_x4(al[mt], base + 16384 + SWZ128((uint32_t)((aRowL + mt * 16) * 128 + aColL + ks * 32)));
#pragma unroll
            for (int mt = 0; mt < 4; mt++)
#pragma unroll
                for (int p = 0; p < 2; p++) {
                    mma16816f(acc[mt][2 * p],     al[mt], &bh4[p][0]);
                    mma16816f(acc[mt][2 * p + 1], al[mt], &bh4[p][2]);
                }
        }
    }

#pragma unroll
    for (int mt = 0; mt < 4; mt++) {
        int mb = m0 + warp_m * 64 + mt * 16 + (lane >> 2);
#pragma unroll
        for (int h2 = 0; h2 < 2; h2++) {
            int m = mb + h2 * 8;
            float s = 1.f, bb = 0.f;
            if (scale) { s = scale[m]; bb = bias[m]; }
            long rowOff = (long)b * outStride + (long)m * HW;
            long resOff = Res ? ((long)b * resStride + (long)m * HW) : 0;
#pragma unroll
            for (int nt = 0; nt < 4; nt++) {
                int n = n0 + warp_n * 32 + nt * 8 + (lane & 3) * 2;
                float v0 = acc[mt][nt][h2 * 2 + 0] * s + bb;
                float v1 = acc[mt][nt][h2 * 2 + 1] * s + bb;
                if (doSilu) { v0 = silu_f(v0); v1 = silu_f(v1); }
                if (Res) {
                    float2 r2 = *(const float2*)&Res[resOff + n];
                    v0 += r2.x; v1 += r2.y;
                }
                if (Out) *(float2*)&Out[rowOff + n] = make_float2(v0, v1);
                if (OutH) {
                    __half2 hv = __floats2half2_rn(v0, v1);
                    *(__half2*)&OutH[rowOff + n] = hv;
                }
            }
        }
    }
}

// ---------------- warp-MMA GEMM (N-tile 64): K-chunk 64, single-sync; generic or conv B ----------------
#define MG64_STAGE 40960
#define MG64_SMEM  81920

__device__ __forceinline__ void mg64_load(uint32_t smb, int tid,
    const uint4* __restrict__ wHi, const uint4* __restrict__ wLo,
    const uint4* __restrict__ bHi,
    int m0, int n0, int K16, int c, uint32_t stOff)
{
    uint32_t sb = smb + stOff;
#pragma unroll
    for (int l = 0; l < 4; l++) {
        int e = tid + l * 256;
        int r = e >> 3, j = e & 7;
        uint32_t off = SWZ128((uint32_t)(r * 128 + j * 16));
        cpa16(sb + off,         wHi + (long)(m0 + r) * K16 + c * 8 + j);
        cpa16(sb + 16384 + off, wLo + (long)(m0 + r) * K16 + c * 8 + j);
    }
#pragma unroll
    for (int l = 0; l < 2; l++) {
        int e = tid + l * 256;
        int r = e >> 3, j = e & 7;
        uint32_t off = SWZ128((uint32_t)(r * 128 + j * 16));
        cpa16(sb + 32768 + off, bHi + (long)(n0 + r) * K16 + c * 8 + j);
    }
}

// implicit 3x3 conv B loader: B is yi in fp16 [n][256]; chunk c (64 wide) -> tap (c>>2), quarter (c&3)
__device__ __forceinline__ void mgc_load(uint32_t smb, int tid,
    const uint4* __restrict__ wHi, const uint4* __restrict__ wLo,
    const uint4* __restrict__ bHi,
    int m0, int n0, int K16, int c, uint32_t stOff)
{
    uint32_t sb = smb + stOff;
#pragma unroll
    for (int l = 0; l < 4; l++) {
        int e = tid + l * 256;
        int r = e >> 3, j = e & 7;
        uint32_t off = SWZ128((uint32_t)(r * 128 + j * 16));
        cpa16(sb + off,         wHi + (long)(m0 + r) * K16 + c * 8 + j);
        cpa16(sb + 16384 + off, wLo + (long)(m0 + r) * K16 + c * 8 + j);
    }
    int tap = c >> 2, q = c & 3;
    int dy = tap / 3 - 1, dx = tap % 3 - 1;
#pragma unroll
    for (int l = 0; l < 2; l++) {
        int e = tid + l * 256;
        int r = e >> 3, j = e & 7;
        int pix = n0 + r;
        int y = (pix >> 5) + dy, x = (pix & 31) + dx;
        bool ok = ((unsigned)y < 32u) && ((unsigned)x < 32u);
        int ps = ok ? (y * 32 + x) : 0;
        int sz = ok ? 16 : 0;
        uint32_t off = SWZ128((uint32_t)(r * 128 + j * 16));
        cpa16z(sb + 32768 + off, bHi + (long)ps * 32 + q * 8 + j, sz);
    }
}

template <int CONV>
__global__ void __launch_bounds__(256, 2) mgemm64_kernel_t(
    const uint16_t* __restrict__ Bhi,
    const uint16_t* __restrict__ Whi, const uint16_t* __restrict__ Wlo,
    int K, int bK,
    float* __restrict__ Out, uint16_t* __restrict__ OutH, long outStride,
    const float* __restrict__ scale, const float* __restrict__ bias,
    const float* __restrict__ Res, long resStride,
    int doSilu)
{
    int b = blockIdx.z, m0 = blockIdx.y * 128, n0 = blockIdx.x * 64;
    int tid = threadIdx.x, wid = tid >> 5, lane = tid & 31;
    int warp_m = wid & 3, warp_n = wid >> 2;
    uint32_t smb = smem_u32(mg_smem);

    int K16 = K >> 3;
    const uint4* wHi = (const uint4*)Whi;
    const uint4* wLo = (const uint4*)Wlo;
    const uint4* bHi = (const uint4*)(Bhi + (long)b * 1024 * bK);

    float acc[2][4][4];
#pragma unroll
    for (int i = 0; i < 2; i++)
#pragma unroll
        for (int j = 0; j < 4; j++)
#pragma unroll
            for (int r = 0; r < 4; r++) acc[i][j][r] = 0.f;

    int nChunks = K >> 6;
    if (CONV) mgc_load(smb, tid, wHi, wLo, bHi, m0, n0, K16, 0, 0);
    else      mg64_load(smb, tid, wHi, wLo, bHi, m0, n0, K16, 0, 0);
    CPA_COMMIT();

    int aRowL = warp_m * 32 + (lane & 7) + (lane & 8);
    int aColL = ((lane >> 4) & 1) * 16;
    int bRowX4 = warp_n * 32 + (lane >> 4) * 8 + (lane & 7);  // + p*16
    uint32_t bColX4 = (uint32_t)(((lane >> 3) & 1) * 16);

    for (int c = 0; c < nChunks; c++) {
        int s = c & 1;
        CPA_WAIT0();
        __syncthreads();
        if (c + 1 < nChunks) {
            if (CONV) mgc_load(smb, tid, wHi, wLo, bHi, m0, n0, K16, c + 1, (uint32_t)((s ^ 1) * MG64_STAGE));
            else      mg64_load(smb, tid, wHi, wLo, bHi, m0, n0, K16, c + 1, (uint32_t)((s ^ 1) * MG64_STAGE));
            CPA_COMMIT();
        }

        uint32_t base = smb + (uint32_t)(s * MG64_STAGE);
#pragma unroll
        for (int ks = 0; ks < 4; ks++) {
            uint32_t ah[2][4], bh4[2][4];
#pragma unroll
            for (int mt = 0; mt < 2; mt++)
                ldsm_x4(ah[mt], base + SWZ128((uint32_t)((aRowL + mt * 16) * 128 + aColL + ks * 32)));
#pragma unroll
            for (int p = 0; p < 2; p++)
                ldsm_x4(bh4[p], base + 32768 + SWZ128((uint32_t)((bRowX4 + p * 16) * 128 + bColX4 + ks * 32)));
#pragma unroll
            for (int mt = 0; mt < 2; mt++)
#pragma unroll
                for (int p = 0; p < 2; p++) {
                    mma16816f(acc[mt][2 * p],     ah[mt], &bh4[p][0]);
                    mma16816f(acc[mt][2 * p + 1], ah[mt], &bh4[p][2]);
                }

            uint32_t al[2][4];
#pragma unroll
            for (int mt = 0; mt < 2; mt++)
                ldsm_x4(al[mt], base + 16384 + SWZ128((uint32_t)((aRowL + mt * 16) * 128 + aColL + ks * 32)));
#pragma unroll
            for (int mt = 0; mt < 2; mt++)
#pragma unroll
                for (int p = 0; p < 2; p++) {
                    mma16816f(acc[mt][2 * p],     al[mt], &bh4[p][0]);
                    mma16816f(acc[mt][2 * p + 1], al[mt], &bh4[p][2]);
                }
        }
    }

#pragma unroll
    for (int mt = 0; mt < 2; mt++) {
        int mb = m0 + warp_m * 32 + mt * 16 + (lane >> 2);
#pragma unroll
        for (int h2 = 0; h2 < 2; h2++) {
            int m = mb + h2 * 8;
            float s = 1.f, bb = 0.f;
            if (scale) { s = scale[m]; bb = bias[m]; }
            long rowOff = (long)b * outStride + (long)m * HW;
            long resOff = Res ? ((long)b * resStride + (long)m * HW) : 0;
#pragma unroll
            for (int nt = 0; nt < 4; nt++) {
                int n = n0 + warp_n * 32 + nt * 8 + (lane & 3) * 2;
                float v0 = acc[mt][nt][h2 * 2 + 0] * s + bb;
                float v1 = acc[mt][nt][h2 * 2 + 1] * s + bb;
                if (doSilu) { v0 = silu_f(v0); v1 = silu_f(v1); }
                if (Res) {
                    float2 r2 = *(const float2*)&Res[resOff + n];
                    v0 += r2.x; v1 += r2.y;
                }
                if (Out) *(float2*)&Out[rowOff + n] = make_float2(v0, v1);
                if (OutH) {
                    __half2 hv = __floats2half2_rn(v0, v1);
                    *(__half2*)&OutH[rowOff + n] = hv;
                }
            }
        }
    }
}

// ---------------- attention converter: qkv fp16 -> qT/kT(+relpos)/v bf16 hi/lo ----------------
__global__ void convAttn_kernel(const uint16_t* __restrict__ QKVH,
                                const float* __restrict__ RW, const float* __restrict__ RH,
                                __nv_bfloat16* __restrict__ Hi, __nv_bfloat16* __restrict__ Lo)
{
    __shared__ float tq[32][33], tk[32][33];
    int it = blockIdx.x, dt = blockIdx.y, bh = blockIdx.z;
    int b = bh >> 2, hh = bh & 3;
    int tx = threadIdx.x, ty = threadIdx.y;
    const __half* base = (const __half*)QKVH + (long)b * 768 * HW;
#pragma unroll
    for (int l = 0; l < 4; l++) {
        int d = dt * 32 + ty + l * 8;
        int ch = hh * 64 + d;
        float qv = __half2float(base[(long)ch * HW + it * 32 + tx]) * 0.125f;
        float kv = __half2float(base[(long)(256 + ch) * HW + it * 32 + tx]) + RW[ch * 32 + tx] + RH[ch * 32 + it];
        float vv = __half2float(base[(long)(512 + ch) * HW + it * 32 + tx]);
        tq[ty + l * 8][tx] = qv;
        tk[ty + l * 8][tx] = kv;
        long vo = V_OFF + ((long)bh * 64 + d) * 1024 + it * 32 + tx;
        __nv_bfloat16 vh = __float2bfloat16(vv);
        Hi[vo] = vh;
        Lo[vo] = __float2bfloat16(vv - __bfloat162float(vh));
    }
    __syncthreads();
#pragma unroll
    for (int l = 0; l < 4; l++) {
        int i = it * 32 + ty + l * 8;
        int d = dt * 32 + tx;
        float qv = tq[tx][ty + l * 8];
        float kv = tk[tx][ty + l * 8];
        long qo = ((long)bh * 1024 + i) * 64 + d;
        __nv_bfloat16 qh = __float2bfloat16(qv);
        Hi[QT_OFF + qo] = qh;
        Lo[QT_OFF + qo] = __float2bfloat16(qv - __bfloat162float(qh));
        __nv_bfloat16 kh = __float2bfloat16(kv);
        Hi[KT_OFF + qo] = kh;
        Lo[KT_OFF + qo] = __float2bfloat16(kv - __bfloat162float(kh));
    }
}

// ---------------- MMA flash attention (bf16 split-3) ----------------
#define AT_SMEM 163840

__device__ __forceinline__ void kv_load(uint32_t smb, int tid,
    const __nv_bfloat16* __restrict__ kTh, const __nv_bfloat16* __restrict__ kTl,
    const __nv_bfloat16* __restrict__ vH, const __nv_bfloat16* __restrict__ vL,
    int bh, int t, uint32_t stOff)
{
    uint32_t kb = smb + stOff;
    const uint4* kh4 = (const uint4*)(kTh + ((long)bh * 1024 + t * 128) * 64);
    const uint4* kl4 = (const uint4*)(kTl + ((long)bh * 1024 + t * 128) * 64);
    int r = tid >> 1, j0 = (tid & 1) * 4;
#pragma unroll
    for (int j = 0; j < 4; j++) {
        uint32_t off = SWZ128((uint32_t)(r * 128 + (j0 + j) * 16));
        cpa16(kb + off, kh4 + (long)r * 8 + j0 + j);
        cpa16(kb + 16384 + off, kl4 + (long)r * 8 + j0 + j);
    }
    const uint4* vh4 = (const uint4*)(vH + (long)bh * 65536 + t * 128);
    const uint4* vl4 = (const uint4*)(vL + (long)bh * 65536 + t * 128);
    int d = tid >> 2, jc0 = (tid & 3) * 4;
#pragma unroll
    for (int j = 0; j < 4; j++) {
        int jc = jc0 + j;
        uint32_t off = (uint32_t)((jc >> 3) * 8192) + SWZ128((uint32_t)(d * 128 + (jc & 7) * 16));
        cpa16(kb + 32768 + off, vh4 + (long)d * 128 + jc);
        cpa16(kb + 49152 + off, vl4 + (long)d * 128 + jc);
    }
}

extern __shared__ char at_smem[];

__global__ void __launch_bounds__(256) attn_mma_kernel(
    const __nv_bfloat16* __restrict__ Hi, const __nv_bfloat16* __restrict__ Lo,
    uint16_t* __restrict__ OutpH)
{
    int qt = blockIdx.x, h = blockIdx.y, b = blockIdx.z;
    int bh = b * 4 + h;
    int tid = threadIdx.x, wid = tid >> 5, lane = tid & 31, li = lane & 15;
    uint32_t smb = smem_u32(at_smem);

    const __nv_bfloat16* qTh = Hi + QT_OFF;
    const __nv_bfloat16* qTl = Lo + QT_OFF;
    const __nv_bfloat16* kTh = Hi + KT_OFF;
    const __nv_bfloat16* kTl = Lo + KT_OFF;
    const __nv_bfloat16* vH  = Hi + V_OFF;
    const __nv_bfloat16* vL  = Lo + V_OFF;

    {
        const uint4* qh4 = (const uint4*)(qTh + ((long)bh * 1024 + qt * 128) * 64);
        const uint4* ql4 = (const uint4*)(qTl + ((long)bh * 1024 + qt * 128) * 64);
        int r = tid >> 1, j0 = (tid & 1) * 4;
        uint32_t qb = smb + 131072;
#pragma unroll
        for (int j = 0; j < 4; j++) {
            uint32_t off = SWZ128((uint32_t)(r * 128 + (j0 + j) * 16));
            cpa16(qb + off, qh4 + (long)r * 8 + j0 + j);
            cpa16(qb + 16384 + off, ql4 + (long)r * 8 + j0 + j);
        }
    }
    CPA_COMMIT();
    kv_load(smb, tid, kTh, kTl, vH, vL, bh, 0, 0);
    CPA_COMMIT();
    CPA_WAIT1();
    __syncthreads();

    uint32_t qfh[4][4], qfl[4][4];
    {
        int aRow = wid * 16 + (lane & 7) + (lane & 8);
        int aCol = ((lane >> 4) & 1) * 16;
#pragma unroll
        for (int ks = 0; ks < 4; ks++) {
            uint32_t off = SWZ128((uint32_t)(aRow * 128 + aCol + ks * 32));
            ldsm_x4(qfh[ks], smb + 131072 + off);
            ldsm_x4(qfl[ks], smb + 131072 + 16384 + off);
        }
    }

    float oacc[8][4];
#pragma unroll
    for (int i = 0; i < 8; i++)
#pragma unroll
        for (int j = 0; j < 4; j++) oacc[i][j] = 0.f;
    float m0 = -1e30f, m1 = -1e30f, l0 = 0.f, l1 = 0.f;

    int sRowX4 = (lane >> 4) * 8 + (lane & 7);
    uint32_t sColX4 = (uint32_t)(((lane >> 3) & 1) * 16);

    for (int t = 0; t < 8; t++) {
        int s = t & 1;
        if (t < 7) {
            kv_load(smb, tid, kTh, kTl, vH, vL, bh, t + 1, (uint32_t)((s ^ 1) * 65536));
            CPA_COMMIT();
            CPA_WAIT1();
        } else {
            CPA_WAIT0();
        }
        __syncthreads();

        uint32_t kb = smb + s * 65536;
        float sacc[16][4];
#pragma unroll
        for (int i = 0; i < 16; i++)
#pragma unroll
            for (int j = 0; j < 4; j++) sacc[i][j] = 0.f;

#pragma unroll
        for (int p = 0; p < 8; p++) {
            int rowB = p * 16 + sRowX4;
#pragma unroll
            for (int ks = 0; ks < 4; ks++) {
                uint32_t off = SWZ128((uint32_t)(rowB * 128 + sColX4 + ks * 32));
                uint32_t kh4[4], kl4[4];
                ldsm_x4(kh4, kb + off);
                ldsm_x4(kl4, kb + 16384 + off);
                mma16816(sacc[2 * p],     qfh[ks], &kh4[0]);
                mma16816(sacc[2 * p + 1], qfh[ks], &kh4[2]);
                mma16816(sacc[2 * p],     qfl[ks], &kh4[0]);
                mma16816(sacc[2 * p + 1], qfl[ks], &kh4[2]);
                mma16816(sacc[2 * p],     qfh[ks], &kl4[0]);
                mma16816(sacc[2 * p + 1], qfh[ks], &kl4[2]);
            }
        }

        float mx0 = m0, mx1 = m1;
#pragma unroll
        for (int nt = 0; nt < 16; nt++) {
            mx0 = fmaxf(mx0, fmaxf(sacc[nt][0], sacc[nt][1]));
            mx1 = fmaxf(mx1, fmaxf(sacc[nt][2], sacc[nt][3]));
        }
        mx0 = fmaxf(mx0, __shfl_xor_sync(0xffffffffu, mx0, 1));
        mx0 = fmaxf(mx0, __shfl_xor_sync(0xffffffffu, mx0, 2));
        mx1 = fmaxf(mx1, __shfl_xor_sync(0xffffffffu, mx1, 1));
        mx1 = fmaxf(mx1, __shfl_xor_sync(0xffffffffu, mx1, 2));
        float a0 = __expf(m0 - mx0), a1 = __expf(m1 - mx1);
        m0 = mx0; m1 = mx1;

        float ls0 = 0.f, ls1 = 0.f;
        uint32_t pah[8][4], pal[8][4];
#pragma unroll
        for (int kj = 0; kj < 8; kj++) {
            float p00 = __expf(sacc[2 * kj][0] - m0);
            float p01 = __expf(sacc[2 * kj][1] - m0);
            float p02 = __expf(sacc[2 * kj][2] - m1);
            float p03 = __expf(sacc[2 * kj][3] - m1);
            float p10 = __expf(sacc[2 * kj + 1][0] - m0);
            float p11 = __expf(sacc[2 * kj + 1][1] - m0);
            float p12 = __expf(sacc[2 * kj + 1][2] - m1);
            float p13 = __expf(sacc[2 * kj + 1][3] - m1);
            ls0 += p00 + p01 + p10 + p11;
            ls1 += p02 + p03 + p12 + p13;
            pah[kj][0] = packbf(p00, p01);
            pah[kj][1] = packbf(p02, p03);
            pah[kj][2] = packbf(p10, p11);
            pah[kj][3] = packbf(p12, p13);
            float q00 = p00 - __bfloat162float(__float2bfloat16(p00));
            float q01 = p01 - __bfloat162float(__float2bfloat16(p01));
            float q02 = p02 - __bfloat162float(__float2bfloat16(p02));
            float q03 = p03 - __bfloat162float(__float2bfloat16(p03));
            float q10 = p10 - __bfloat162float(__float2bfloat16(p10));
            float q11 = p11 - __bfloat162float(__float2bfloat16(p11));
            float q12 = p12 - __bfloat162float(__float2bfloat16(p12));
            float q13 = p13 - __bfloat162float(__float2bfloat16(p13));
            pal[kj][0] = packbf(q00, q01);
            pal[kj][1] = packbf(q02, q03);
            pal[kj][2] = packbf(q10, q11);
            pal[kj][3] = packbf(q12, q13);
        }
        ls0 += __shfl_xor_sync(0xffffffffu, ls0, 1);
        ls0 += __shfl_xor_sync(0xffffffffu, ls0, 2);
        ls1 += __shfl_xor_sync(0xffffffffu, ls1, 1);
        ls1 += __shfl_xor_sync(0xffffffffu, ls1, 2);
        l0 = l0 * a0 + ls0;
        l1 = l1 * a1 + ls1;
#pragma unroll
        for (int dt = 0; dt < 8; dt++) {
            oacc[dt][0] *= a0; oacc[dt][1] *= a0;
            oacc[dt][2] *= a1; oacc[dt][3] *= a1;
        }

#pragma unroll
        for (int dt = 0; dt < 8; dt++) {
            int rowV = dt * 8 + (li & 7);
#pragma unroll
            for (int kj = 0; kj < 8; kj++) {
                uint32_t off = (uint32_t)((kj >> 2) * 8192) +
                               SWZ128((uint32_t)(rowV * 128 + (li >> 3) * 16 + (kj & 3) * 32));
                uint32_t vh2[2], vl2[2];
                ldsm_x2(vh2, kb + 32768 + off);
                ldsm_x2(vl2, kb + 49152 + off);
                mma16816(oacc[dt], pah[kj], vh2);
                mma16816(oacc[dt], pal[kj], vh2);
                mma16816(oacc[dt], pah[kj], vl2);
            }
        }
        __syncthreads();
    }

    float i0 = 1.f / l0, i1 = 1.f / l1;
    float* stg = (float*)at_smem;   // [128][66]
    int r0 = wid * 16 + (lane >> 2);
#pragma unroll
    for (int dt = 0; dt < 8; dt++) {
        int d = dt * 8 + (lane & 3) * 2;
        stg[r0 * 66 + d]           = oacc[dt][0] * i0;
        stg[r0 * 66 + d + 1]       = oacc[dt][1] * i0;
        stg[(r0 + 8) * 66 + d]     = oacc[dt][2] * i1;
        stg[(r0 + 8) * 66 + d + 1] = oacc[dt][3] * i1;
    }
    __syncthreads();
    for (int e = tid; e < 8192; e += 256) {
        int d = e >> 7, i = e & 127;
        OutpH[((long)b * 256 + h * 64 + d) * HW + qt * 128 + i] =
            __half_as_ushort(__float2half(stg[i * 66 + d]));
    }
}

// ---------------- launch ----------------
extern "C" void kernel_launch(void* const* d_in, const int* in_sizes, int n_in,
                              void* d_out, int out_size)
{
    const float* x      = (const float*)d_in[0];
    const float* cv1_w  = (const float*)d_in[1];
    const float* cv1_bn = (const float*)d_in[2];
    const float* cv2_w  = (const float*)d_in[3];
    const float* cv2_bn = (const float*)d_in[4];
    const float* mcv1w  = (const float*)d_in[5];
    const float* mcv1bn = (const float*)d_in[6];
    const float* mqkvw  = (const float*)d_in[7];
    const float* mrw    = (const float*)d_in[8];
    const float* mrh    = (const float*)d_in[9];
    const float* mcv2w  = (const float*)d_in[10];
    const float* mcv2bn = (const float*)d_in[11];
    float* out = (float*)d_out;

    float *cat, *scl, *bia;
    uint16_t *catH, *zH, *qkvH, *attoH, *whi, *wlo, *bhi, *blo;
    cudaGetSymbolAddress((void**)&cat,   g_cat);
    cudaGetSymbolAddress((void**)&catH,  g_catH);
    cudaGetSymbolAddress((void**)&zH,    g_zH);
    cudaGetSymbolAddress((void**)&qkvH,  g_qkvH);
    cudaGetSymbolAddress((void**)&attoH, g_attoH);
    cudaGetSymbolAddress((void**)&scl,   g_scale);
    cudaGetSymbolAddress((void**)&bia,   g_bias);
    cudaGetSymbolAddress((void**)&whi,   g_Whi);
    cudaGetSymbolAddress((void**)&wlo,   g_Wlo);
    cudaGetSymbolAddress((void**)&bhi,   g_Bhi);
    cudaGetSymbolAddress((void**)&blo,   g_Blo);
    __nv_bfloat16* bhiB = (__nv_bfloat16*)bhi;
    __nv_bfloat16* bloB = (__nv_bfloat16*)blo;

    cudaFuncSetAttribute(mgemm_kernel, cudaFuncAttributeMaxDynamicSharedMemorySize, MG_SMEM);
    cudaFuncSetAttribute(mgemm64_kernel_t<0>, cudaFuncAttributeMaxDynamicSharedMemorySize, MG64_SMEM);
    cudaFuncSetAttribute(mgemm64_kernel_t<1>, cudaFuncAttributeMaxDynamicSharedMemorySize, MG64_SMEM);
    cudaFuncSetAttribute(attn_mma_kernel, cudaFuncAttributeMaxDynamicSharedMemorySize, AT_SMEM);

    fold_bn_kernel<<<8, 256>>>(cv1_bn, cv2_bn, mcv1bn, mcv2bn);

    // ---- cv1: 512 -> 512, BN+SiLU -> fp32 cat[0:512) + fp16 catH[0:512) ----
    convW_kernel<<<(512 * 512 + 255) / 256, 256>>>(cv1_w, 512, 512, 0, whi, wlo);
    convB_kernel<float><<<dim3(32, 16, 8), dim3(32, 8)>>>(x, (long)512 * HW, 512, bhi);
    mgemm_kernel<<<dim3(8, 4, 8), 256, MG_SMEM>>>(
        bhi, whi, wlo, 512, cat, catH, (long)1024 * HW,
        scl + 0, bia + 0, nullptr, 0, 1);

    for (int i = 0; i < 2; i++) {
        long yin  = (long)(i == 0 ? 256 : 512) * HW;
        long yout = (long)(512 + i * 256) * HW;

        // z = cbs(yi, 3x3) as IMPLICIT GEMM from catH fp16; output fp16 zH only
        convW_kernel<<<(256 * 2304 + 255) / 256, 256>>>(
            mcv1w + (long)i * 256 * 2304, 256, 2304, 1, whi, wlo);
        convB_kernel<__half><<<dim3(32, 8, 8), dim3(32, 8)>>>(
            (const __half*)(catH + yin), (long)1024 * HW, 256, bhi);
        mgemm64_kernel_t<1><<<dim3(16, 2, 8), 256, MG64_SMEM>>>(
            bhi, whi, wlo, 2304, 256, nullptr, zH, (long)256 * HW,
            scl + 1024 + i * 256, bia + 1024 + i * 256, nullptr, 0, 1);

        // qkv = conv1x1(z), 256 -> 768; output fp16 qkvH only
        convW_kernel<<<(768 * 256 + 255) / 256, 256>>>(
            mqkvw + (long)i * 768 * 256, 768, 256, 0, whi, wlo);
        convB_kernel<__half><<<dim3(32, 8, 8), dim3(32, 8)>>>(
            (const __half*)zH, (long)256 * HW, 256, bhi);
        mgemm_kernel<<<dim3(8, 6, 8), 256, MG_SMEM>>>(
            bhi, whi, wlo, 256, nullptr, qkvH, (long)768 * HW,
            nullptr, nullptr, nullptr, 0, 0);

        // attention operand conversion (bf16 split-3) + MMA flash attention -> fp16 attoH
        convAttn_kernel<<<dim3(32, 2, 32), dim3(32, 8)>>>(
            qkvH, mrw + (long)i * 8192, mrh + (long)i * 8192, bhiB, bloB);
        attn_mma_kernel<<<dim3(8, 4, 8), 256, AT_SMEM>>>(bhiB, bloB, attoH);

        // y_{i+2} = yi + silu(bn(conv1x1(atto))) -> fp32 cat slice + fp16 catH slice
        convW_kernel<<<(256 * 256 + 255) / 256, 256>>>(
            mcv2w + (long)i * 256 * 256, 256, 256, 0, whi, wlo);
        convB_kernel<__half><<<dim3(32, 8, 8), dim3(32, 8)>>>(
            (const __half*)attoH, (long)256 * HW, 256, bhi);
        mgemm64_kernel_t<0><<<dim3(16, 2, 8), 256, MG64_SMEM>>>(
            bhi, whi, wlo, 256, 256, cat + yout, catH + yout, (long)1024 * HW,
            scl + 1536 + i * 256, bia + 1536 + i * 256, cat + yin, (long)1024 * HW, 1);
    }

    // ---- final: 1024 -> 512, BN+SiLU, fp32 out only ----
    convW_kernel<<<(512 * 1024 + 255) / 256, 256>>>(cv2_w, 512, 1024, 0, whi, wlo);
    convB_kernel<__half><<<dim3(32, 32, 8), dim3(32, 8)>>>(
        (const __half*)catH, (long)1024 * HW, 1024, bhi);
    mgemm_kernel<<<dim3(8, 4, 8), 256, MG_SMEM>>>(
        bhi, whi, wlo, 1024, out, nullptr, (long)512 * HW,
        scl + 512, bia + 512, nullptr, 0, 1);
}

// round 12
// speedup vs baseline: 1.6775x; 1.0462x over previous
#include <cuda_runtime.h>
#include <cuda_bf16.h>
#include <cuda_fp16.h>
#include <cstdint>

#define HW 1024

// ---------------- scratch (__device__ globals: alloc-guard-safe) ----------------
__device__ float    g_cat  [8u * 1024u * HW];   // 32 MB fp32 (residual path)
__device__ uint16_t g_catH [8u * 1024u * HW];   // 16 MB fp16 shadow
__device__ uint16_t g_qkvH [8u * 768u  * HW];   // fp16 qkv
__device__ float g_scale[2048];
__device__ float g_bias [2048];
__device__ uint16_t g_Whi[2490368];
__device__ uint16_t g_Wlo[2490368];
__device__ uint16_t g_Bhi[18874368];
__device__ uint16_t g_Blo[18874368];

// arena offsets (elements) inside g_Bhi
#define B0_OFF  0u          // generic B buffer (up to K=1024)
#define ZB_OFF  8388608u    // conv output in B-layout [n][256]
#define ATB_OFF 10485760u   // attention output in B-layout [n][256]
#define QT_OFF  12582912    // bf16 attn operands (also in g_Blo)
#define KT_OFF  14680064
#define V_OFF   16777216

// weight arena offsets
#define W_CV1   0
#define W_CONV0 262144
#define W_CONV1 851968
#define W_QKV0  1441792
#define W_QKV1  1638400
#define W_CV2M0 1835008
#define W_CV2M1 1900544
#define W_FIN   1966080
#define W_TOTAL 2490368

__device__ __forceinline__ float silu_f(float v) { return v / (1.f + __expf(-v)); }

__device__ __forceinline__ uint32_t smem_u32(const void* p) {
    uint32_t a;
    asm("{ .reg .u64 t; cvta.to.shared.u64 t, %1; cvt.u32.u64 %0, t; }" : "=r"(a) : "l"(p));
    return a;
}
#define SWZ128(o) ((o) ^ (((o) >> 3) & 0x70))

__device__ __forceinline__ void ldsm_x4(uint32_t* r, uint32_t a) {
    asm volatile("ldmatrix.sync.aligned.m8n8.x4.shared.b16 {%0,%1,%2,%3}, [%4];"
        : "=r"(r[0]), "=r"(r[1]), "=r"(r[2]), "=r"(r[3]) : "r"(a));
}
__device__ __forceinline__ void ldsm_x2(uint32_t* r, uint32_t a) {
    asm volatile("ldmatrix.sync.aligned.m8n8.x2.shared.b16 {%0,%1}, [%2];"
        : "=r"(r[0]), "=r"(r[1]) : "r"(a));
}
__device__ __forceinline__ void mma16816(float* d, const uint32_t* a, const uint32_t* b) {
    asm volatile("mma.sync.aligned.m16n8k16.row.col.f32.bf16.bf16.f32 "
        "{%0,%1,%2,%3}, {%4,%5,%6,%7}, {%8,%9}, {%0,%1,%2,%3};"
        : "+f"(d[0]), "+f"(d[1]), "+f"(d[2]), "+f"(d[3])
        : "r"(a[0]), "r"(a[1]), "r"(a[2]), "r"(a[3]), "r"(b[0]), "r"(b[1]));
}
__device__ __forceinline__ void mma16816f(float* d, const uint32_t* a, const uint32_t* b) {
    asm volatile("mma.sync.aligned.m16n8k16.row.col.f32.f16.f16.f32 "
        "{%0,%1,%2,%3}, {%4,%5,%6,%7}, {%8,%9}, {%0,%1,%2,%3};"
        : "+f"(d[0]), "+f"(d[1]), "+f"(d[2]), "+f"(d[3])
        : "r"(a[0]), "r"(a[1]), "r"(a[2]), "r"(a[3]), "r"(b[0]), "r"(b[1]));
}
__device__ __forceinline__ void cpa16(uint32_t d, const void* s) {
    asm volatile("cp.async.cg.shared.global [%0], [%1], 16;" :: "r"(d), "l"(s));
}
__device__ __forceinline__ void cpa16z(uint32_t d, const void* s, int sz) {
    asm volatile("cp.async.cg.shared.global [%0], [%1], 16, %2;" :: "r"(d), "l"(s), "r"(sz));
}
#define CPA_COMMIT() asm volatile("cp.async.commit_group;" ::: "memory")
#define CPA_WAIT1()  asm volatile("cp.async.wait_group 1;" ::: "memory")
#define CPA_WAIT0()  asm volatile("cp.async.wait_group 0;" ::: "memory")

__device__ __forceinline__ uint32_t packbf(float lo, float hi) {
    uint32_t r;
    asm("cvt.rn.bf16x2.f32 %0, %1, %2;" : "=r"(r) : "f"(hi), "f"(lo));
    return r;
}

// ---------------- BN fold ----------------
__global__ void fold_bn_kernel(const float* __restrict__ cv1, const float* __restrict__ cv2,
                               const float* __restrict__ mcv1, const float* __restrict__ mcv2)
{
    int c = blockIdx.x * 256 + threadIdx.x;
    if (c >= 2048) return;
    const float* p; int C, lc;
    if (c < 512)        { p = cv1;  C = 512; lc = c; }
    else if (c < 1024)  { p = cv2;  C = 512; lc = c - 512; }
    else if (c < 1536)  { int i = (c - 1024) >> 8; p = mcv1 + i * 1024; C = 256; lc = (c - 1024) & 255; }
    else                { int i = (c - 1536) >> 8; p = mcv2 + i * 1024; C = 256; lc = (c - 1536) & 255; }
    float g = p[lc], b = p[C + lc], m = p[2 * C + lc], v = p[3 * C + lc];
    float s = g / sqrtf(v + 1e-3f);
    g_scale[c] = s;
    g_bias[c]  = b - m * s;
}

// ---------------- fused weight converter: all weights fp32 -> fp16 hi/lo ----------------
__global__ void convW_all_kernel(const float* __restrict__ cv1w, const float* __restrict__ mcv1w,
                                 const float* __restrict__ mqkvw, const float* __restrict__ mcv2w,
                                 const float* __restrict__ cv2w,
                                 uint16_t* __restrict__ Whi, uint16_t* __restrict__ Wlo)
{
    long e = (long)blockIdx.x * 256 + threadIdx.x;
    if (e >= W_TOTAL) return;
    const float* W; long rel; int K; int isConv = 0;
    if (e < W_CONV0)      { W = cv1w; rel = e; K = 512; }
    else if (e < W_QKV0)  { long r = e - W_CONV0; int i = r >= 589824; rel = r - (long)i * 589824;
                            W = mcv1w + (long)i * 589824; K = 2304; isConv = 1; }
    else if (e < W_CV2M0) { long r = e - W_QKV0; int i = r >= 196608; rel = r - (long)i * 196608;
                            W = mqkvw + (long)i * 196608; K = 256; }
    else if (e < W_FIN)   { long r = e - W_CV2M0; int i = r >= 65536; rel = r - (long)i * 65536;
                            W = mcv2w + (long)i * 65536; K = 256; }
    else                  { W = cv2w; rel = e - W_FIN; K = 1024; }
    long m = rel / K, k = rel % K;
    float v;
    if (isConv) { int off = (int)(k >> 8), ci = (int)(k & 255); v = W[m * 2304 + ci * 9 + off]; }
    else v = W[rel];
    __half h = __float2half(v);
    __half l = __float2half(v - __half2float(h));
    Whi[e] = __half_as_ushort(h);
    Wlo[e] = __half_as_ushort(l);
}

// ---------------- activation transposer: [b][K][HW] (T) -> fp16 [b][n][K] ----------------
template <typename T>
__global__ void convB_kernel(const T* __restrict__ In, long inStride, int K,
                             uint16_t* __restrict__ Bhi)
{
    __shared__ float t[32][33];
    int n0 = blockIdx.x * 32, k0 = blockIdx.y * 32, b = blockIdx.z;
    int tx = threadIdx.x, ty = threadIdx.y;
    const T* in = In + (long)b * inStride;
#pragma unroll
    for (int yy = 0; yy < 32; yy += 8)
        t[yy + ty][tx] = (float)in[(long)(k0 + yy + ty) * HW + n0 + tx];
    __syncthreads();
#pragma unroll
    for (int yy = 0; yy < 32; yy += 8) {
        int n = n0 + yy + ty, k = k0 + tx;
        float v = t[tx][yy + ty];
        long o = ((long)b * 1024 + n) * K + k;
        Bhi[o] = __half_as_ushort(__float2half(v));
    }
}

// ---------------- warp-MMA GEMM (N-tile 128): fp16 split-2, K-chunk 64, 2-stage ----------------
#define MG_STAGE 49152
#define MG_SMEM  98304

__device__ __forceinline__ void mg_load(uint32_t smb, int tid,
    const uint4* __restrict__ wHi, const uint4* __restrict__ wLo,
    const uint4* __restrict__ bHi,
    int m0, int n0, int K16, int c, uint32_t stOff)
{
    uint32_t sb = smb + stOff;
#pragma unroll
    for (int l = 0; l < 4; l++) {
        int e = tid + l * 256;
        int r = e >> 3, j = e & 7;
        uint32_t off = SWZ128((uint32_t)(r * 128 + j * 16));
        cpa16(sb + off,         wHi + (long)(m0 + r) * K16 + c * 8 + j);
        cpa16(sb + 16384 + off, wLo + (long)(m0 + r) * K16 + c * 8 + j);
        cpa16(sb + 32768 + off, bHi + (long)(n0 + r) * K16 + c * 8 + j);
    }
}

extern __shared__ char mg_smem[];

__global__ void __launch_bounds__(256, 2) mgemm_kernel(
    const uint16_t* __restrict__ Bhi,
    const uint16_t* __restrict__ Whi, const uint16_t* __restrict__ Wlo,
    int K,
    float* __restrict__ Out, uint16_t* __restrict__ OutH, long outStride,
    const float* __restrict__ scale, const float* __restrict__ bias,
    const float* __restrict__ Res, long resStride,
    int doSilu)
{
    int b = blockIdx.z, m0 = blockIdx.y * 128, n0 = blockIdx.x * 128;
    int tid = threadIdx.x, wid = tid >> 5, lane = tid & 31;
    int warp_m = wid & 1, warp_n = wid >> 1;
    uint32_t smb = smem_u32(mg_smem);

    int K16 = K >> 3;
    const uint4* wHi = (const uint4*)Whi;
    const uint4* wLo = (const uint4*)Wlo;
    const uint4* bHi = (const uint4*)(Bhi + (long)b * 1024 * K);

    float acc[4][4][4];
#pragma unroll
    for (int i = 0; i < 4; i++)
#pragma unroll
        for (int j = 0; j < 4; j++)
#pragma unroll
            for (int r = 0; r < 4; r++) acc[i][j][r] = 0.f;

    int nChunks = K >> 6;
    mg_load(smb, tid, wHi, wLo, bHi, m0, n0, K16, 0, 0);
    CPA_COMMIT();

    int aRowL = warp_m * 64 + (lane & 7) + (lane & 8);
    int aColL = ((lane >> 4) & 1) * 16;
    int bRowX4 = warp_n * 32 + (lane >> 4) * 8 + (lane & 7);
    uint32_t bColX4 = (uint32_t)(((lane >> 3) & 1) * 16);

    for (int c = 0; c < nChunks; c++) {
        int s = c & 1;
        CPA_WAIT0();
        __syncthreads();
        if (c + 1 < nChunks) {
            mg_load(smb, tid, wHi, wLo, bHi, m0, n0, K16, c + 1, (uint32_t)((s ^ 1) * MG_STAGE));
            CPA_COMMIT();
        }

        uint32_t base = smb + (uint32_t)(s * MG_STAGE);
#pragma unroll
        for (int ks = 0; ks < 4; ks++) {
            uint32_t ah[4][4], bh4[2][4];
#pragma unroll
            for (int mt = 0; mt < 4; mt++)
                ldsm_x4(ah[mt], base + SWZ128((uint32_t)((aRowL + mt * 16) * 128 + aColL + ks * 32)));
#pragma unroll
            for (int p = 0; p < 2; p++)
                ldsm_x4(bh4[p], base + 32768 + SWZ128((uint32_t)((bRowX4 + p * 16) * 128 + bColX4 + ks * 32)));
#pragma unroll
            for (int mt = 0; mt < 4; mt++)
#pragma unroll
                for (int p = 0; p < 2; p++) {
                    mma16816f(acc[mt][2 * p],     ah[mt], &bh4[p][0]);
                    mma16816f(acc[mt][2 * p + 1], ah[mt], &bh4[p][2]);
                }

            uint32_t al[4][4];
#pragma unroll
            for (int mt = 0; mt < 4; mt++)
                ldsm_x4(al[mt], base + 16384 + SWZ128((uint32_t)((aRowL + mt * 16) * 128 + aColL + ks * 32)));
#pragma unroll
            for (int mt = 0; mt < 4; mt++)
#pragma unroll
                for (int p = 0; p < 2; p++) {
                    mma16816f(acc[mt][2 * p],     al[mt], &bh4[p][0]);
                    mma16816f(acc[mt][2 * p + 1], al[mt], &bh4[p][2]);
                }
        }
    }

#pragma unroll
    for (int mt = 0; mt < 4; mt++) {
        int mb = m0 + warp_m * 64 + mt * 16 + (lane >> 2);
#pragma unroll
        for (int h2 = 0; h2 < 2; h2++) {
            int m = mb + h2 * 8;
            float s = 1.f, bb = 0.f;
            if (scale) { s = scale[m]; bb = bias[m]; }
            long rowOff = (long)b * outStride + (long)m * HW;
            long resOff = Res ? ((long)b * resStride + (long)m * HW) : 0;
#pragma unroll
            for (int nt = 0; nt < 4; nt++) {
                int n = n0 + warp_n * 32 + nt * 8 + (lane & 3) * 2;
                float v0 = acc[mt][nt][h2 * 2 + 0] * s + bb;
                float v1 = acc[mt][nt][h2 * 2 + 1] * s + bb;
                if (doSilu) { v0 = silu_f(v0); v1 = silu_f(v1); }
                if (Res) {
                    float2 r2 = *(const float2*)&Res[resOff + n];
                    v0 += r2.x; v1 += r2.y;
                }
                if (Out) *(float2*)&Out[rowOff + n] = make_float2(v0, v1);
                if (OutH) {
                    __half2 hv = __floats2half2_rn(v0, v1);
                    *(__half2*)&OutH[rowOff + n] = hv;
                }
            }
        }
    }
}

// ---------------- warp-MMA GEMM (N-tile 64): K-chunk 64, single-sync ----------------
#define MG64_STAGE 40960
#define MG64_SMEM  81920

__device__ __forceinline__ void mg64_load(uint32_t smb, int tid,
    const uint4* __restrict__ wHi, const uint4* __restrict__ wLo,
    const uint4* __restrict__ bHi,
    int m0, int n0, int K16, int c, uint32_t stOff)
{
    uint32_t sb = smb + stOff;
#pragma unroll
    for (int l = 0; l < 4; l++) {
        int e = tid + l * 256;
        int r = e >> 3, j = e & 7;
        uint32_t off = SWZ128((uint32_t)(r * 128 + j * 16));
        cpa16(sb + off,         wHi + (long)(m0 + r) * K16 + c * 8 + j);
        cpa16(sb + 16384 + off, wLo + (long)(m0 + r) * K16 + c * 8 + j);
    }
#pragma unroll
    for (int l = 0; l < 2; l++) {
        int e = tid + l * 256;
        int r = e >> 3, j = e & 7;
        uint32_t off = SWZ128((uint32_t)(r * 128 + j * 16));
        cpa16(sb + 32768 + off, bHi + (long)(n0 + r) * K16 + c * 8 + j);
    }
}

// implicit 3x3 conv B loader: B is yi in fp16 [n][256]; chunk c (64 wide) -> tap (c>>2), quarter (c&3)
__device__ __forceinline__ void mgc_load(uint32_t smb, int tid,
    const uint4* __restrict__ wHi, const uint4* __restrict__ wLo,
    const uint4* __restrict__ bHi,
    int m0, int n0, int K16, int c, uint32_t stOff)
{
    uint32_t sb = smb + stOff;
#pragma unroll
    for (int l = 0; l < 4; l++) {
        int e = tid + l * 256;
        int r = e >> 3, j = e & 7;
        uint32_t off = SWZ128((uint32_t)(r * 128 + j * 16));
        cpa16(sb + off,         wHi + (long)(m0 + r) * K16 + c * 8 + j);
        cpa16(sb + 16384 + off, wLo + (long)(m0 + r) * K16 + c * 8 + j);
    }
    int tap = c >> 2, q = c & 3;
    int dy = tap / 3 - 1, dx = tap % 3 - 1;
#pragma unroll
    for (int l = 0; l < 2; l++) {
        int e = tid + l * 256;
        int r = e >> 3, j = e & 7;
        int pix = n0 + r;
        int y = (pix >> 5) + dy, x = (pix & 31) + dx;
        bool ok = ((unsigned)y < 32u) && ((unsigned)x < 32u);
        int ps = ok ? (y * 32 + x) : 0;
        int sz = ok ? 16 : 0;
        uint32_t off = SWZ128((uint32_t)(r * 128 + j * 16));
        cpa16z(sb + 32768 + off, bHi + (long)ps * 32 + q * 8 + j, sz);
    }
}

template <int CONV>
__global__ void __launch_bounds__(256, 2) mgemm64_kernel_t(
    const uint16_t* __restrict__ Bhi,
    const uint16_t* __restrict__ Whi, const uint16_t* __restrict__ Wlo,
    int K, int bK,
    float* __restrict__ Out, uint16_t* __restrict__ OutH, long outStride,
    uint16_t* __restrict__ OutB,
    const float* __restrict__ scale, const float* __restrict__ bias,
    const float* __restrict__ Res, long resStride,
    int doSilu)
{
    int b = blockIdx.z, m0 = blockIdx.y * 128, n0 = blockIdx.x * 64;
    int tid = threadIdx.x, wid = tid >> 5, lane = tid & 31;
    int warp_m = wid & 3, warp_n = wid >> 2;
    uint32_t smb = smem_u32(mg_smem);

    int K16 = K >> 3;
    const uint4* wHi = (const uint4*)Whi;
    const uint4* wLo = (const uint4*)Wlo;
    const uint4* bHi = (const uint4*)(Bhi + (long)b * 1024 * bK);

    float acc[2][4][4];
#pragma unroll
    for (int i = 0; i < 2; i++)
#pragma unroll
        for (int j = 0; j < 4; j++)
#pragma unroll
            for (int r = 0; r < 4; r++) acc[i][j][r] = 0.f;

    int nChunks = K >> 6;
    if (CONV) mgc_load(smb, tid, wHi, wLo, bHi, m0, n0, K16, 0, 0);
    else      mg64_load(smb, tid, wHi, wLo, bHi, m0, n0, K16, 0, 0);
    CPA_COMMIT();

    int aRowL = warp_m * 32 + (lane & 7) + (lane & 8);
    int aColL = ((lane >> 4) & 1) * 16;
    int bRowX4 = warp_n * 32 + (lane >> 4) * 8 + (lane & 7);
    uint32_t bColX4 = (uint32_t)(((lane >> 3) & 1) * 16);

    for (int c = 0; c < nChunks; c++) {
        int s = c & 1;
        CPA_WAIT0();
        __syncthreads();
        if (c + 1 < nChunks) {
            if (CONV) mgc_load(smb, tid, wHi, wLo, bHi, m0, n0, K16, c + 1, (uint32_t)((s ^ 1) * MG64_STAGE));
            else      mg64_load(smb, tid, wHi, wLo, bHi, m0, n0, K16, c + 1, (uint32_t)((s ^ 1) * MG64_STAGE));
            CPA_COMMIT();
        }

        uint32_t base = smb + (uint32_t)(s * MG64_STAGE);
#pragma unroll
        for (int ks = 0; ks < 4; ks++) {
            uint32_t ah[2][4], bh4[2][4];
#pragma unroll
            for (int mt = 0; mt < 2; mt++)
                ldsm_x4(ah[mt], base + SWZ128((uint32_t)((aRowL + mt * 16) * 128 + aColL + ks * 32)));
#pragma unroll
            for (int p = 0; p < 2; p++)
                ldsm_x4(bh4[p], base + 32768 + SWZ128((uint32_t)((bRowX4 + p * 16) * 128 + bColX4 + ks * 32)));
#pragma unroll
            for (int mt = 0; mt < 2; mt++)
#pragma unroll
                for (int p = 0; p < 2; p++) {
                    mma16816f(acc[mt][2 * p],     ah[mt], &bh4[p][0]);
                    mma16816f(acc[mt][2 * p + 1], ah[mt], &bh4[p][2]);
                }

            uint32_t al[2][4];
#pragma unroll
            for (int mt = 0; mt < 2; mt++)
                ldsm_x4(al[mt], base + 16384 + SWZ128((uint32_t)((aRowL + mt * 16) * 128 + aColL + ks * 32)));
#pragma unroll
            for (int mt = 0; mt < 2; mt++)
#pragma unroll
                for (int p = 0; p < 2; p++) {
                    mma16816f(acc[mt][2 * p],     al[mt], &bh4[p][0]);
                    mma16816f(acc[mt][2 * p + 1], al[mt], &bh4[p][2]);
                }
        }
    }

    float* stage = (float*)mg_smem;   // [64][132] when OutB
    if (OutB) __syncthreads();

#pragma unroll
    for (int mt = 0; mt < 2; mt++) {
        int mlB = warp_m * 32 + mt * 16 + (lane >> 2);
#pragma unroll
        for (int h2 = 0; h2 < 2; h2++) {
            int ml = mlB + h2 * 8;
            int m = m0 + ml;
            float s = 1.f, bb = 0.f;
            if (scale) { s = scale[m]; bb = bias[m]; }
            long rowOff = (long)b * outStride + (long)m * HW;
            long resOff = Res ? ((long)b * resStride + (long)m * HW) : 0;
#pragma unroll
            for (int nt = 0; nt < 4; nt++) {
                int nl = warp_n * 32 + nt * 8 + (lane & 3) * 2;
                int n = n0 + nl;
                float v0 = acc[mt][nt][h2 * 2 + 0] * s + bb;
                float v1 = acc[mt][nt][h2 * 2 + 1] * s + bb;
                if (doSilu) { v0 = silu_f(v0); v1 = silu_f(v1); }
                if (Res) {
                    float2 r2 = *(const float2*)&Res[resOff + n];
                    v0 += r2.x; v1 += r2.y;
                }
                if (Out) *(float2*)&Out[rowOff + n] = make_float2(v0, v1);
                if (OutH) {
                    __half2 hv = __floats2half2_rn(v0, v1);
                    *(__half2*)&OutH[rowOff + n] = hv;
                }
                if (OutB) {
                    stage[nl * 132 + ml] = v0;
                    stage[(nl + 1) * 132 + ml] = v1;
                }
            }
        }
    }

    if (OutB) {
        __syncthreads();
        for (int e = tid; e < 4096; e += 256) {
            int row = e >> 6, c2 = e & 63;
            float v0 = stage[row * 132 + c2 * 2];
            float v1 = stage[row * 132 + c2 * 2 + 1];
            __half2 hv = __floats2half2_rn(v0, v1);
            *(__half2*)&OutB[((long)b * 1024 + n0 + row) * 256 + m0 + c2 * 2] = hv;
        }
    }
}

// ---------------- attention converter: qkv fp16 -> qT/kT(+relpos)/v bf16 hi/lo ----------------
__global__ void convAttn_kernel(const uint16_t* __restrict__ QKVH,
                                const float* __restrict__ RW, const float* __restrict__ RH,
                                __nv_bfloat16* __restrict__ Hi, __nv_bfloat16* __restrict__ Lo)
{
    __shared__ float tq[32][33], tk[32][33];
    int it = blockIdx.x, dt = blockIdx.y, bh = blockIdx.z;
    int b = bh >> 2, hh = bh & 3;
    int tx = threadIdx.x, ty = threadIdx.y;
    const __half* base = (const __half*)QKVH + (long)b * 768 * HW;
#pragma unroll
    for (int l = 0; l < 4; l++) {
        int d = dt * 32 + ty + l * 8;
        int ch = hh * 64 + d;
        float qv = __half2float(base[(long)ch * HW + it * 32 + tx]) * 0.125f;
        float kv = __half2float(base[(long)(256 + ch) * HW + it * 32 + tx]) + RW[ch * 32 + tx] + RH[ch * 32 + it];
        float vv = __half2float(base[(long)(512 + ch) * HW + it * 32 + tx]);
        tq[ty + l * 8][tx] = qv;
        tk[ty + l * 8][tx] = kv;
        long vo = V_OFF + ((long)bh * 64 + d) * 1024 + it * 32 + tx;
        __nv_bfloat16 vh = __float2bfloat16(vv);
        Hi[vo] = vh;
        Lo[vo] = __float2bfloat16(vv - __bfloat162float(vh));
    }
    __syncthreads();
#pragma unroll
    for (int l = 0; l < 4; l++) {
        int i = it * 32 + ty + l * 8;
        int d = dt * 32 + tx;
        float qv = tq[tx][ty + l * 8];
        float kv = tk[tx][ty + l * 8];
        long qo = ((long)bh * 1024 + i) * 64 + d;
        __nv_bfloat16 qh = __float2bfloat16(qv);
        Hi[QT_OFF + qo] = qh;
        Lo[QT_OFF + qo] = __float2bfloat16(qv - __bfloat162float(qh));
        __nv_bfloat16 kh = __float2bfloat16(kv);
        Hi[KT_OFF + qo] = kh;
        Lo[KT_OFF + qo] = __float2bfloat16(kv - __bfloat162float(kh));
    }
}

// ---------------- MMA flash attention (bf16 split-3), emits B-layout fp16 ----------------
#define AT_SMEM 163840

__device__ __forceinline__ void kv_load(uint32_t smb, int tid,
    const __nv_bfloat16* __restrict__ kTh, const __nv_bfloat16* __restrict__ kTl,
    const __nv_bfloat16* __restrict__ vH, const __nv_bfloat16* __restrict__ vL,
    int bh, int t, uint32_t stOff)
{
    uint32_t kb = smb + stOff;
    const uint4* kh4 = (const uint4*)(kTh + ((long)bh * 1024 + t * 128) * 64);
    const uint4* kl4 = (const uint4*)(kTl + ((long)bh * 1024 + t * 128) * 64);
    int r = tid >> 1, j0 = (tid & 1) * 4;
#pragma unroll
    for (int j = 0; j < 4; j++) {
        uint32_t off = SWZ128((uint32_t)(r * 128 + (j0 + j) * 16));
        cpa16(kb + off, kh4 + (long)r * 8 + j0 + j);
        cpa16(kb + 16384 + off, kl4 + (long)r * 8 + j0 + j);
    }
    const uint4* vh4 = (const uint4*)(vH + (long)bh * 65536 + t * 128);
    const uint4* vl4 = (const uint4*)(vL + (long)bh * 65536 + t * 128);
    int d = tid >> 2, jc0 = (tid & 3) * 4;
#pragma unroll
    for (int j = 0; j < 4; j++) {
        int jc = jc0 + j;
        uint32_t off = (uint32_t)((jc >> 3) * 8192) + SWZ128((uint32_t)(d * 128 + (jc & 7) * 16));
        cpa16(kb + 32768 + off, vh4 + (long)d * 128 + jc);
        cpa16(kb + 49152 + off, vl4 + (long)d * 128 + jc);
    }
}

extern __shared__ char at_smem[];

__global__ void __launch_bounds__(256) attn_mma_kernel(
    const __nv_bfloat16* __restrict__ Hi, const __nv_bfloat16* __restrict__ Lo,
    uint16_t* __restrict__ OutB)
{
    int qt = blockIdx.x, h = blockIdx.y, b = blockIdx.z;
    int bh = b * 4 + h;
    int tid = threadIdx.x, wid = tid >> 5, lane = tid & 31, li = lane & 15;
    uint32_t smb = smem_u32(at_smem);

    const __nv_bfloat16* qTh = Hi + QT_OFF;
    const __nv_bfloat16* qTl = Lo + QT_OFF;
    const __nv_bfloat16* kTh = Hi + KT_OFF;
    const __nv_bfloat16* kTl = Lo + KT_OFF;
    const __nv_bfloat16* vH  = Hi + V_OFF;
    const __nv_bfloat16* vL  = Lo + V_OFF;

    {
        const uint4* qh4 = (const uint4*)(qTh + ((long)bh * 1024 + qt * 128) * 64);
        const uint4* ql4 = (const uint4*)(qTl + ((long)bh * 1024 + qt * 128) * 64);
        int r = tid >> 1, j0 = (tid & 1) * 4;
        uint32_t qb = smb + 131072;
#pragma unroll
        for (int j = 0; j < 4; j++) {
            uint32_t off = SWZ128((uint32_t)(r * 128 + (j0 + j) * 16));
            cpa16(qb + off, qh4 + (long)r * 8 + j0 + j);
            cpa16(qb + 16384 + off, ql4 + (long)r * 8 + j0 + j);
        }
    }
    CPA_COMMIT();
    kv_load(smb, tid, kTh, kTl, vH, vL, bh, 0, 0);
    CPA_COMMIT();
    CPA_WAIT1();
    __syncthreads();

    uint32_t qfh[4][4], qfl[4][4];
    {
        int aRow = wid * 16 + (lane & 7) + (lane & 8);
        int aCol = ((lane >> 4) & 1) * 16;
#pragma unroll
        for (int ks = 0; ks < 4; ks++) {
            uint32_t off = SWZ128((uint32_t)(aRow * 128 + aCol + ks * 32));
            ldsm_x4(qfh[ks], smb + 131072 + off);
            ldsm_x4(qfl[ks], smb + 131072 + 16384 + off);
        }
    }

    float oacc[8][4];
#pragma unroll
    for (int i = 0; i < 8; i++)
#pragma unroll
        for (int j = 0; j < 4; j++) oacc[i][j] = 0.f;
    float m0 = -1e30f, m1 = -1e30f, l0 = 0.f, l1 = 0.f;

    int sRowX4 = (lane >> 4) * 8 + (lane & 7);
    uint32_t sColX4 = (uint32_t)(((lane >> 3) & 1) * 16);

    for (int t = 0; t < 8; t++) {
        int s = t & 1;
        if (t < 7) {
            kv_load(smb, tid, kTh, kTl, vH, vL, bh, t + 1, (uint32_t)((s ^ 1) * 65536));
            CPA_COMMIT();
            CPA_WAIT1();
        } else {
            CPA_WAIT0();
        }
        __syncthreads();

        uint32_t kb = smb + s * 65536;
        float sacc[16][4];
#pragma unroll
        for (int i = 0; i < 16; i++)
#pragma unroll
            for (int j = 0; j < 4; j++) sacc[i][j] = 0.f;

#pragma unroll
        for (int p = 0; p < 8; p++) {
            int rowB = p * 16 + sRowX4;
#pragma unroll
            for (int ks = 0; ks < 4; ks++) {
                uint32_t off = SWZ128((uint32_t)(rowB * 128 + sColX4 + ks * 32));
                uint32_t kh4[4], kl4[4];
                ldsm_x4(kh4, kb + off);
                ldsm_x4(kl4, kb + 16384 + off);
                mma16816(sacc[2 * p],     qfh[ks], &kh4[0]);
                mma16816(sacc[2 * p + 1], qfh[ks], &kh4[2]);
                mma16816(sacc[2 * p],     qfl[ks], &kh4[0]);
                mma16816(sacc[2 * p + 1], qfl[ks], &kh4[2]);
                mma16816(sacc[2 * p],     qfh[ks], &kl4[0]);
                mma16816(sacc[2 * p + 1], qfh[ks], &kl4[2]);
            }
        }

        float mx0 = m0, mx1 = m1;
#pragma unroll
        for (int nt = 0; nt < 16; nt++) {
            mx0 = fmaxf(mx0, fmaxf(sacc[nt][0], sacc[nt][1]));
            mx1 = fmaxf(mx1, fmaxf(sacc[nt][2], sacc[nt][3]));
        }
        mx0 = fmaxf(mx0, __shfl_xor_sync(0xffffffffu, mx0, 1));
        mx0 = fmaxf(mx0, __shfl_xor_sync(0xffffffffu, mx0, 2));
        mx1 = fmaxf(mx1, __shfl_xor_sync(0xffffffffu, mx1, 1));
        mx1 = fmaxf(mx1, __shfl_xor_sync(0xffffffffu, mx1, 2));
        float a0 = __expf(m0 - mx0), a1 = __expf(m1 - mx1);
        m0 = mx0; m1 = mx1;

        float ls0 = 0.f, ls1 = 0.f;
        uint32_t pah[8][4], pal[8][4];
#pragma unroll
        for (int kj = 0; kj < 8; kj++) {
            float p00 = __expf(sacc[2 * kj][0] - m0);
            float p01 = __expf(sacc[2 * kj][1] - m0);
            float p02 = __expf(sacc[2 * kj][2] - m1);
            float p03 = __expf(sacc[2 * kj][3] - m1);
            float p10 = __expf(sacc[2 * kj + 1][0] - m0);
            float p11 = __expf(sacc[2 * kj + 1][1] - m0);
            float p12 = __expf(sacc[2 * kj + 1][2] - m1);
            float p13 = __expf(sacc[2 * kj + 1][3] - m1);
            ls0 += p00 + p01 + p10 + p11;
            ls1 += p02 + p03 + p12 + p13;
            pah[kj][0] = packbf(p00, p01);
            pah[kj][1] = packbf(p02, p03);
            pah[kj][2] = packbf(p10, p11);
            pah[kj][3] = packbf(p12, p13);
            float q00 = p00 - __bfloat162float(__float2bfloat16(p00));
            float q01 = p01 - __bfloat162float(__float2bfloat16(p01));
            float q02 = p02 - __bfloat162float(__float2bfloat16(p02));
            float q03 = p03 - __bfloat162float(__float2bfloat16(p03));
            float q10 = p10 - __bfloat162float(__float2bfloat16(p10));
            float q11 = p11 - __bfloat162float(__float2bfloat16(p11));
            float q12 = p12 - __bfloat162float(__float2bfloat16(p12));
            float q13 = p13 - __bfloat162float(__float2bfloat16(p13));
            pal[kj][0] = packbf(q00, q01);
            pal[kj][1] = packbf(q02, q03);
            pal[kj][2] = packbf(q10, q11);
            pal[kj][3] = packbf(q12, q13);
        }
        ls0 += __shfl_xor_sync(0xffffffffu, ls0, 1);
        ls0 += __shfl_xor_sync(0xffffffffu, ls0, 2);
        ls1 += __shfl_xor_sync(0xffffffffu, ls1, 1);
        ls1 += __shfl_xor_sync(0xffffffffu, ls1, 2);
        l0 = l0 * a0 + ls0;
        l1 = l1 * a1 + ls1;
#pragma unroll
        for (int dt = 0; dt < 8; dt++) {
            oacc[dt][0] *= a0; oacc[dt][1] *= a0;
            oacc[dt][2] *= a1; oacc[dt][3] *= a1;
        }

#pragma unroll
        for (int dt = 0; dt < 8; dt++) {
            int rowV = dt * 8 + (li & 7);
#pragma unroll
            for (int kj = 0; kj < 8; kj++) {
                uint32_t off = (uint32_t)((kj >> 2) * 8192) +
                               SWZ128((uint32_t)(rowV * 128 + (li >> 3) * 16 + (kj & 3) * 32));
                uint32_t vh2[2], vl2[2];
                ldsm_x2(vh2, kb + 32768 + off);
                ldsm_x2(vl2, kb + 49152 + off);
                mma16816(oacc[dt], pah[kj], vh2);
                mma16816(oacc[dt], pal[kj], vh2);
                mma16816(oacc[dt], pah[kj], vl2);
            }
        }
        __syncthreads();
    }

    float i0 = 1.f / l0, i1 = 1.f / l1;
    float* stg = (float*)at_smem;   // [128][66]
    int r0 = wid * 16 + (lane >> 2);
#pragma unroll
    for (int dt = 0; dt < 8; dt++) {
        int d = dt * 8 + (lane & 3) * 2;
        stg[r0 * 66 + d]           = oacc[dt][0] * i0;
        stg[r0 * 66 + d + 1]       = oacc[dt][1] * i0;
        stg[(r0 + 8) * 66 + d]     = oacc[dt][2] * i1;
        stg[(r0 + 8) * 66 + d + 1] = oacc[dt][3] * i1;
    }
    __syncthreads();
    // emit B-layout fp16: [n = global token][k = 256 channels]
    for (int e = tid; e < 4096; e += 256) {
        int i = e >> 5, dp = (e & 31) * 2;
        __half2 hv = __floats2half2_rn(stg[i * 66 + dp], stg[i * 66 + dp + 1]);
        *(__half2*)&OutB[((long)b * 1024 + qt * 128 + i) * 256 + h * 64 + dp] = hv;
    }
}

// ---------------- launch ----------------
extern "C" void kernel_launch(void* const* d_in, const int* in_sizes, int n_in,
                              void* d_out, int out_size)
{
    const float* x      = (const float*)d_in[0];
    const float* cv1_w  = (const float*)d_in[1];
    const float* cv1_bn = (const float*)d_in[2];
    const float* cv2_w  = (const float*)d_in[3];
    const float* cv2_bn = (const float*)d_in[4];
    const float* mcv1w  = (const float*)d_in[5];
    const float* mcv1bn = (const float*)d_in[6];
    const float* mqkvw  = (const float*)d_in[7];
    const float* mrw    = (const float*)d_in[8];
    const float* mrh    = (const float*)d_in[9];
    const float* mcv2w  = (const float*)d_in[10];
    const float* mcv2bn = (const float*)d_in[11];
    float* out = (float*)d_out;

    float *cat, *scl, *bia;
    uint16_t *catH, *qkvH, *whi, *wlo, *bhi, *blo;
    cudaGetSymbolAddress((void**)&cat,   g_cat);
    cudaGetSymbolAddress((void**)&catH,  g_catH);
    cudaGetSymbolAddress((void**)&qkvH,  g_qkvH);
    cudaGetSymbolAddress((void**)&scl,   g_scale);
    cudaGetSymbolAddress((void**)&bia,   g_bias);
    cudaGetSymbolAddress((void**)&whi,   g_Whi);
    cudaGetSymbolAddress((void**)&wlo,   g_Wlo);
    cudaGetSymbolAddress((void**)&bhi,   g_Bhi);
    cudaGetSymbolAddress((void**)&blo,   g_Blo);
    __nv_bfloat16* bhiB = (__nv_bfloat16*)bhi;
    __nv_bfloat16* bloB = (__nv_bfloat16*)blo;

    cudaFuncSetAttribute(mgemm_kernel, cudaFuncAttributeMaxDynamicSharedMemorySize, MG_SMEM);
    cudaFuncSetAttribute(mgemm64_kernel_t<0>, cudaFuncAttributeMaxDynamicSharedMemorySize, MG64_SMEM);
    cudaFuncSetAttribute(mgemm64_kernel_t<1>, cudaFuncAttributeMaxDynamicSharedMemorySize, MG64_SMEM);
    cudaFuncSetAttribute(attn_mma_kernel, cudaFuncAttributeMaxDynamicSharedMemorySize, AT_SMEM);

    fold_bn_kernel<<<8, 256>>>(cv1_bn, cv2_bn, mcv1bn, mcv2bn);
    convW_all_kernel<<<(W_TOTAL + 255) / 256, 256>>>(cv1_w, mcv1w, mqkvw, mcv2w, cv2_w, whi, wlo);

    // ---- cv1: 512 -> 512, BN+SiLU -> fp32 cat[0:512) + fp16 catH[0:512) ----
    convB_kernel<float><<<dim3(32, 16, 8), dim3(32, 8)>>>(x, (long)512 * HW, 512, bhi + B0_OFF);
    mgemm_kernel<<<dim3(8, 4, 8), 256, MG_SMEM>>>(
        bhi + B0_OFF, whi + W_CV1, wlo + W_CV1, 512, cat, catH, (long)1024 * HW,
        scl + 0, bia + 0, nullptr, 0, 1);

    for (int i = 0; i < 2; i++) {
        long yin  = (long)(i == 0 ? 256 : 512) * HW;
        long yout = (long)(512 + i * 256) * HW;
        long wConv = i ? W_CONV1 : W_CONV0;
        long wQkv  = i ? W_QKV1  : W_QKV0;
        long wCv2  = i ? W_CV2M1 : W_CV2M0;

        // z = cbs(yi, 3x3) as IMPLICIT GEMM; emits fp16 B-layout ZB directly
        convB_kernel<__half><<<dim3(32, 8, 8), dim3(32, 8)>>>(
            (const __half*)(catH + yin), (long)1024 * HW, 256, bhi + B0_OFF);
        mgemm64_kernel_t<1><<<dim3(16, 2, 8), 256, MG64_SMEM>>>(
            bhi + B0_OFF, whi + wConv, wlo + wConv, 2304, 256,
            nullptr, nullptr, 0, bhi + ZB_OFF,
            scl + 1024 + i * 256, bia + 1024 + i * 256, nullptr, 0, 1);

        // qkv = conv1x1(z), 256 -> 768 (reads ZB directly); output fp16 qkvH
        mgemm_kernel<<<dim3(8, 6, 8), 256, MG_SMEM>>>(
            bhi + ZB_OFF, whi + wQkv, wlo + wQkv, 256, nullptr, qkvH, (long)768 * HW,
            nullptr, nullptr, nullptr, 0, 0);

        // attention operand conversion + MMA flash attention -> fp16 B-layout ATB
        convAttn_kernel<<<dim3(32, 2, 32), dim3(32, 8)>>>(
            qkvH, mrw + (long)i * 8192, mrh + (long)i * 8192, bhiB, bloB);
        attn_mma_kernel<<<dim3(8, 4, 8), 256, AT_SMEM>>>(bhiB, bloB, bhi + ATB_OFF);

        // y_{i+2} = yi + silu(bn(conv1x1(attn))) (reads ATB) -> fp32 cat + fp16 catH
        mgemm64_kernel_t<0><<<dim3(16, 2, 8), 256, MG64_SMEM>>>(
            bhi + ATB_OFF, whi + wCv2, wlo + wCv2, 256, 256,
            cat + yout, catH + yout, (long)1024 * HW, nullptr,
            scl + 1536 + i * 256, bia + 1536 + i * 256, cat + yin, (long)1024 * HW, 1);
    }

    // ---- final: 1024 -> 512, BN+SiLU, fp32 out ----
    convB_kernel<__half><<<dim3(32, 32, 8), dim3(32, 8)>>>(
        (const __half*)catH, (long)1024 * HW, 1024, bhi + B0_OFF);
    mgemm_kernel<<<dim3(8, 4, 8), 256, MG_SMEM>>>(
        bhi + B0_OFF, whi + W_FIN, wlo + W_FIN, 1024, out, nullptr, (long)512 * HW,
        scl + 512, bia + 512, nullptr, 0, 1);
}

// round 13
// speedup vs baseline: 2.0368x; 1.2142x over previous
#include <cuda_runtime.h>
#include <cuda_bf16.h>
#include <cuda_fp16.h>
#include <cstdint>

#define HW 1024

// ---------------- scratch (__device__ globals: alloc-guard-safe) ----------------
__device__ float    g_cat  [8u * 1024u * HW];   // 32 MB fp32 (residual path)
__device__ uint16_t g_catH [8u * 1024u * HW];   // 16 MB fp16 shadow
__device__ uint16_t g_qkvH [8u * 768u  * HW];   // fp16 qkv
__device__ float g_scale[2048];
__device__ float g_bias [2048];
__device__ uint16_t g_Whi[2490368];
__device__ uint16_t g_Bhi[18874368];
__device__ uint16_t g_Blo[18874368];

// arena offsets (elements) inside g_Bhi
#define B0_OFF  0u          // generic B buffer (up to K=1024)
#define ZB_OFF  8388608u    // conv output in B-layout [n][256]
#define ATB_OFF 10485760u   // attention output in B-layout [n][256]
#define QT_OFF  12582912    // bf16 attn operands (also in g_Blo)
#define KT_OFF  14680064
#define V_OFF   16777216

// weight arena offsets
#define W_CV1   0
#define W_CONV0 262144
#define W_CONV1 851968
#define W_QKV0  1441792
#define W_QKV1  1638400
#define W_CV2M0 1835008
#define W_CV2M1 1900544
#define W_FIN   1966080
#define W_TOTAL 2490368

__device__ __forceinline__ float silu_f(float v) { return v / (1.f + __expf(-v)); }

__device__ __forceinline__ uint32_t smem_u32(const void* p) {
    uint32_t a;
    asm("{ .reg .u64 t; cvta.to.shared.u64 t, %1; cvt.u32.u64 %0, t; }" : "=r"(a) : "l"(p));
    return a;
}
#define SWZ128(o) ((o) ^ (((o) >> 3) & 0x70))

__device__ __forceinline__ void ldsm_x4(uint32_t* r, uint32_t a) {
    asm volatile("ldmatrix.sync.aligned.m8n8.x4.shared.b16 {%0,%1,%2,%3}, [%4];"
        : "=r"(r[0]), "=r"(r[1]), "=r"(r[2]), "=r"(r[3]) : "r"(a));
}
__device__ __forceinline__ void ldsm_x2(uint32_t* r, uint32_t a) {
    asm volatile("ldmatrix.sync.aligned.m8n8.x2.shared.b16 {%0,%1}, [%2];"
        : "=r"(r[0]), "=r"(r[1]) : "r"(a));
}
__device__ __forceinline__ void mma16816(float* d, const uint32_t* a, const uint32_t* b) {
    asm volatile("mma.sync.aligned.m16n8k16.row.col.f32.bf16.bf16.f32 "
        "{%0,%1,%2,%3}, {%4,%5,%6,%7}, {%8,%9}, {%0,%1,%2,%3};"
        : "+f"(d[0]), "+f"(d[1]), "+f"(d[2]), "+f"(d[3])
        : "r"(a[0]), "r"(a[1]), "r"(a[2]), "r"(a[3]), "r"(b[0]), "r"(b[1]));
}
__device__ __forceinline__ void mma16816f(float* d, const uint32_t* a, const uint32_t* b) {
    asm volatile("mma.sync.aligned.m16n8k16.row.col.f32.f16.f16.f32 "
        "{%0,%1,%2,%3}, {%4,%5,%6,%7}, {%8,%9}, {%0,%1,%2,%3};"
        : "+f"(d[0]), "+f"(d[1]), "+f"(d[2]), "+f"(d[3])
        : "r"(a[0]), "r"(a[1]), "r"(a[2]), "r"(a[3]), "r"(b[0]), "r"(b[1]));
}
__device__ __forceinline__ void cpa16(uint32_t d, const void* s) {
    asm volatile("cp.async.cg.shared.global [%0], [%1], 16;" :: "r"(d), "l"(s));
}
__device__ __forceinline__ void cpa16z(uint32_t d, const void* s, int sz) {
    asm volatile("cp.async.cg.shared.global [%0], [%1], 16, %2;" :: "r"(d), "l"(s), "r"(sz));
}
#define CPA_COMMIT() asm volatile("cp.async.commit_group;" ::: "memory")
#define CPA_WAIT1()  asm volatile("cp.async.wait_group 1;" ::: "memory")
#define CPA_WAIT0()  asm volatile("cp.async.wait_group 0;" ::: "memory")

__device__ __forceinline__ uint32_t packbf(float lo, float hi) {
    uint32_t r;
    asm("cvt.rn.bf16x2.f32 %0, %1, %2;" : "=r"(r) : "f"(hi), "f"(lo));
    return r;
}

// ---------------- BN fold ----------------
__global__ void fold_bn_kernel(const float* __restrict__ cv1, const float* __restrict__ cv2,
                               const float* __restrict__ mcv1, const float* __restrict__ mcv2)
{
    int c = blockIdx.x * 256 + threadIdx.x;
    if (c >= 2048) return;
    const float* p; int C, lc;
    if (c < 512)        { p = cv1;  C = 512; lc = c; }
    else if (c < 1024)  { p = cv2;  C = 512; lc = c - 512; }
    else if (c < 1536)  { int i = (c - 1024) >> 8; p = mcv1 + i * 1024; C = 256; lc = (c - 1024) & 255; }
    else                { int i = (c - 1536) >> 8; p = mcv2 + i * 1024; C = 256; lc = (c - 1536) & 255; }
    float g = p[lc], b = p[C + lc], m = p[2 * C + lc], v = p[3 * C + lc];
    float s = g / sqrtf(v + 1e-3f);
    g_scale[c] = s;
    g_bias[c]  = b - m * s;
}

// ---------------- fused weight converter: all weights fp32 -> fp16 ----------------
__global__ void convW_all_kernel(const float* __restrict__ cv1w, const float* __restrict__ mcv1w,
                                 const float* __restrict__ mqkvw, const float* __restrict__ mcv2w,
                                 const float* __restrict__ cv2w,
                                 uint16_t* __restrict__ Whi)
{
    long e = (long)blockIdx.x * 256 + threadIdx.x;
    if (e >= W_TOTAL) return;
    const float* W; long rel; int K; int isConv = 0;
    if (e < W_CONV0)      { W = cv1w; rel = e; K = 512; }
    else if (e < W_QKV0)  { long r = e - W_CONV0; int i = r >= 589824; rel = r - (long)i * 589824;
                            W = mcv1w + (long)i * 589824; K = 2304; isConv = 1; }
    else if (e < W_CV2M0) { long r = e - W_QKV0; int i = r >= 196608; rel = r - (long)i * 196608;
                            W = mqkvw + (long)i * 196608; K = 256; }
    else if (e < W_FIN)   { long r = e - W_CV2M0; int i = r >= 65536; rel = r - (long)i * 65536;
                            W = mcv2w + (long)i * 65536; K = 256; }
    else                  { W = cv2w; rel = e - W_FIN; K = 1024; }
    long m = rel / K, k = rel % K;
    float v;
    if (isConv) { int off = (int)(k >> 8), ci = (int)(k & 255); v = W[m * 2304 + ci * 9 + off]; }
    else v = W[rel];
    Whi[e] = __half_as_ushort(__float2half(v));
}

// ---------------- activation transposer: [b][K][HW] (T) -> fp16 [b][n][K] ----------------
template <typename T>
__global__ void convB_kernel(const T* __restrict__ In, long inStride, int K,
                             uint16_t* __restrict__ Bhi)
{
    __shared__ float t[32][33];
    int n0 = blockIdx.x * 32, k0 = blockIdx.y * 32, b = blockIdx.z;
    int tx = threadIdx.x, ty = threadIdx.y;
    const T* in = In + (long)b * inStride;
#pragma unroll
    for (int yy = 0; yy < 32; yy += 8)
        t[yy + ty][tx] = (float)in[(long)(k0 + yy + ty) * HW + n0 + tx];
    __syncthreads();
#pragma unroll
    for (int yy = 0; yy < 32; yy += 8) {
        int n = n0 + yy + ty, k = k0 + tx;
        float v = t[tx][yy + ty];
        long o = ((long)b * 1024 + n) * K + k;
        Bhi[o] = __half_as_ushort(__float2half(v));
    }
}

// ---------------- warp-MMA GEMM (N-tile 128): fp16, K-chunk 64, 2-stage ----------------
#define MG_STAGE 32768
#define MG_SMEM  65536

__device__ __forceinline__ void mg_load(uint32_t smb, int tid,
    const uint4* __restrict__ wHi, const uint4* __restrict__ bHi,
    int m0, int n0, int K16, int c, uint32_t stOff)
{
    uint32_t sb = smb + stOff;
#pragma unroll
    for (int l = 0; l < 4; l++) {
        int e = tid + l * 256;
        int r = e >> 3, j = e & 7;
        uint32_t off = SWZ128((uint32_t)(r * 128 + j * 16));
        cpa16(sb + off,         wHi + (long)(m0 + r) * K16 + c * 8 + j);
        cpa16(sb + 16384 + off, bHi + (long)(n0 + r) * K16 + c * 8 + j);
    }
}

extern __shared__ char mg_smem[];

__global__ void __launch_bounds__(256, 2) mgemm_kernel(
    const uint16_t* __restrict__ Bhi,
    const uint16_t* __restrict__ Whi,
    int K,
    float* __restrict__ Out, uint16_t* __restrict__ OutH, long outStride,
    const float* __restrict__ scale, const float* __restrict__ bias,
    const float* __restrict__ Res, long resStride,
    int doSilu)
{
    int b = blockIdx.z, m0 = blockIdx.y * 128, n0 = blockIdx.x * 128;
    int tid = threadIdx.x, wid = tid >> 5, lane = tid & 31;
    int warp_m = wid & 1, warp_n = wid >> 1;
    uint32_t smb = smem_u32(mg_smem);

    int K16 = K >> 3;
    const uint4* wHi = (const uint4*)Whi;
    const uint4* bHi = (const uint4*)(Bhi + (long)b * 1024 * K);

    float acc[4][4][4];
#pragma unroll
    for (int i = 0; i < 4; i++)
#pragma unroll
        for (int j = 0; j < 4; j++)
#pragma unroll
            for (int r = 0; r < 4; r++) acc[i][j][r] = 0.f;

    int nChunks = K >> 6;
    mg_load(smb, tid, wHi, bHi, m0, n0, K16, 0, 0);
    CPA_COMMIT();

    int aRowL = warp_m * 64 + (lane & 7) + (lane & 8);
    int aColL = ((lane >> 4) & 1) * 16;
    int bRowX4 = warp_n * 32 + (lane >> 4) * 8 + (lane & 7);
    uint32_t bColX4 = (uint32_t)(((lane >> 3) & 1) * 16);

    for (int c = 0; c < nChunks; c++) {
        int s = c & 1;
        CPA_WAIT0();
        __syncthreads();
        if (c + 1 < nChunks) {
            mg_load(smb, tid, wHi, bHi, m0, n0, K16, c + 1, (uint32_t)((s ^ 1) * MG_STAGE));
            CPA_COMMIT();
        }

        uint32_t base = smb + (uint32_t)(s * MG_STAGE);
#pragma unroll
        for (int ks = 0; ks < 4; ks++) {
            uint32_t ah[4][4], bh4[2][4];
#pragma unroll
            for (int mt = 0; mt < 4; mt++)
                ldsm_x4(ah[mt], base + SWZ128((uint32_t)((aRowL + mt * 16) * 128 + aColL + ks * 32)));
#pragma unroll
            for (int p = 0; p < 2; p++)
                ldsm_x4(bh4[p], base + 16384 + SWZ128((uint32_t)((bRowX4 + p * 16) * 128 + bColX4 + ks * 32)));
#pragma unroll
            for (int mt = 0; mt < 4; mt++)
#pragma unroll
                for (int p = 0; p < 2; p++) {
                    mma16816f(acc[mt][2 * p],     ah[mt], &bh4[p][0]);
                    mma16816f(acc[mt][2 * p + 1], ah[mt], &bh4[p][2]);
                }
        }
    }

#pragma unroll
    for (int mt = 0; mt < 4; mt++) {
        int mb = m0 + warp_m * 64 + mt * 16 + (lane >> 2);
#pragma unroll
        for (int h2 = 0; h2 < 2; h2++) {
            int m = mb + h2 * 8;
            float s = 1.f, bb = 0.f;
            if (scale) { s = scale[m]; bb = bias[m]; }
            long rowOff = (long)b * outStride + (long)m * HW;
            long resOff = Res ? ((long)b * resStride + (long)m * HW) : 0;
#pragma unroll
            for (int nt = 0; nt < 4; nt++) {
                int n = n0 + warp_n * 32 + nt * 8 + (lane & 3) * 2;
                float v0 = acc[mt][nt][h2 * 2 + 0] * s + bb;
                float v1 = acc[mt][nt][h2 * 2 + 1] * s + bb;
                if (doSilu) { v0 = silu_f(v0); v1 = silu_f(v1); }
                if (Res) {
                    float2 r2 = *(const float2*)&Res[resOff + n];
                    v0 += r2.x; v1 += r2.y;
                }
                if (Out) *(float2*)&Out[rowOff + n] = make_float2(v0, v1);
                if (OutH) {
                    __half2 hv = __floats2half2_rn(v0, v1);
                    *(__half2*)&OutH[rowOff + n] = hv;
                }
            }
        }
    }
}

// ---------------- warp-MMA GEMM (N-tile 64): fp16, K-chunk 64, single-sync ----------------
#define MG64_STAGE 24576
#define MG64_SMEM  49152

__device__ __forceinline__ void mg64_load(uint32_t smb, int tid,
    const uint4* __restrict__ wHi, const uint4* __restrict__ bHi,
    int m0, int n0, int K16, int c, uint32_t stOff)
{
    uint32_t sb = smb + stOff;
#pragma unroll
    for (int l = 0; l < 4; l++) {
        int e = tid + l * 256;
        int r = e >> 3, j = e & 7;
        uint32_t off = SWZ128((uint32_t)(r * 128 + j * 16));
        cpa16(sb + off, wHi + (long)(m0 + r) * K16 + c * 8 + j);
    }
#pragma unroll
    for (int l = 0; l < 2; l++) {
        int e = tid + l * 256;
        int r = e >> 3, j = e & 7;
        uint32_t off = SWZ128((uint32_t)(r * 128 + j * 16));
        cpa16(sb + 16384 + off, bHi + (long)(n0 + r) * K16 + c * 8 + j);
    }
}

// implicit 3x3 conv B loader: B is yi in fp16 [n][256]; chunk c (64 wide) -> tap (c>>2), quarter (c&3)
__device__ __forceinline__ void mgc_load(uint32_t smb, int tid,
    const uint4* __restrict__ wHi, const uint4* __restrict__ bHi,
    int m0, int n0, int K16, int c, uint32_t stOff)
{
    uint32_t sb = smb + stOff;
#pragma unroll
    for (int l = 0; l < 4; l++) {
        int e = tid + l * 256;
        int r = e >> 3, j = e & 7;
        uint32_t off = SWZ128((uint32_t)(r * 128 + j * 16));
        cpa16(sb + off, wHi + (long)(m0 + r) * K16 + c * 8 + j);
    }
    int tap = c >> 2, q = c & 3;
    int dy = tap / 3 - 1, dx = tap % 3 - 1;
#pragma unroll
    for (int l = 0; l < 2; l++) {
        int e = tid + l * 256;
        int r = e >> 3, j = e & 7;
        int pix = n0 + r;
        int y = (pix >> 5) + dy, x = (pix & 31) + dx;
        bool ok = ((unsigned)y < 32u) && ((unsigned)x < 32u);
        int ps = ok ? (y * 32 + x) : 0;
        int sz = ok ? 16 : 0;
        uint32_t off = SWZ128((uint32_t)(r * 128 + j * 16));
        cpa16z(sb + 16384 + off, bHi + (long)ps * 32 + q * 8 + j, sz);
    }
}

template <int CONV>
__global__ void __launch_bounds__(256, 2) mgemm64_kernel_t(
    const uint16_t* __restrict__ Bhi,
    const uint16_t* __restrict__ Whi,
    int K, int bK,
    float* __restrict__ Out, uint16_t* __restrict__ OutH, long outStride,
    uint16_t* __restrict__ OutB,
    const float* __restrict__ scale, const float* __restrict__ bias,
    const float* __restrict__ Res, long resStride,
    int doSilu)
{
    int b = blockIdx.z, m0 = blockIdx.y * 128, n0 = blockIdx.x * 64;
    int tid = threadIdx.x, wid = tid >> 5, lane = tid & 31;
    int warp_m = wid & 3, warp_n = wid >> 2;
    uint32_t smb = smem_u32(mg_smem);

    int K16 = K >> 3;
    const uint4* wHi = (const uint4*)Whi;
    const uint4* bHi = (const uint4*)(Bhi + (long)b * 1024 * bK);

    float acc[2][4][4];
#pragma unroll
    for (int i = 0; i < 2; i++)
#pragma unroll
        for (int j = 0; j < 4; j++)
#pragma unroll
            for (int r = 0; r < 4; r++) acc[i][j][r] = 0.f;

    int nChunks = K >> 6;
    if (CONV) mgc_load(smb, tid, wHi, bHi, m0, n0, K16, 0, 0);
    else      mg64_load(smb, tid, wHi, bHi, m0, n0, K16, 0, 0);
    CPA_COMMIT();

    int aRowL = warp_m * 32 + (lane & 7) + (lane & 8);
    int aColL = ((lane >> 4) & 1) * 16;
    int bRowX4 = warp_n * 32 + (lane >> 4) * 8 + (lane & 7);
    uint32_t bColX4 = (uint32_t)(((lane >> 3) & 1) * 16);

    for (int c = 0; c < nChunks; c++) {
        int s = c & 1;
        CPA_WAIT0();
        __syncthreads();
        if (c + 1 < nChunks) {
            if (CONV) mgc_load(smb, tid, wHi, bHi, m0, n0, K16, c + 1, (uint32_t)((s ^ 1) * MG64_STAGE));
            else      mg64_load(smb, tid, wHi, bHi, m0, n0, K16, c + 1, (uint32_t)((s ^ 1) * MG64_STAGE));
            CPA_COMMIT();
        }

        uint32_t base = smb + (uint32_t)(s * MG64_STAGE);
#pragma unroll
        for (int ks = 0; ks < 4; ks++) {
            uint32_t ah[2][4], bh4[2][4];
#pragma unroll
            for (int mt = 0; mt < 2; mt++)
                ldsm_x4(ah[mt], base + SWZ128((uint32_t)((aRowL + mt * 16) * 128 + aColL + ks * 32)));
#pragma unroll
            for (int p = 0; p < 2; p++)
                ldsm_x4(bh4[p], base + 16384 + SWZ128((uint32_t)((bRowX4 + p * 16) * 128 + bColX4 + ks * 32)));
#pragma unroll
            for (int mt = 0; mt < 2; mt++)
#pragma unroll
                for (int p = 0; p < 2; p++) {
                    mma16816f(acc[mt][2 * p],     ah[mt], &bh4[p][0]);
                    mma16816f(acc[mt][2 * p + 1], ah[mt], &bh4[p][2]);
                }
        }
    }

    float* stage = (float*)mg_smem;   // [64][132] when OutB (33 KB < 48 KB)
    if (OutB) __syncthreads();

#pragma unroll
    for (int mt = 0; mt < 2; mt++) {
        int mlB = warp_m * 32 + mt * 16 + (lane >> 2);
#pragma unroll
        for (int h2 = 0; h2 < 2; h2++) {
            int ml = mlB + h2 * 8;
            int m = m0 + ml;
            float s = 1.f, bb = 0.f;
            if (scale) { s = scale[m]; bb = bias[m]; }
            long rowOff = (long)b * outStride + (long)m * HW;
            long resOff = Res ? ((long)b * resStride + (long)m * HW) : 0;
#pragma unroll
            for (int nt = 0; nt < 4; nt++) {
                int nl = warp_n * 32 + nt * 8 + (lane & 3) * 2;
                int n = n0 + nl;
                float v0 = acc[mt][nt][h2 * 2 + 0] * s + bb;
                float v1 = acc[mt][nt][h2 * 2 + 1] * s + bb;
                if (doSilu) { v0 = silu_f(v0); v1 = silu_f(v1); }
                if (Res) {
                    float2 r2 = *(const float2*)&Res[resOff + n];
                    v0 += r2.x; v1 += r2.y;
                }
                if (Out) *(float2*)&Out[rowOff + n] = make_float2(v0, v1);
                if (OutH) {
                    __half2 hv = __floats2half2_rn(v0, v1);
                    *(__half2*)&OutH[rowOff + n] = hv;
                }
                if (OutB) {
                    stage[nl * 132 + ml] = v0;
                    stage[(nl + 1) * 132 + ml] = v1;
                }
            }
        }
    }

    if (OutB) {
        __syncthreads();
        for (int e = tid; e < 4096; e += 256) {
            int row = e >> 6, c2 = e & 63;
            float v0 = stage[row * 132 + c2 * 2];
            float v1 = stage[row * 132 + c2 * 2 + 1];
            __half2 hv = __floats2half2_rn(v0, v1);
            *(__half2*)&OutB[((long)b * 1024 + n0 + row) * 256 + m0 + c2 * 2] = hv;
        }
    }
}

// ---------------- attention converter: qkv fp16 -> qT/kT(+relpos)/v bf16 hi/lo ----------------
__global__ void convAttn_kernel(const uint16_t* __restrict__ QKVH,
                                const float* __restrict__ RW, const float* __restrict__ RH,
                                __nv_bfloat16* __restrict__ Hi, __nv_bfloat16* __restrict__ Lo)
{
    __shared__ float tq[32][33], tk[32][33];
    int it = blockIdx.x, dt = blockIdx.y, bh = blockIdx.z;
    int b = bh >> 2, hh = bh & 3;
    int tx = threadIdx.x, ty = threadIdx.y;
    const __half* base = (const __half*)QKVH + (long)b * 768 * HW;
#pragma unroll
    for (int l = 0; l < 4; l++) {
        int d = dt * 32 + ty + l * 8;
        int ch = hh * 64 + d;
        float qv = __half2float(base[(long)ch * HW + it * 32 + tx]) * 0.125f;
        float kv = __half2float(base[(long)(256 + ch) * HW + it * 32 + tx]) + RW[ch * 32 + tx] + RH[ch * 32 + it];
        float vv = __half2float(base[(long)(512 + ch) * HW + it * 32 + tx]);
        tq[ty + l * 8][tx] = qv;
        tk[ty + l * 8][tx] = kv;
        long vo = V_OFF + ((long)bh * 64 + d) * 1024 + it * 32 + tx;
        __nv_bfloat16 vh = __float2bfloat16(vv);
        Hi[vo] = vh;
        Lo[vo] = __float2bfloat16(vv - __bfloat162float(vh));
    }
    __syncthreads();
#pragma unroll
    for (int l = 0; l < 4; l++) {
        int i = it * 32 + ty + l * 8;
        int d = dt * 32 + tx;
        float qv = tq[tx][ty + l * 8];
        float kv = tk[tx][ty + l * 8];
        long qo = ((long)bh * 1024 + i) * 64 + d;
        __nv_bfloat16 qh = __float2bfloat16(qv);
        Hi[QT_OFF + qo] = qh;
        Lo[QT_OFF + qo] = __float2bfloat16(qv - __bfloat162float(qh));
        __nv_bfloat16 kh = __float2bfloat16(kv);
        Hi[KT_OFF + qo] = kh;
        Lo[KT_OFF + qo] = __float2bfloat16(kv - __bfloat162float(kh));
    }
}

// ---------------- MMA flash attention (bf16 split-3), emits B-layout fp16 ----------------
#define AT_SMEM 163840

__device__ __forceinline__ void kv_load(uint32_t smb, int tid,
    const __nv_bfloat16* __restrict__ kTh, const __nv_bfloat16* __restrict__ kTl,
    const __nv_bfloat16* __restrict__ vH, const __nv_bfloat16* __restrict__ vL,
    int bh, int t, uint32_t stOff)
{
    uint32_t kb = smb + stOff;
    const uint4* kh4 = (const uint4*)(kTh + ((long)bh * 1024 + t * 128) * 64);
    const uint4* kl4 = (const uint4*)(kTl + ((long)bh * 1024 + t * 128) * 64);
    int r = tid >> 1, j0 = (tid & 1) * 4;
#pragma unroll
    for (int j = 0; j < 4; j++) {
        uint32_t off = SWZ128((uint32_t)(r * 128 + (j0 + j) * 16));
        cpa16(kb + off, kh4 + (long)r * 8 + j0 + j);
        cpa16(kb + 16384 + off, kl4 + (long)r * 8 + j0 + j);
    }
    const uint4* vh4 = (const uint4*)(vH + (long)bh * 65536 + t * 128);
    const uint4* vl4 = (const uint4*)(vL + (long)bh * 65536 + t * 128);
    int d = tid >> 2, jc0 = (tid & 3) * 4;
#pragma unroll
    for (int j = 0; j < 4; j++) {
        int jc = jc0 + j;
        uint32_t off = (uint32_t)((jc >> 3) * 8192) + SWZ128((uint32_t)(d * 128 + (jc & 7) * 16));
        cpa16(kb + 32768 + off, vh4 + (long)d * 128 + jc);
        cpa16(kb + 49152 + off, vl4 + (long)d * 128 + jc);
    }
}

extern __shared__ char at_smem[];

__global__ void __launch_bounds__(256) attn_mma_kernel(
    const __nv_bfloat16* __restrict__ Hi, const __nv_bfloat16* __restrict__ Lo,
    uint16_t* __restrict__ OutB)
{
    int qt = blockIdx.x, h = blockIdx.y, b = blockIdx.z;
    int bh = b * 4 + h;
    int tid = threadIdx.x, wid = tid >> 5, lane = tid & 31, li = lane & 15;
    uint32_t smb = smem_u32(at_smem);

    const __nv_bfloat16* qTh = Hi + QT_OFF;
    const __nv_bfloat16* qTl = Lo + QT_OFF;
    const __nv_bfloat16* kTh = Hi + KT_OFF;
    const __nv_bfloat16* kTl = Lo + KT_OFF;
    const __nv_bfloat16* vH  = Hi + V_OFF;
    const __nv_bfloat16* vL  = Lo + V_OFF;

    {
        const uint4* qh4 = (const uint4*)(qTh + ((long)bh * 1024 + qt * 128) * 64);
        const uint4* ql4 = (const uint4*)(qTl + ((long)bh * 1024 + qt * 128) * 64);
        int r = tid >> 1, j0 = (tid & 1) * 4;
        uint32_t qb = smb + 131072;
#pragma unroll
        for (int j = 0; j < 4; j++) {
            uint32_t off = SWZ128((uint32_t)(r * 128 + (j0 + j) * 16));
            cpa16(qb + off, qh4 + (long)r * 8 + j0 + j);
            cpa16(qb + 16384 + off, ql4 + (long)r * 8 + j0 + j);
        }
    }
    CPA_COMMIT();
    kv_load(smb, tid, kTh, kTl, vH, vL, bh, 0, 0);
    CPA_COMMIT();
    CPA_WAIT1();
    __syncthreads();

    uint32_t qfh[4][4], qfl[4][4];
    {
        int aRow = wid * 16 + (lane & 7) + (lane & 8);
        int aCol = ((lane >> 4) & 1) * 16;
#pragma unroll
        for (int ks = 0; ks < 4; ks++) {
            uint32_t off = SWZ128((uint32_t)(aRow * 128 + aCol + ks * 32));
            ldsm_x4(qfh[ks], smb + 131072 + off);
            ldsm_x4(qfl[ks], smb + 131072 + 16384 + off);
        }
    }

    float oacc[8][4];
#pragma unroll
    for (int i = 0; i < 8; i++)
#pragma unroll
        for (int j = 0; j < 4; j++) oacc[i][j] = 0.f;
    float m0 = -1e30f, m1 = -1e30f, l0 = 0.f, l1 = 0.f;

    int sRowX4 = (lane >> 4) * 8 + (lane & 7);
    uint32_t sColX4 = (uint32_t)(((lane >> 3) & 1) * 16);

    for (int t = 0; t < 8; t++) {
        int s = t & 1;
        if (t < 7) {
            kv_load(smb, tid, kTh, kTl, vH, vL, bh, t + 1, (uint32_t)((s ^ 1) * 65536));
            CPA_COMMIT();
            CPA_WAIT1();
        } else {
            CPA_WAIT0();
        }
        __syncthreads();

        uint32_t kb = smb + s * 65536;
        float sacc[16][4];
#pragma unroll
        for (int i = 0; i < 16; i++)
#pragma unroll
            for (int j = 0; j < 4; j++) sacc[i][j] = 0.f;

#pragma unroll
        for (int p = 0; p < 8; p++) {
            int rowB = p * 16 + sRowX4;
#pragma unroll
            for (int ks = 0; ks < 4; ks++) {
                uint32_t off = SWZ128((uint32_t)(rowB * 128 + sColX4 + ks * 32));
                uint32_t kh4[4], kl4[4];
                ldsm_x4(kh4, kb + off);
                ldsm_x4(kl4, kb + 16384 + off);
                mma16816(sacc[2 * p],     qfh[ks], &kh4[0]);
                mma16816(sacc[2 * p + 1], qfh[ks], &kh4[2]);
                mma16816(sacc[2 * p],     qfl[ks], &kh4[0]);
                mma16816(sacc[2 * p + 1], qfl[ks], &kh4[2]);
                mma16816(sacc[2 * p],     qfh[ks], &kl4[0]);
                mma16816(sacc[2 * p + 1], qfh[ks], &kl4[2]);
            }
        }

        float mx0 = m0, mx1 = m1;
#pragma unroll
        for (int nt = 0; nt < 16; nt++) {
            mx0 = fmaxf(mx0, fmaxf(sacc[nt][0], sacc[nt][1]));
            mx1 = fmaxf(mx1, fmaxf(sacc[nt][2], sacc[nt][3]));
        }
        mx0 = fmaxf(mx0, __shfl_xor_sync(0xffffffffu, mx0, 1));
        mx0 = fmaxf(mx0, __shfl_xor_sync(0xffffffffu, mx0, 2));
        mx1 = fmaxf(mx1, __shfl_xor_sync(0xffffffffu, mx1, 1));
        mx1 = fmaxf(mx1, __shfl_xor_sync(0xffffffffu, mx1, 2));
        float a0 = __expf(m0 - mx0), a1 = __expf(m1 - mx1);
        m0 = mx0; m1 = mx1;

        float ls0 = 0.f, ls1 = 0.f;
        uint32_t pah[8][4], pal[8][4];
#pragma unroll
        for (int kj = 0; kj < 8; kj++) {
            float p00 = __expf(sacc[2 * kj][0] - m0);
            float p01 = __expf(sacc[2 * kj][1] - m0);
            float p02 = __expf(sacc[2 * kj][2] - m1);
            float p03 = __expf(sacc[2 * kj][3] - m1);
            float p10 = __expf(sacc[2 * kj + 1][0] - m0);
            float p11 = __expf(sacc[2 * kj + 1][1] - m0);
            float p12 = __expf(sacc[2 * kj + 1][2] - m1);
            float p13 = __expf(sacc[2 * kj + 1][3] - m1);
            ls0 += p00 + p01 + p10 + p11;
            ls1 += p02 + p03 + p12 + p13;
            pah[kj][0] = packbf(p00, p01);
            pah[kj][1] = packbf(p02, p03);
            pah[kj][2] = packbf(p10, p11);
            pah[kj][3] = packbf(p12, p13);
            float q00 = p00 - __bfloat162float(__float2bfloat16(p00));
            float q01 = p01 - __bfloat162float(__float2bfloat16(p01));
            float q02 = p02 - __bfloat162float(__float2bfloat16(p02));
            float q03 = p03 - __bfloat162float(__float2bfloat16(p03));
            float q10 = p10 - __bfloat162float(__float2bfloat16(p10));
            float q11 = p11 - __bfloat162float(__float2bfloat16(p11));
            float q12 = p12 - __bfloat162float(__float2bfloat16(p12));
            float q13 = p13 - __bfloat162float(__float2bfloat16(p13));
            pal[kj][0] = packbf(q00, q01);
            pal[kj][1] = packbf(q02, q03);
            pal[kj][2] = packbf(q10, q11);
            pal[kj][3] = packbf(q12, q13);
        }
        ls0 += __shfl_xor_sync(0xffffffffu, ls0, 1);
        ls0 += __shfl_xor_sync(0xffffffffu, ls0, 2);
        ls1 += __shfl_xor_sync(0xffffffffu, ls1, 1);
        ls1 += __shfl_xor_sync(0xffffffffu, ls1, 2);
        l0 = l0 * a0 + ls0;
        l1 = l1 * a1 + ls1;
#pragma unroll
        for (int dt = 0; dt < 8; dt++) {
            oacc[dt][0] *= a0; oacc[dt][1] *= a0;
            oacc[dt][2] *= a1; oacc[dt][3] *= a1;
        }

#pragma unroll
        for (int dt = 0; dt < 8; dt++) {
            int rowV = dt * 8 + (li & 7);
#pragma unroll
            for (int kj = 0; kj < 8; kj++) {
                uint32_t off = (uint32_t)((kj >> 2) * 8192) +
                               SWZ128((uint32_t)(rowV * 128 + (li >> 3) * 16 + (kj & 3) * 32));
                uint32_t vh2[2], vl2[2];
                ldsm_x2(vh2, kb + 32768 + off);
                ldsm_x2(vl2, kb + 49152 + off);
                mma16816(oacc[dt], pah[kj], vh2);
                mma16816(oacc[dt], pal[kj], vh2);
                mma16816(oacc[dt], pah[kj], vl2);
            }
        }
        __syncthreads();
    }

    float i0 = 1.f / l0, i1 = 1.f / l1;
    float* stg = (float*)at_smem;   // [128][66]
    int r0 = wid * 16 + (lane >> 2);
#pragma unroll
    for (int dt = 0; dt < 8; dt++) {
        int d = dt * 8 + (lane & 3) * 2;
        stg[r0 * 66 + d]           = oacc[dt][0] * i0;
        stg[r0 * 66 + d + 1]       = oacc[dt][1] * i0;
        stg[(r0 + 8) * 66 + d]     = oacc[dt][2] * i1;
        stg[(r0 + 8) * 66 + d + 1] = oacc[dt][3] * i1;
    }
    __syncthreads();
    // emit B-layout fp16: [n = global token][k = 256 channels]
    for (int e = tid; e < 4096; e += 256) {
        int i = e >> 5, dp = (e & 31) * 2;
        __half2 hv = __floats2half2_rn(stg[i * 66 + dp], stg[i * 66 + dp + 1]);
        *(__half2*)&OutB[((long)b * 1024 + qt * 128 + i) * 256 + h * 64 + dp] = hv;
    }
}

// ---------------- launch ----------------
extern "C" void kernel_launch(void* const* d_in, const int* in_sizes, int n_in,
                              void* d_out, int out_size)
{
    const float* x      = (const float*)d_in[0];
    const float* cv1_w  = (const float*)d_in[1];
    const float* cv1_bn = (const float*)d_in[2];
    const float* cv2_w  = (const float*)d_in[3];
    const float* cv2_bn = (const float*)d_in[4];
    const float* mcv1w  = (const float*)d_in[5];
    const float* mcv1bn = (const float*)d_in[6];
    const float* mqkvw  = (const float*)d_in[7];
    const float* mrw    = (const float*)d_in[8];
    const float* mrh    = (const float*)d_in[9];
    const float* mcv2w  = (const float*)d_in[10];
    const float* mcv2bn = (const float*)d_in[11];
    float* out = (float*)d_out;

    float *cat, *scl, *bia;
    uint16_t *catH, *qkvH, *whi, *bhi, *blo;
    cudaGetSymbolAddress((void**)&cat,   g_cat);
    cudaGetSymbolAddress((void**)&catH,  g_catH);
    cudaGetSymbolAddress((void**)&qkvH,  g_qkvH);
    cudaGetSymbolAddress((void**)&scl,   g_scale);
    cudaGetSymbolAddress((void**)&bia,   g_bias);
    cudaGetSymbolAddress((void**)&whi,   g_Whi);
    cudaGetSymbolAddress((void**)&bhi,   g_Bhi);
    cudaGetSymbolAddress((void**)&blo,   g_Blo);
    __nv_bfloat16* bhiB = (__nv_bfloat16*)bhi;
    __nv_bfloat16* bloB = (__nv_bfloat16*)blo;

    cudaFuncSetAttribute(mgemm_kernel, cudaFuncAttributeMaxDynamicSharedMemorySize, MG_SMEM);
    cudaFuncSetAttribute(mgemm64_kernel_t<0>, cudaFuncAttributeMaxDynamicSharedMemorySize, MG64_SMEM);
    cudaFuncSetAttribute(mgemm64_kernel_t<1>, cudaFuncAttributeMaxDynamicSharedMemorySize, MG64_SMEM);
    cudaFuncSetAttribute(attn_mma_kernel, cudaFuncAttributeMaxDynamicSharedMemorySize, AT_SMEM);

    fold_bn_kernel<<<8, 256>>>(cv1_bn, cv2_bn, mcv1bn, mcv2bn);
    convW_all_kernel<<<(W_TOTAL + 255) / 256, 256>>>(cv1_w, mcv1w, mqkvw, mcv2w, cv2_w, whi);

    // ---- cv1: 512 -> 512, BN+SiLU -> fp32 cat[0:512) + fp16 catH[0:512) ----
    convB_kernel<float><<<dim3(32, 16, 8), dim3(32, 8)>>>(x, (long)512 * HW, 512, bhi + B0_OFF);
    mgemm_kernel<<<dim3(8, 4, 8), 256, MG_SMEM>>>(
        bhi + B0_OFF, whi + W_CV1, 512, cat, catH, (long)1024 * HW,
        scl + 0, bia + 0, nullptr, 0, 1);

    for (int i = 0; i < 2; i++) {
        long yin  = (long)(i == 0 ? 256 : 512) * HW;
        long yout = (long)(512 + i * 256) * HW;
        long wConv = i ? W_CONV1 : W_CONV0;
        long wQkv  = i ? W_QKV1  : W_QKV0;
        long wCv2  = i ? W_CV2M1 : W_CV2M0;

        // z = cbs(yi, 3x3) as IMPLICIT GEMM; emits fp16 B-layout ZB directly
        convB_kernel<__half><<<dim3(32, 8, 8), dim3(32, 8)>>>(
            (const __half*)(catH + yin), (long)1024 * HW, 256, bhi + B0_OFF);
        mgemm64_kernel_t<1><<<dim3(16, 2, 8), 256, MG64_SMEM>>>(
            bhi + B0_OFF, whi + wConv, 2304, 256,
            nullptr, nullptr, 0, bhi + ZB_OFF,
            scl + 1024 + i * 256, bia + 1024 + i * 256, nullptr, 0, 1);

        // qkv = conv1x1(z), 256 -> 768 (reads ZB directly); output fp16 qkvH
        mgemm_kernel<<<dim3(8, 6, 8), 256, MG_SMEM>>>(
            bhi + ZB_OFF, whi + wQkv, 256, nullptr, qkvH, (long)768 * HW,
            nullptr, nullptr, nullptr, 0, 0);

        // attention operand conversion + MMA flash attention -> fp16 B-layout ATB
        convAttn_kernel<<<dim3(32, 2, 32), dim3(32, 8)>>>(
            qkvH, mrw + (long)i * 8192, mrh + (long)i * 8192, bhiB, bloB);
        attn_mma_kernel<<<dim3(8, 4, 8), 256, AT_SMEM>>>(bhiB, bloB, bhi + ATB_OFF);

        // y_{i+2} = yi + silu(bn(conv1x1(attn))) (reads ATB) -> fp32 cat + fp16 catH
        mgemm64_kernel_t<0><<<dim3(16, 2, 8), 256, MG64_SMEM>>>(
            bhi + ATB_OFF, whi + wCv2, 256, 256,
            cat + yout, catH + yout, (long)1024 * HW, nullptr,
            scl + 1536 + i * 256, bia + 1536 + i * 256, cat + yin, (long)1024 * HW, 1);
    }

    // ---- final: 1024 -> 512, BN+SiLU, fp32 out ----
    convB_kernel<__half><<<dim3(32, 32, 8), dim3(32, 8)>>>(
        (const __half*)catH, (long)1024 * HW, 1024, bhi + B0_OFF);
    mgemm_kernel<<<dim3(8, 4, 8), 256, MG_SMEM>>>(
        bhi + B0_OFF, whi + W_FIN, 1024, out, nullptr, (long)512 * HW,
        scl + 512, bia + 512, nullptr, 0, 1);
}